// round 10
// baseline (speedup 1.0000x reference)
#include <cuda_runtime.h>
#include <cuda_bf16.h>
#include <math.h>
#include <stdint.h>

#define NN      25000
#define NE      100000
#define NEP     125000
#define NG      512
#define NH      10
#define NF      78
#define HF      780
#define SEQL    1000
#define EMB     128
#define NFILT   32
#define CONVOUT 121
#define VOCAB   26
#define UCOLS   (VOCAB*8)        // 208
#define USZ     (NFILT*UCOLS)

#define KP_GAT  128
#define KP_GCN  832
#define NPADG   896              // 7 x 128 N-tiles
#define KP_POOL 1600
#define NP_FCG1 1024
#define KP_U    256

// ---------------- device scratch ----------------
__device__ float d_h[NN*HF];
__device__ float d_asrc[NN*NH];
__device__ float d_adst[NN*NH];
__device__ float d_wsrc[NF*NH];
__device__ float d_wdst[NF*NH];
__device__ float d_invden[NN*NH];
__device__ float d_alpha[(size_t)NEP*NH];
__device__ float d_h2[NN*HF];
__device__ float d_x2[NN*HF];
__device__ float d_dinv[NN];
__device__ int   d_deg[NN];
__device__ int   d_roff[NN+1];
__device__ int   d_rpos[NN];
__device__ int   d_csrc[NEP];
__device__ int   d_start[NG+1];
__device__ float d_xg1[NG*1024];
__device__ float d_Wt[SEQL*NFILT*8];
__device__ float d_conv[(size_t)NG*NFILT*CONVOUT];
__device__ float d_fcxtb2[128];
__device__ float d_xc[NG*256];
__device__ float d_f1[NG*1024];
__device__ float d_f2[NG*512];
__device__ __nv_bfloat16 d_xh[(size_t)NN*KP_GAT];
__device__ __nv_bfloat16 d_xl[(size_t)NN*KP_GAT];
__device__ __nv_bfloat16 d_x1h[(size_t)NN*KP_GCN];
__device__ __nv_bfloat16 d_x1l[(size_t)NN*KP_GCN];
__device__ __nv_bfloat16 d_gWh[(size_t)NPADG*KP_GAT];
__device__ __nv_bfloat16 d_gWl[(size_t)NPADG*KP_GAT];
__device__ __nv_bfloat16 d_cWh[(size_t)NPADG*KP_GCN];
__device__ __nv_bfloat16 d_cWl[(size_t)NPADG*KP_GCN];
__device__ __nv_bfloat16 d_poolh[(size_t)NG*KP_POOL];
__device__ __nv_bfloat16 d_pooll[(size_t)NG*KP_POOL];
__device__ __nv_bfloat16 d_fWh[(size_t)NP_FCG1*KP_POOL];
__device__ __nv_bfloat16 d_fWl[(size_t)NP_FCG1*KP_POOL];
__device__ __nv_bfloat16 d_Uh[(size_t)NG*NFILT*KP_U];
__device__ __nv_bfloat16 d_Ul[(size_t)NG*NFILT*KP_U];
__device__ __nv_bfloat16 d_Mmh[128*KP_U];
__device__ __nv_bfloat16 d_Mml[128*KP_U];

// ================= helpers =================
__device__ __forceinline__ uint32_t smem_u32(const void* p){
    uint32_t a;
    asm("{ .reg .u64 t; cvta.to.shared.u64 t, %1; cvt.u32.u64 %0, t; }" : "=r"(a) : "l"(p));
    return a;
}
#define LDMX4(r, a) \
    asm volatile("ldmatrix.sync.aligned.m8n8.x4.shared.b16 {%0,%1,%2,%3}, [%4];" \
        : "=r"((r)[0]), "=r"((r)[1]), "=r"((r)[2]), "=r"((r)[3]) : "r"(a))
#define MMA16816(d, a, b0, b1) \
    asm volatile("mma.sync.aligned.m16n8k16.row.col.f32.bf16.bf16.f32 " \
        "{%0,%1,%2,%3}, {%4,%5,%6,%7}, {%8,%9}, {%0,%1,%2,%3};" \
        : "+f"((d)[0]), "+f"((d)[1]), "+f"((d)[2]), "+f"((d)[3]) \
        : "r"((a)[0]), "r"((a)[1]), "r"((a)[2]), "r"((a)[3]), "r"(b0), "r"(b1))
#define CPA_COMMIT() asm volatile("cp.async.commit_group;" ::: "memory")
#define CPA_WAIT0()  asm volatile("cp.async.wait_group 0;" ::: "memory")

__device__ __forceinline__ void cpa16(uint32_t dst, const void* src, int sz){
    size_t g;
    asm("cvta.to.global.u64 %0, %1;" : "=l"(g) : "l"(src));
    asm volatile("cp.async.cg.shared.global [%0], [%1], 16, %2;" :: "r"(dst), "l"(g), "r"(sz) : "memory");
}
__device__ __forceinline__ void split_bf16(float v, __nv_bfloat16& h, __nv_bfloat16& l){
    h = __float2bfloat16(v);
    l = __float2bfloat16(v - __bfloat162float(h));
}

// ================= BIG mma GEMM: 256x128 tile, 512 threads =================
#define BATILE 36864     // 256 * 144
#define BBTILE 18432     // 128 * 144
#define BSTG   110592    // 2*BATILE + 2*BBTILE
#define BGP    72

__device__ __forceinline__ void ld_tileA_b(uint32_t sdst, const __nv_bfloat16* G,
                                           int row0, int k0, int KP, int rlim, int tid){
    #pragma unroll
    for (int i = 0; i < 4; i++){
        int v = tid + i*512;          // 0..2047
        int r = v >> 3, cq = v & 7;
        int row = row0 + r;
        int sz = (row < rlim) ? 16 : 0;
        cpa16(sdst + r*144 + cq*16, G + (size_t)(sz ? row : row0)*KP + k0 + cq*8, sz);
    }
}
__device__ __forceinline__ void ld_tileB_b(uint32_t sdst, const __nv_bfloat16* G,
                                           int row0, int k0, int KP, int rlim, int tid){
    #pragma unroll
    for (int i = 0; i < 2; i++){
        int v = tid + i*512;          // 0..1023
        int r = v >> 3, cq = v & 7;
        int row = row0 + r;
        int sz = (row < rlim) ? 16 : 0;
        cpa16(sdst + r*144 + cq*16, G + (size_t)(sz ? row : row0)*KP + k0 + cq*8, sz);
    }
}

__global__ void __launch_bounds__(512, 1) gemm_mma_b(
    const __nv_bfloat16* __restrict__ Ah, const __nv_bfloat16* __restrict__ Al,
    const __nv_bfloat16* __restrict__ Bh, const __nv_bfloat16* __restrict__ Bl,
    float* __restrict__ C, int M, int Nout, int KP, int ldc, int Brows)
{
    extern __shared__ char sm[];
    uint32_t sb = smem_u32(sm);
    int tid = threadIdx.x;
    int m0 = blockIdx.y*256, n0 = blockIdx.x*128;
    int w = tid >> 5, lane = tid & 31;
    int wm = (w >> 2) * 64;     // 4 warps along M
    int wn = (w & 3) * 32;      // 4 warps along N
    int NC = KP / 64;

    float acc[4][4][4];
    #pragma unroll
    for (int i=0;i<4;i++)
        #pragma unroll
        for (int j=0;j<4;j++)
            #pragma unroll
            for (int q=0;q<4;q++) acc[i][j][q] = 0.f;

    int a_row = (lane & 15);
    int a_kc  = (lane >> 4) * 8;
    int b_row = ((lane >> 4) * 8) + (lane & 7);
    int b_kc  = ((lane >> 3) & 1) * 8;

    ld_tileA_b(sb + 0,                 Ah, m0, 0, KP, M, tid);
    ld_tileA_b(sb + BATILE,            Al, m0, 0, KP, M, tid);
    ld_tileB_b(sb + 2*BATILE,          Bh, n0, 0, KP, Brows, tid);
    ld_tileB_b(sb + 2*BATILE + BBTILE, Bl, n0, 0, KP, Brows, tid);
    CPA_COMMIT();

    for (int ci = 0; ci < NC; ci++){
        int b = ci & 1;
        uint32_t st = sb + b*BSTG;
        CPA_WAIT0();
        __syncthreads();
        if (ci + 1 < NC){
            uint32_t s2 = sb + (1-b)*BSTG;
            int k0n = (ci+1)*64;
            ld_tileA_b(s2 + 0,                 Ah, m0, k0n, KP, M, tid);
            ld_tileA_b(s2 + BATILE,            Al, m0, k0n, KP, M, tid);
            ld_tileB_b(s2 + 2*BATILE,          Bh, n0, k0n, KP, Brows, tid);
            ld_tileB_b(s2 + 2*BATILE + BBTILE, Bl, n0, k0n, KP, Brows, tid);
            CPA_COMMIT();
        }
        uint32_t bAh = st, bAl = st + BATILE, bBh = st + 2*BATILE, bBl = st + 2*BATILE + BBTILE;
        #pragma unroll
        for (int kk = 0; kk < 64; kk += 16){
            uint32_t ah[4][4], al[4][4];
            #pragma unroll
            for (int mt = 0; mt < 4; mt++){
                uint32_t off = (uint32_t)((wm + mt*16 + a_row)*BGP + kk + a_kc) * 2;
                LDMX4(ah[mt], bAh + off);
                LDMX4(al[mt], bAl + off);
            }
            #pragma unroll
            for (int nt2 = 0; nt2 < 2; nt2++){
                uint32_t offb = (uint32_t)((wn + nt2*16 + b_row)*BGP + kk + b_kc) * 2;
                uint32_t bh[4], bl[4];
                LDMX4(bh, bBh + offb);
                LDMX4(bl, bBl + offb);
                // term-major: same-acc MMAs spaced 8 apart
                #pragma unroll
                for (int mt = 0; mt < 4; mt++){
                    MMA16816(acc[mt][nt2*2],   ah[mt], bh[0], bh[1]);
                    MMA16816(acc[mt][nt2*2+1], ah[mt], bh[2], bh[3]);
                }
                #pragma unroll
                for (int mt = 0; mt < 4; mt++){
                    MMA16816(acc[mt][nt2*2],   ah[mt], bl[0], bl[1]);
                    MMA16816(acc[mt][nt2*2+1], ah[mt], bl[2], bl[3]);
                }
                #pragma unroll
                for (int mt = 0; mt < 4; mt++){
                    MMA16816(acc[mt][nt2*2],   al[mt], bh[0], bh[1]);
                    MMA16816(acc[mt][nt2*2+1], al[mt], bh[2], bh[3]);
                }
            }
        }
    }
    #pragma unroll
    for (int mt = 0; mt < 4; mt++){
        int r0 = m0 + wm + mt*16 + (lane >> 2);
        #pragma unroll
        for (int nt = 0; nt < 4; nt++){
            int c = n0 + wn + nt*8 + (lane & 3)*2;
            #pragma unroll
            for (int half = 0; half < 2; half++){
                int rr = r0 + half*8;
                if (rr >= M) continue;
                #pragma unroll
                for (int q = 0; q < 2; q++){
                    int cc = c + q;
                    if (cc >= Nout) continue;
                    C[(size_t)rr*ldc + cc] = acc[mt][nt][half*2 + q];
                }
            }
        }
    }
}

// ================= small mma GEMM (128x64) for fcg1/conv =================
#define GPITCH 72
#define ATILEB 18432
#define BTILEB 9216
#define STG    55296

__device__ __forceinline__ void ld_tileA(uint32_t sdst, const __nv_bfloat16* G,
                                         int row0, int k0, int KP, int rlim, int tid){
    #pragma unroll
    for (int i = 0; i < 4; i++){
        int v = tid + i*256;
        int r = v >> 3, cq = v & 7;
        int row = row0 + r;
        int sz = (row < rlim) ? 16 : 0;
        cpa16(sdst + r*144 + cq*16, G + (size_t)(sz ? row : row0)*KP + k0 + cq*8, sz);
    }
}
__device__ __forceinline__ void ld_tileB(uint32_t sdst, const __nv_bfloat16* G,
                                         int row0, int k0, int KP, int rlim, int tid){
    #pragma unroll
    for (int i = 0; i < 2; i++){
        int v = tid + i*256;
        int r = v >> 3, cq = v & 7;
        int row = row0 + r;
        int sz = (row < rlim) ? 16 : 0;
        cpa16(sdst + r*144 + cq*16, G + (size_t)(sz ? row : row0)*KP + k0 + cq*8, sz);
    }
}

__global__ void __launch_bounds__(256, 2) gemm_mma(
    const __nv_bfloat16* __restrict__ Ah, const __nv_bfloat16* __restrict__ Al,
    const __nv_bfloat16* __restrict__ Bh, const __nv_bfloat16* __restrict__ Bl,
    float* __restrict__ C, int M, int Nout, int KP, int ldc,
    const float* __restrict__ bias, int act, int Brows)
{
    extern __shared__ char sm[];
    uint32_t sb = smem_u32(sm);
    int tid = threadIdx.x;
    int m0 = blockIdx.y*128, n0 = blockIdx.x*64;
    int w = tid >> 5, lane = tid & 31;
    int wm = (w >> 1) * 32;
    int wn = (w & 1) * 32;
    int NC = KP / 64;

    float acc[2][4][4];
    #pragma unroll
    for (int i=0;i<2;i++)
        #pragma unroll
        for (int j=0;j<4;j++)
            #pragma unroll
            for (int q=0;q<4;q++) acc[i][j][q] = 0.f;

    int a_row = (lane & 15);
    int a_kc  = (lane >> 4) * 8;
    int b_row = ((lane >> 4) * 8) + (lane & 7);
    int b_kc  = ((lane >> 3) & 1) * 8;

    ld_tileA(sb + 0,                 Ah, m0, 0, KP, M, tid);
    ld_tileA(sb + ATILEB,            Al, m0, 0, KP, M, tid);
    ld_tileB(sb + 2*ATILEB,          Bh, n0, 0, KP, Brows, tid);
    ld_tileB(sb + 2*ATILEB + BTILEB, Bl, n0, 0, KP, Brows, tid);
    CPA_COMMIT();

    for (int ci = 0; ci < NC; ci++){
        int b = ci & 1;
        uint32_t st = sb + b*STG;
        CPA_WAIT0();
        __syncthreads();
        if (ci + 1 < NC){
            uint32_t s2 = sb + (1-b)*STG;
            int k0n = (ci+1)*64;
            ld_tileA(s2 + 0,                 Ah, m0, k0n, KP, M, tid);
            ld_tileA(s2 + ATILEB,            Al, m0, k0n, KP, M, tid);
            ld_tileB(s2 + 2*ATILEB,          Bh, n0, k0n, KP, Brows, tid);
            ld_tileB(s2 + 2*ATILEB + BTILEB, Bl, n0, k0n, KP, Brows, tid);
            CPA_COMMIT();
        }
        uint32_t bAh = st, bAl = st + ATILEB, bBh = st + 2*ATILEB, bBl = st + 2*ATILEB + BTILEB;
        #pragma unroll
        for (int kk = 0; kk < 64; kk += 16){
            uint32_t ah[2][4], al[2][4];
            #pragma unroll
            for (int mt = 0; mt < 2; mt++){
                uint32_t off = (uint32_t)((wm + mt*16 + a_row)*GPITCH + kk + a_kc) * 2;
                LDMX4(ah[mt], bAh + off);
                LDMX4(al[mt], bAl + off);
            }
            #pragma unroll
            for (int nt2 = 0; nt2 < 2; nt2++){
                uint32_t offb = (uint32_t)((wn + nt2*16 + b_row)*GPITCH + kk + b_kc) * 2;
                uint32_t bh[4], bl[4];
                LDMX4(bh, bBh + offb);
                LDMX4(bl, bBl + offb);
                #pragma unroll
                for (int mt = 0; mt < 2; mt++){
                    MMA16816(acc[mt][nt2*2],   ah[mt], bh[0], bh[1]);
                    MMA16816(acc[mt][nt2*2+1], ah[mt], bh[2], bh[3]);
                }
                #pragma unroll
                for (int mt = 0; mt < 2; mt++){
                    MMA16816(acc[mt][nt2*2],   ah[mt], bl[0], bl[1]);
                    MMA16816(acc[mt][nt2*2+1], ah[mt], bl[2], bl[3]);
                }
                #pragma unroll
                for (int mt = 0; mt < 2; mt++){
                    MMA16816(acc[mt][nt2*2],   al[mt], bh[0], bh[1]);
                    MMA16816(acc[mt][nt2*2+1], al[mt], bh[2], bh[3]);
                }
            }
        }
    }
    #pragma unroll
    for (int mt = 0; mt < 2; mt++){
        int r0 = m0 + wm + mt*16 + (lane >> 2);
        #pragma unroll
        for (int nt = 0; nt < 4; nt++){
            int c = n0 + wn + nt*8 + (lane & 3)*2;
            #pragma unroll
            for (int half = 0; half < 2; half++){
                int rr = r0 + half*8;
                if (rr >= M) continue;
                #pragma unroll
                for (int q = 0; q < 2; q++){
                    int cc = c + q;
                    if (cc >= Nout) continue;
                    float v = acc[mt][nt][half*2 + q];
                    if (bias) v += bias[cc];
                    if (act)  v = fmaxf(v, 0.f);
                    C[(size_t)rr*ldc + cc] = v;
                }
            }
        }
    }
}

// ================= split-prep =================
__global__ void k_split_x(const float* __restrict__ x){
    int i = blockIdx.x*blockDim.x + threadIdx.x;
    if (i >= NN*KP_GAT) return;
    int r = i >> 7, k = i & (KP_GAT-1);
    float v = (k < NF) ? x[r*NF + k] : 0.f;
    split_bf16(v, d_xh[i], d_xl[i]);
}
__global__ void k_splitB(const float* __restrict__ W, __nv_bfloat16* __restrict__ bh,
                         __nv_bfloat16* __restrict__ bl, int K, int N, int KP, int NR){
    int i = blockIdx.x*blockDim.x + threadIdx.x;
    if (i >= NR*KP) return;
    int n = i / KP, k = i - n*KP;
    float v = (k < K && n < N) ? W[(size_t)k*N + n] : 0.f;
    __nv_bfloat16 h, l; split_bf16(v, h, l);
    bh[i] = h; bl[i] = l;
}

// ================= CSR build =================
__global__ void k_deg_init(){
    int n = blockIdx.x*blockDim.x + threadIdx.x;
    if (n < NN) d_deg[n] = 1;
}
__global__ void k_count(const int* __restrict__ ei){
    int e = blockIdx.x*blockDim.x + threadIdx.x;
    if (e < NE) atomicAdd(&d_deg[ei[NE+e]], 1);
}
__global__ void k_scan(){
    __shared__ int part[1024];
    int t = threadIdx.x;
    const int PER = 25;
    int base = t*PER, sum = 0;
    for (int i = 0; i < PER; i++){ int idx = base+i; if (idx < NN) sum += d_deg[idx]; }
    part[t] = sum; __syncthreads();
    for (int off = 1; off < 1024; off <<= 1){
        int v = (t >= off) ? part[t-off] : 0; __syncthreads();
        part[t] += v; __syncthreads();
    }
    int run = part[t] - sum;
    for (int i = 0; i < PER; i++){
        int idx = base+i;
        if (idx < NN){ d_roff[idx] = run; d_rpos[idx] = run; run += d_deg[idx]; }
    }
    if (t == 1023) d_roff[NN] = NEP;
}
__global__ void k_fill(const int* __restrict__ ei){
    int e = blockIdx.x*blockDim.x + threadIdx.x;
    if (e >= NEP) return;
    int s, d;
    if (e < NE){ s = ei[e]; d = ei[NE+e]; } else { s = d = e - NE; }
    int pos = atomicAdd(&d_rpos[d], 1);
    d_csrc[pos] = s;
}
__global__ void k_dinv(){
    int n = blockIdx.x*blockDim.x + threadIdx.x;
    if (n < NN) d_dinv[n] = rsqrtf((float)d_deg[n]);
}

// ================= GAT attention (folded) =================
__global__ void k_attw(const float* __restrict__ gat_W,
                       const float* __restrict__ att_src,
                       const float* __restrict__ att_dst){
    int wid  = (blockIdx.x*blockDim.x + threadIdx.x) >> 5;
    int lane = threadIdx.x & 31;
    if (wid >= 2*NF*NH) return;
    int which = (wid >= NF*NH);
    int r = wid - which*NF*NH;
    int f_in = r / NH, hh = r - f_in*NH;
    const float* att = which ? att_dst : att_src;
    float s = 0.f;
    for (int f = lane; f < NF; f += 32)
        s += gat_W[(size_t)f_in*HF + hh*NF + f] * att[hh*NF + f];
    #pragma unroll
    for (int o = 16; o > 0; o >>= 1) s += __shfl_down_sync(~0u, s, o);
    if (!lane){
        if (which) d_wdst[f_in*NH + hh] = s;
        else       d_wsrc[f_in*NH + hh] = s;
    }
}
__global__ void k_asrcdst(const float* __restrict__ x){
    __shared__ float ws[NF*NH], wd[NF*NH];
    int tid = threadIdx.x;
    for (int i = tid; i < NF*NH; i += 256){ ws[i] = d_wsrc[i]; wd[i] = d_wdst[i]; }
    __syncthreads();
    int n = blockIdx.x*256 + tid;
    if (n >= NN) return;
    float as[NH], ad[NH];
    #pragma unroll
    for (int hh = 0; hh < NH; hh++){ as[hh] = 0.f; ad[hh] = 0.f; }
    const float* xr = x + (size_t)n*NF;
    for (int f = 0; f < NF; f++){
        float xv = xr[f];
        #pragma unroll
        for (int hh = 0; hh < NH; hh++){
            as[hh] += xv * ws[f*NH + hh];
            ad[hh] += xv * wd[f*NH + hh];
        }
    }
    #pragma unroll
    for (int hh = 0; hh < NH; hh++){
        d_asrc[n*NH + hh] = as[hh];
        d_adst[n*NH + hh] = ad[hh];
    }
}

__global__ void k_gat_soft(){
    int w    = (blockIdx.x*blockDim.x + threadIdx.x) >> 5;
    int lane = threadIdx.x & 31;
    if (w >= NN || lane >= NH) return;
    int s0 = d_roff[w], s1 = d_roff[w+1];
    float ad = d_adst[w*NH + lane];
    float mx = -1e30f;
    for (int p = s0; p < s1; p++){
        float a = d_asrc[d_csrc[p]*NH + lane] + ad;
        a = a > 0.f ? a : 0.2f*a;
        mx = fmaxf(mx, a);
    }
    float sum = 0.f;
    for (int p = s0; p < s1; p++){
        float a = d_asrc[d_csrc[p]*NH + lane] + ad;
        a = a > 0.f ? a : 0.2f*a;
        float e = expf(a - mx);
        d_alpha[(size_t)p*NH + lane] = e;
        sum += e;
    }
    d_invden[w*NH + lane] = 1.f / (sum + 1e-16f);
}
__global__ void k_gat_agg(const float* __restrict__ gat_b){
    int n = blockIdx.x;
    int tid = threadIdx.x;
    __shared__ float invd[NH];
    __shared__ int   csrc_c[25];
    __shared__ float coef_c[25][NH];
    if (tid < NH) invd[tid] = d_invden[n*NH + tid];
    __syncthreads();
    int s0 = d_roff[n], s1 = d_roff[n+1];
    float4 acc = make_float4(0.f,0.f,0.f,0.f);
    int c0 = tid*4;
    int h0 = c0/NF, h1 = (c0+1)/NF, h2 = (c0+2)/NF, h3 = (c0+3)/NF;
    for (int base = s0; base < s1; base += 25){
        int cnt = s1 - base; if (cnt > 25) cnt = 25;
        if (tid < cnt) csrc_c[tid] = d_csrc[base + tid];
        if (tid < cnt*NH){
            int p = tid / NH, hh = tid - p*NH;
            coef_c[p][hh] = d_alpha[(size_t)(base+p)*NH + hh] * invd[hh];
        }
        __syncthreads();
        if (tid < 195){
            #pragma unroll 2
            for (int j = 0; j < cnt; j++){
                float4 v = *(const float4*)(d_h + (size_t)csrc_c[j]*HF + c0);
                acc.x += coef_c[j][h0]*v.x;
                acc.y += coef_c[j][h1]*v.y;
                acc.z += coef_c[j][h2]*v.z;
                acc.w += coef_c[j][h3]*v.w;
            }
        }
        __syncthreads();
    }
    if (tid < 195){
        float4 bb = *(const float4*)(gat_b + c0);
        float r[4] = { fmaxf(acc.x + bb.x, 0.f), fmaxf(acc.y + bb.y, 0.f),
                       fmaxf(acc.z + bb.z, 0.f), fmaxf(acc.w + bb.w, 0.f) };
        #pragma unroll
        for (int q = 0; q < 4; q++){
            __nv_bfloat16 h, l; split_bf16(r[q], h, l);
            d_x1h[(size_t)n*KP_GCN + c0 + q] = h;
            d_x1l[(size_t)n*KP_GCN + c0 + q] = l;
        }
    } else if (tid < 208){
        #pragma unroll
        for (int q = 0; q < 4; q++){
            d_x1h[(size_t)n*KP_GCN + c0 + q] = __float2bfloat16(0.f);
            d_x1l[(size_t)n*KP_GCN + c0 + q] = __float2bfloat16(0.f);
        }
    }
}

// ================= GCN aggregate =================
__global__ void k_gcn_agg(const float* __restrict__ gcn_b){
    int n = blockIdx.x;
    int tid = threadIdx.x;
    __shared__ int   csrc_c[64];
    __shared__ float coef_c[64];
    int s0 = d_roff[n], s1 = d_roff[n+1];
    float dn = d_dinv[n];
    float4 acc = make_float4(0.f,0.f,0.f,0.f);
    int c0 = tid*4;
    for (int base = s0; base < s1; base += 64){
        int cnt = s1 - base; if (cnt > 64) cnt = 64;
        if (tid < cnt){
            int s = d_csrc[base + tid];
            csrc_c[tid] = s;
            coef_c[tid] = dn * d_dinv[s];
        }
        __syncthreads();
        if (tid < 195){
            #pragma unroll 2
            for (int j = 0; j < cnt; j++){
                float4 v = *(const float4*)(d_h2 + (size_t)csrc_c[j]*HF + c0);
                float cf = coef_c[j];
                acc.x += cf*v.x; acc.y += cf*v.y; acc.z += cf*v.z; acc.w += cf*v.w;
            }
        }
        __syncthreads();
    }
    if (tid < 195){
        float4 bb = *(const float4*)(gcn_b + c0);
        float4 r = make_float4(fmaxf(acc.x + bb.x, 0.f), fmaxf(acc.y + bb.y, 0.f),
                               fmaxf(acc.z + bb.z, 0.f), fmaxf(acc.w + bb.w, 0.f));
        *(float4*)(d_x2 + (size_t)n*HF + c0) = r;
    }
}

// ================= pooling =================
__global__ void k_start(const int* __restrict__ batch){
    int g = blockIdx.x*blockDim.x + threadIdx.x;
    if (g > NG) return;
    if (g == NG){ d_start[NG] = NN; return; }
    int lo = 0, hi = NN;
    while (lo < hi){ int mid = (lo+hi) >> 1; if (batch[mid] < g) lo = mid+1; else hi = mid; }
    d_start[g] = lo;
}
__global__ void k_pool(){
    int g = blockIdx.x;
    int s = d_start[g], e = d_start[g+1];
    int cnt = e - s;
    size_t rb = (size_t)g*KP_POOL;
    for (int c = threadIdx.x; c < HF; c += blockDim.x){
        float mx = -1e30f, sm = 0.f;
        #pragma unroll 4
        for (int n = s; n < e; n++){
            float v = d_x2[(size_t)n*HF + c];
            mx = fmaxf(mx, v); sm += v;
        }
        float vmax = (cnt > 0) ? mx : 0.f;
        float vmean = sm / fmaxf((float)cnt, 1.f);
        __nv_bfloat16 h, l;
        split_bf16(vmax, h, l);  d_poolh[rb + c] = h;      d_pooll[rb + c] = l;
        split_bf16(vmean, h, l); d_poolh[rb + HF + c] = h; d_pooll[rb + HF + c] = l;
    }
    if (threadIdx.x < KP_POOL - 2*HF){
        d_poolh[rb + 2*HF + threadIdx.x] = __float2bfloat16(0.f);
        d_pooll[rb + 2*HF + threadIdx.x] = __float2bfloat16(0.f);
    }
}

// ================= small GEMM (f32x2, split-K) =================
__global__ void gemm2_kernel(const float* __restrict__ A, const float* __restrict__ B,
                             const float* __restrict__ bias, float* __restrict__ C,
                             int M, int N, int K, int ldc, int act)
{
    __shared__ float As[16*64];
    __shared__ float Bs[16*64];
    int tid = threadIdx.x;
    int row0 = blockIdx.y*64, col0 = blockIdx.x*64;
    int tx = tid & 15, ty = tid >> 4;
    int Z = gridDim.z, z = blockIdx.z;
    int T = (K + 15) / 16;
    int kc0 = (int)((long long)T * z / Z), kc1 = (int)((long long)T * (z+1) / Z);
    unsigned long long acc2[4][2];
    #pragma unroll
    for (int i=0;i<4;i++){ acc2[i][0] = 0ull; acc2[i][1] = 0ull; }
    for (int kc = kc0; kc < kc1; kc++){
        int k0 = kc*16;
        #pragma unroll
        for (int i=0;i<4;i++){
            int l = tid + i*256;
            int m = l >> 4, kk = l & 15;
            int r = row0 + m, kg = k0 + kk;
            As[kk*64+m] = (r < M && kg < K) ? A[(size_t)r*K + kg] : 0.f;
        }
        #pragma unroll
        for (int i=0;i<4;i++){
            int l = tid + i*256;
            int kk = l >> 6, n = l & 63;
            int kg = k0 + kk, c = col0 + n;
            Bs[kk*64+n] = (kg < K && c < N) ? B[(size_t)kg*N + c] : 0.f;
        }
        __syncthreads();
        #pragma unroll
        for (int kk=0; kk<16; kk++){
            float ra[4];
            #pragma unroll
            for (int i=0;i<4;i++) ra[i] = As[kk*64 + ty*4 + i];
            unsigned long long rb0 = *(const unsigned long long*)&Bs[kk*64 + tx*4];
            unsigned long long rb1 = *(const unsigned long long*)&Bs[kk*64 + tx*4 + 2];
            #pragma unroll
            for (int i=0;i<4;i++){
                unsigned long long ad;
                asm("mov.b64 %0, {%1, %1};" : "=l"(ad) : "r"(__float_as_uint(ra[i])));
                asm("fma.rn.f32x2 %0, %1, %2, %0;" : "+l"(acc2[i][0]) : "l"(ad), "l"(rb0));
                asm("fma.rn.f32x2 %0, %1, %2, %0;" : "+l"(acc2[i][1]) : "l"(ad), "l"(rb1));
            }
        }
        __syncthreads();
    }
    #pragma unroll
    for (int i=0;i<4;i++){
        int r = row0 + ty*4 + i;
        if (r >= M) continue;
        #pragma unroll
        for (int jp=0;jp<2;jp++){
            unsigned int lo, hi;
            asm("mov.b64 {%0, %1}, %2;" : "=r"(lo), "=r"(hi) : "l"(acc2[i][jp]));
            float vv[2] = { __uint_as_float(lo), __uint_as_float(hi) };
            int c = col0 + tx*4 + jp*2;
            #pragma unroll
            for (int q=0;q<2;q++){
                int cc = c + q;
                if (cc >= N) continue;
                if (Z == 1){
                    float v = vv[q];
                    if (bias) v += bias[cc];
                    if (act)  v = fmaxf(v, 0.f);
                    C[(size_t)r*ldc + cc] = v;
                } else {
                    atomicAdd(&C[(size_t)r*ldc + cc], vv[q]);
                }
            }
        }
    }
}

__global__ void k_binit(float* __restrict__ C, const float* __restrict__ bias,
                        int M, int N, int ldc){
    int i = blockIdx.x*blockDim.x + threadIdx.x;
    if (i >= M*N) return;
    int r = i / N, c = i - r*N;
    C[(size_t)r*ldc + c] = bias[c];
}
__global__ void k_relu(float* __restrict__ C, int total){
    int i = blockIdx.x*blockDim.x + threadIdx.x;
    if (i < total) C[i] = fmaxf(C[i], 0.f);
}

// ================= target branch =================
__global__ void k_buildM(const float* __restrict__ emb){
    int i = blockIdx.x*blockDim.x + threadIdx.x;
    if (i >= 128*KP_U) return;
    int p = i / KP_U, kidx = i - p*KP_U;
    float val = 0.f;
    if (p < CONVOUT && kidx < UCOLS){
        int v = kidx >> 3, kk = kidx & 7;
        val = emb[v*EMB + p + kk];
    }
    __nv_bfloat16 h, l; split_bf16(val, h, l);
    d_Mmh[i] = h; d_Mml[i] = l;
}
__global__ void k_transW(const float* __restrict__ W){
    int i = blockIdx.x*blockDim.x + threadIdx.x;
    if (i >= NFILT*SEQL*8) return;
    int o = i / (SEQL*8), c = (i >> 3) % SEQL, k = i & 7;
    d_Wt[c*(NFILT*8) + o*8 + k] = W[i];
}
__global__ void k_buildU(const int* __restrict__ target){
    __shared__ float sU[USZ];
    __shared__ int   st[SEQL];
    int g = blockIdx.x;
    for (int i = threadIdx.x; i < USZ;  i += blockDim.x) sU[i] = 0.f;
    for (int i = threadIdx.x; i < SEQL; i += blockDim.x) st[i] = target[g*SEQL + i];
    __syncthreads();
    int o = threadIdx.x >> 3, k = threadIdx.x & 7;
    for (int c = 0; c < SEQL; c++){
        int v = st[c];
        sU[o*UCOLS + v*8 + k] += d_Wt[c*(NFILT*8) + threadIdx.x];
    }
    __syncthreads();
    for (int i = threadIdx.x; i < NFILT*KP_U; i += blockDim.x){
        int oo = i / KP_U, col = i - oo*KP_U;
        float v = (col < UCOLS) ? sU[oo*UCOLS + col] : 0.f;
        __nv_bfloat16 h, l; split_bf16(v, h, l);
        size_t idx = ((size_t)g*NFILT + oo)*KP_U + col;
        d_Uh[idx] = h; d_Ul[idx] = l;
    }
}
__global__ void k_fcxtb2(const float* __restrict__ fcxt_W,
                         const float* __restrict__ fcxt_b,
                         const float* __restrict__ conv_b){
    int j = blockIdx.x;
    __shared__ float red[128];
    float s = 0.f;
    for (int r = threadIdx.x; r < NFILT*CONVOUT; r += blockDim.x)
        s += conv_b[r / CONVOUT] * fcxt_W[(size_t)r*128 + j];
    red[threadIdx.x] = s; __syncthreads();
    for (int o = 64; o > 0; o >>= 1){
        if (threadIdx.x < o) red[threadIdx.x] += red[threadIdx.x + o];
        __syncthreads();
    }
    if (!threadIdx.x) d_fcxtb2[j] = fcxt_b[j] + red[0];
}

// ================= final projection =================
__global__ void k_out(const float* __restrict__ oW, const float* __restrict__ ob,
                      float* __restrict__ out){
    int g    = (blockIdx.x*blockDim.x + threadIdx.x) >> 5;
    int lane = threadIdx.x & 31;
    if (g >= NG) return;
    float s = 0.f;
    for (int k = lane; k < 512; k += 32) s += d_f2[g*512 + k] * oW[k];
    #pragma unroll
    for (int o = 16; o > 0; o >>= 1) s += __shfl_down_sync(~0u, s, o);
    if (!lane) out[g] = s + ob[0];
}

extern "C" void kernel_launch(void* const* d_in, const int* in_sizes, int n_in,
                              void* d_out, int out_size){
    const float* x        = (const float*)d_in[0];
    const int*   ei       = (const int*)  d_in[1];
    const int*   batch    = (const int*)  d_in[2];
    const int*   target   = (const int*)  d_in[3];
    const float* gat_W    = (const float*)d_in[4];
    const float* gat_asrc = (const float*)d_in[5];
    const float* gat_adst = (const float*)d_in[6];
    const float* gat_b    = (const float*)d_in[7];
    const float* gcn_W    = (const float*)d_in[8];
    const float* gcn_b    = (const float*)d_in[9];
    const float* fcg1_W   = (const float*)d_in[10];
    const float* fcg1_b   = (const float*)d_in[11];
    const float* fcg2_W   = (const float*)d_in[12];
    const float* fcg2_b   = (const float*)d_in[13];
    const float* emb      = (const float*)d_in[14];
    const float* conv_W   = (const float*)d_in[15];
    const float* conv_b   = (const float*)d_in[16];
    const float* fcxt_W   = (const float*)d_in[17];
    const float* fcxt_b   = (const float*)d_in[18];
    const float* fc1_W    = (const float*)d_in[19];
    const float* fc1_b    = (const float*)d_in[20];
    const float* fc2_W    = (const float*)d_in[21];
    const float* fc2_b    = (const float*)d_in[22];
    const float* out_W    = (const float*)d_in[23];
    const float* out_b    = (const float*)d_in[24];

    float *p_h, *p_h2, *p_xg1, *p_xc, *p_conv, *p_f1, *p_f2, *p_fcxtb2;
    __nv_bfloat16 *p_xh, *p_xl, *p_x1h, *p_x1l, *p_gWh, *p_gWl, *p_cWh, *p_cWl;
    __nv_bfloat16 *p_poolh, *p_pooll, *p_fWh, *p_fWl, *p_Uh, *p_Ul, *p_Mmh, *p_Mml;
    cudaGetSymbolAddress((void**)&p_h,    d_h);
    cudaGetSymbolAddress((void**)&p_h2,   d_h2);
    cudaGetSymbolAddress((void**)&p_xg1,  d_xg1);
    cudaGetSymbolAddress((void**)&p_xc,   d_xc);
    cudaGetSymbolAddress((void**)&p_conv, d_conv);
    cudaGetSymbolAddress((void**)&p_f1,   d_f1);
    cudaGetSymbolAddress((void**)&p_f2,   d_f2);
    cudaGetSymbolAddress((void**)&p_fcxtb2, d_fcxtb2);
    cudaGetSymbolAddress((void**)&p_xh,  d_xh);
    cudaGetSymbolAddress((void**)&p_xl,  d_xl);
    cudaGetSymbolAddress((void**)&p_x1h, d_x1h);
    cudaGetSymbolAddress((void**)&p_x1l, d_x1l);
    cudaGetSymbolAddress((void**)&p_gWh, d_gWh);
    cudaGetSymbolAddress((void**)&p_gWl, d_gWl);
    cudaGetSymbolAddress((void**)&p_cWh, d_cWh);
    cudaGetSymbolAddress((void**)&p_cWl, d_cWl);
    cudaGetSymbolAddress((void**)&p_poolh, d_poolh);
    cudaGetSymbolAddress((void**)&p_pooll, d_pooll);
    cudaGetSymbolAddress((void**)&p_fWh, d_fWh);
    cudaGetSymbolAddress((void**)&p_fWl, d_fWl);
    cudaGetSymbolAddress((void**)&p_Uh, d_Uh);
    cudaGetSymbolAddress((void**)&p_Ul, d_Ul);
    cudaGetSymbolAddress((void**)&p_Mmh, d_Mmh);
    cudaGetSymbolAddress((void**)&p_Mml, d_Mml);

    cudaFuncSetAttribute(gemm_mma,   cudaFuncAttributeMaxDynamicSharedMemorySize, 2*STG);
    cudaFuncSetAttribute(gemm_mma_b, cudaFuncAttributeMaxDynamicSharedMemorySize, 2*BSTG);

    // launches 0..2: splits (launch 3 = gemm_mma_b GAT lands under ncu -s 5)
    k_split_x<<<(NN*KP_GAT + 255)/256, 256>>>(x);
    k_splitB<<<(NPADG*KP_GAT + 255)/256, 256>>>(gat_W, p_gWh, p_gWl, NF, HF, KP_GAT, NPADG);
    k_splitB<<<(NPADG*KP_GCN + 255)/256, 256>>>(gcn_W, p_cWh, p_cWl, HF, HF, KP_GCN, NPADG);

    // launch 3: GAT transform (profiled)
    {
        dim3 grid(NPADG/128, (NN + 255)/256);
        gemm_mma_b<<<grid, 512, 2*BSTG>>>(p_xh, p_xl, p_gWh, p_gWl, p_h, NN, HF, KP_GAT, HF, NPADG);
    }

    // CSR build
    k_deg_init<<<(NN + 255)/256, 256>>>();
    k_count<<<(NE + 255)/256, 256>>>(ei);
    k_scan<<<1, 1024>>>();
    k_fill<<<(NEP + 255)/256, 256>>>(ei);
    k_dinv<<<(NN + 255)/256, 256>>>();

    // remaining prep
    k_splitB<<<(NP_FCG1*KP_POOL + 255)/256, 256>>>(fcg1_W, p_fWh, p_fWl, 2*HF, 1024, KP_POOL, NP_FCG1);
    k_buildM<<<(128*KP_U + 255)/256, 256>>>(emb);
    k_transW<<<(NFILT*SEQL*8 + 255)/256, 256>>>(conv_W);

    // GAT attention (folded) + aggregation
    k_attw<<<(2*NF*NH*32 + 255)/256, 256>>>(gat_W, gat_asrc, gat_adst);
    k_asrcdst<<<(NN + 255)/256, 256>>>(x);
    k_gat_soft<<<(NN*32 + 255)/256, 256>>>();
    k_gat_agg<<<NN, 256>>>(gat_b);

    // GCN
    {
        dim3 grid(NPADG/128, (NN + 255)/256);
        gemm_mma_b<<<grid, 512, 2*BSTG>>>(p_x1h, p_x1l, p_cWh, p_cWl, p_h2, NN, HF, KP_GCN, HF, NPADG);
    }
    k_gcn_agg<<<NN, 256>>>(gcn_b);

    // pooling + graph head
    k_start<<<3, 256>>>(batch);
    k_pool<<<NG, 256>>>();
    {
        dim3 grid(1024/64, NG/128);
        gemm_mma<<<grid, 256, 2*STG>>>(p_poolh, p_pooll, p_fWh, p_fWl, p_xg1, NG, 1024, KP_POOL, 1024, fcg1_b, 1, NP_FCG1);
    }
    {
        k_binit<<<(NG*128 + 255)/256, 256>>>(p_xc, fcg2_b, NG, 128, 256);
        dim3 grid(2, 8, 4);
        gemm2_kernel<<<grid, 256>>>(p_xg1, fcg2_W, nullptr, p_xc, NG, 128, 1024, 256, 0);
    }

    // target branch
    k_buildU<<<NG, 256>>>(target);
    {
        dim3 grid(2, (NG*NFILT)/128);
        gemm_mma<<<grid, 256, 2*STG>>>(p_Uh, p_Ul, p_Mmh, p_Mml, p_conv, NG*NFILT, CONVOUT, KP_U, CONVOUT, nullptr, 0, 128);
    }
    k_fcxtb2<<<128, 128>>>(fcxt_W, fcxt_b, conv_b);
    {
        k_binit<<<(NG*128 + 255)/256, 256>>>(p_xc + 128, p_fcxtb2, NG, 128, 256);
        dim3 grid(2, 8, 4);
        gemm2_kernel<<<grid, 256>>>(p_conv, fcxt_W, nullptr, p_xc + 128, NG, 128, NFILT*CONVOUT, 256, 0);
    }

    // fusion head
    {
        dim3 grid(16, 8, 1);
        gemm2_kernel<<<grid, 256>>>(p_xc, fc1_W, fc1_b, p_f1, NG, 1024, 256, 1024, 1);
    }
    {
        k_binit<<<(NG*512 + 255)/256, 256>>>(p_f2, fc2_b, NG, 512, 512);
        dim3 grid(8, 8, 2);
        gemm2_kernel<<<grid, 256>>>(p_f1, fc2_W, nullptr, p_f2, NG, 512, 1024, 512, 0);
        k_relu<<<(NG*512 + 255)/256, 256>>>(p_f2, NG*512);
    }
    k_out<<<(NG*32 + 255)/256, 256>>>(out_W, out_b, (float*)d_out);
}

// round 11
// speedup vs baseline: 1.0606x; 1.0606x over previous
#include <cuda_runtime.h>
#include <cuda_bf16.h>
#include <math.h>
#include <stdint.h>

#define NN      25000
#define NE      100000
#define NEP     125000
#define NG      512
#define NH      10
#define NF      78
#define HF      780
#define SEQL    1000
#define EMB     128
#define NFILT   32
#define CONVOUT 121
#define VOCAB   26
#define UCOLS   (VOCAB*8)        // 208
#define USZ     (NFILT*UCOLS)

#define KP_GAT  128
#define KP_GCN  832
#define NPADG   832
#define KP_POOL 1600
#define NP_FCG1 1024
#define KP_U    256

// ---------------- device scratch ----------------
__device__ float d_h[NN*HF];
__device__ float d_asrc[NN*NH];
__device__ float d_adst[NN*NH];
__device__ float d_wsrc[NF*NH];
__device__ float d_wdst[NF*NH];
__device__ float d_invden[NN*NH];
__device__ float d_alpha[(size_t)NEP*NH];
__device__ float d_h2[NN*HF];
__device__ float d_x2[NN*HF];
__device__ float d_dinv[NN];
__device__ int   d_deg[NN];
__device__ int   d_roff[NN+1];
__device__ int   d_rpos[NN];
__device__ int   d_csrc[NEP];
__device__ int   d_start[NG+1];
__device__ float d_xg1[NG*1024];
__device__ float d_Wt[SEQL*NFILT*8];
__device__ float d_conv[(size_t)NG*NFILT*CONVOUT];
__device__ float d_fcxtb2[128];
__device__ float d_xc[NG*256];
__device__ float d_f1[NG*1024];
__device__ float d_f2[NG*512];
__device__ __nv_bfloat16 d_xh[(size_t)NN*KP_GAT];
__device__ __nv_bfloat16 d_xl[(size_t)NN*KP_GAT];
__device__ __nv_bfloat16 d_x1h[(size_t)NN*KP_GCN];
__device__ __nv_bfloat16 d_x1l[(size_t)NN*KP_GCN];
__device__ __nv_bfloat16 d_gWh[(size_t)NPADG*KP_GAT];
__device__ __nv_bfloat16 d_gWl[(size_t)NPADG*KP_GAT];
__device__ __nv_bfloat16 d_cWh[(size_t)NPADG*KP_GCN];
__device__ __nv_bfloat16 d_cWl[(size_t)NPADG*KP_GCN];
__device__ __nv_bfloat16 d_poolh[(size_t)NG*KP_POOL];
__device__ __nv_bfloat16 d_pooll[(size_t)NG*KP_POOL];
__device__ __nv_bfloat16 d_fWh[(size_t)NP_FCG1*KP_POOL];
__device__ __nv_bfloat16 d_fWl[(size_t)NP_FCG1*KP_POOL];
__device__ __nv_bfloat16 d_Uh[(size_t)NG*NFILT*KP_U];
__device__ __nv_bfloat16 d_Ul[(size_t)NG*NFILT*KP_U];
__device__ __nv_bfloat16 d_Mmh[128*KP_U];
__device__ __nv_bfloat16 d_Mml[128*KP_U];

// ================= helpers =================
__device__ __forceinline__ uint32_t smem_u32(const void* p){
    uint32_t a;
    asm("{ .reg .u64 t; cvta.to.shared.u64 t, %1; cvt.u32.u64 %0, t; }" : "=r"(a) : "l"(p));
    return a;
}
#define LDMX4(r, a) \
    asm volatile("ldmatrix.sync.aligned.m8n8.x4.shared.b16 {%0,%1,%2,%3}, [%4];" \
        : "=r"((r)[0]), "=r"((r)[1]), "=r"((r)[2]), "=r"((r)[3]) : "r"(a))
#define MMA16816(d, a, b0, b1) \
    asm volatile("mma.sync.aligned.m16n8k16.row.col.f32.bf16.bf16.f32 " \
        "{%0,%1,%2,%3}, {%4,%5,%6,%7}, {%8,%9}, {%0,%1,%2,%3};" \
        : "+f"((d)[0]), "+f"((d)[1]), "+f"((d)[2]), "+f"((d)[3]) \
        : "r"((a)[0]), "r"((a)[1]), "r"((a)[2]), "r"((a)[3]), "r"(b0), "r"(b1))
#define CPA_COMMIT() asm volatile("cp.async.commit_group;" ::: "memory")
#define CPA_WAIT0()  asm volatile("cp.async.wait_group 0;" ::: "memory")

__device__ __forceinline__ void cpa16(uint32_t dst, const void* src, int sz){
    size_t g;
    asm("cvta.to.global.u64 %0, %1;" : "=l"(g) : "l"(src));
    asm volatile("cp.async.cg.shared.global [%0], [%1], 16, %2;" :: "r"(dst), "l"(g), "r"(sz) : "memory");
}
__device__ __forceinline__ void split_bf16(float v, __nv_bfloat16& h, __nv_bfloat16& l){
    h = __float2bfloat16(v);
    l = __float2bfloat16(v - __bfloat162float(h));
}

// ================= mma.sync split-bf16 GEMM (128x64 tile, Ksteps-masked) =================
#define GPITCH 72
#define ATILEB 18432
#define BTILEB 9216
#define STG    55296

__device__ __forceinline__ void ld_tileA(uint32_t sdst, const __nv_bfloat16* G,
                                         int row0, int k0, int KP, int rlim, int tid){
    #pragma unroll
    for (int i = 0; i < 4; i++){
        int v = tid + i*256;
        int r = v >> 3, cq = v & 7;
        int row = row0 + r;
        int sz = (row < rlim) ? 16 : 0;
        cpa16(sdst + r*144 + cq*16, G + (size_t)(sz ? row : row0)*KP + k0 + cq*8, sz);
    }
}
__device__ __forceinline__ void ld_tileB(uint32_t sdst, const __nv_bfloat16* G,
                                         int row0, int k0, int KP, int rlim, int tid){
    #pragma unroll
    for (int i = 0; i < 2; i++){
        int v = tid + i*256;
        int r = v >> 3, cq = v & 7;
        int row = row0 + r;
        int sz = (row < rlim) ? 16 : 0;
        cpa16(sdst + r*144 + cq*16, G + (size_t)(sz ? row : row0)*KP + k0 + cq*8, sz);
    }
}

__global__ void __launch_bounds__(256, 2) gemm_mma(
    const __nv_bfloat16* __restrict__ Ah, const __nv_bfloat16* __restrict__ Al,
    const __nv_bfloat16* __restrict__ Bh, const __nv_bfloat16* __restrict__ Bl,
    float* __restrict__ C, int M, int Nout, int KP, int ldc,
    const float* __restrict__ bias, int act, int Brows, int Ksteps)
{
    extern __shared__ char sm[];
    uint32_t sb = smem_u32(sm);
    int tid = threadIdx.x;
    int m0 = blockIdx.y*128, n0 = blockIdx.x*64;
    int w = tid >> 5, lane = tid & 31;
    int wm = (w >> 1) * 32;
    int wn = (w & 1) * 32;
    int NC = KP / 64;

    float acc[2][4][4];
    #pragma unroll
    for (int i=0;i<2;i++)
        #pragma unroll
        for (int j=0;j<4;j++)
            #pragma unroll
            for (int q=0;q<4;q++) acc[i][j][q] = 0.f;

    int a_row = (lane & 15);
    int a_kc  = (lane >> 4) * 8;
    int b_row = ((lane >> 4) * 8) + (lane & 7);
    int b_kc  = ((lane >> 3) & 1) * 8;

    ld_tileA(sb + 0,                 Ah, m0, 0, KP, M, tid);
    ld_tileA(sb + ATILEB,            Al, m0, 0, KP, M, tid);
    ld_tileB(sb + 2*ATILEB,          Bh, n0, 0, KP, Brows, tid);
    ld_tileB(sb + 2*ATILEB + BTILEB, Bl, n0, 0, KP, Brows, tid);
    CPA_COMMIT();

    for (int ci = 0; ci < NC; ci++){
        int b = ci & 1;
        uint32_t st = sb + b*STG;
        CPA_WAIT0();
        __syncthreads();
        if (ci + 1 < NC){
            uint32_t s2 = sb + (1-b)*STG;
            int k0n = (ci+1)*64;
            ld_tileA(s2 + 0,                 Ah, m0, k0n, KP, M, tid);
            ld_tileA(s2 + ATILEB,            Al, m0, k0n, KP, M, tid);
            ld_tileB(s2 + 2*ATILEB,          Bh, n0, k0n, KP, Brows, tid);
            ld_tileB(s2 + 2*ATILEB + BTILEB, Bl, n0, k0n, KP, Brows, tid);
            CPA_COMMIT();
        }
        uint32_t bAh = st, bAl = st + ATILEB, bBh = st + 2*ATILEB, bBl = st + 2*ATILEB + BTILEB;
        #pragma unroll
        for (int kk = 0; kk < 64; kk += 16){
            if (ci*4 + (kk >> 4) >= Ksteps) break;   // skip padded K-steps
            uint32_t ah[2][4], al[2][4];
            #pragma unroll
            for (int mt = 0; mt < 2; mt++){
                uint32_t off = (uint32_t)((wm + mt*16 + a_row)*GPITCH + kk + a_kc) * 2;
                LDMX4(ah[mt], bAh + off);
                LDMX4(al[mt], bAl + off);
            }
            #pragma unroll
            for (int nt2 = 0; nt2 < 2; nt2++){
                uint32_t offb = (uint32_t)((wn + nt2*16 + b_row)*GPITCH + kk + b_kc) * 2;
                uint32_t bh[4], bl[4];
                LDMX4(bh, bBh + offb);
                LDMX4(bl, bBl + offb);
                #pragma unroll
                for (int mt = 0; mt < 2; mt++){
                    MMA16816(acc[mt][nt2*2],   ah[mt], bh[0], bh[1]);
                    MMA16816(acc[mt][nt2*2+1], ah[mt], bh[2], bh[3]);
                }
                #pragma unroll
                for (int mt = 0; mt < 2; mt++){
                    MMA16816(acc[mt][nt2*2],   ah[mt], bl[0], bl[1]);
                    MMA16816(acc[mt][nt2*2+1], ah[mt], bl[2], bl[3]);
                }
                #pragma unroll
                for (int mt = 0; mt < 2; mt++){
                    MMA16816(acc[mt][nt2*2],   al[mt], bh[0], bh[1]);
                    MMA16816(acc[mt][nt2*2+1], al[mt], bh[2], bh[3]);
                }
            }
        }
    }
    #pragma unroll
    for (int mt = 0; mt < 2; mt++){
        int r0 = m0 + wm + mt*16 + (lane >> 2);
        #pragma unroll
        for (int nt = 0; nt < 4; nt++){
            int c = n0 + wn + nt*8 + (lane & 3)*2;
            #pragma unroll
            for (int half = 0; half < 2; half++){
                int rr = r0 + half*8;
                if (rr >= M) continue;
                #pragma unroll
                for (int q = 0; q < 2; q++){
                    int cc = c + q;
                    if (cc >= Nout) continue;
                    float v = acc[mt][nt][half*2 + q];
                    if (bias) v += bias[cc];
                    if (act)  v = fmaxf(v, 0.f);
                    C[(size_t)rr*ldc + cc] = v;
                }
            }
        }
    }
}

// ================= split-prep =================
__global__ void k_split_x(const float* __restrict__ x){
    int i = blockIdx.x*blockDim.x + threadIdx.x;
    if (i >= NN*KP_GAT) return;
    int r = i >> 7, k = i & (KP_GAT-1);
    float v = (k < NF) ? x[r*NF + k] : 0.f;
    split_bf16(v, d_xh[i], d_xl[i]);
}
__global__ void k_splitB(const float* __restrict__ W, __nv_bfloat16* __restrict__ bh,
                         __nv_bfloat16* __restrict__ bl, int K, int N, int KP, int NR){
    int i = blockIdx.x*blockDim.x + threadIdx.x;
    if (i >= NR*KP) return;
    int n = i / KP, k = i - n*KP;
    float v = (k < K && n < N) ? W[(size_t)k*N + n] : 0.f;
    __nv_bfloat16 h, l; split_bf16(v, h, l);
    bh[i] = h; bl[i] = l;
}

// ================= CSR build =================
__global__ void k_deg_init(){
    int n = blockIdx.x*blockDim.x + threadIdx.x;
    if (n < NN) d_deg[n] = 1;
}
__global__ void k_count(const int* __restrict__ ei){
    int e = blockIdx.x*blockDim.x + threadIdx.x;
    if (e < NE) atomicAdd(&d_deg[ei[NE+e]], 1);
}
__global__ void k_scan(){
    __shared__ int part[1024];
    int t = threadIdx.x;
    const int PER = 25;
    int base = t*PER, sum = 0;
    for (int i = 0; i < PER; i++){ int idx = base+i; if (idx < NN) sum += d_deg[idx]; }
    part[t] = sum; __syncthreads();
    for (int off = 1; off < 1024; off <<= 1){
        int v = (t >= off) ? part[t-off] : 0; __syncthreads();
        part[t] += v; __syncthreads();
    }
    int run = part[t] - sum;
    for (int i = 0; i < PER; i++){
        int idx = base+i;
        if (idx < NN){ d_roff[idx] = run; d_rpos[idx] = run; run += d_deg[idx]; }
    }
    if (t == 1023) d_roff[NN] = NEP;
}
__global__ void k_fill(const int* __restrict__ ei){
    int e = blockIdx.x*blockDim.x + threadIdx.x;
    if (e >= NEP) return;
    int s, d;
    if (e < NE){ s = ei[e]; d = ei[NE+e]; } else { s = d = e - NE; }
    int pos = atomicAdd(&d_rpos[d], 1);
    d_csrc[pos] = s;
}
__global__ void k_dinv(){
    int n = blockIdx.x*blockDim.x + threadIdx.x;
    if (n < NN) d_dinv[n] = rsqrtf((float)d_deg[n]);
}

// ================= GAT attention (folded) =================
__global__ void k_attw(const float* __restrict__ gat_W,
                       const float* __restrict__ att_src,
                       const float* __restrict__ att_dst){
    int wid  = (blockIdx.x*blockDim.x + threadIdx.x) >> 5;
    int lane = threadIdx.x & 31;
    if (wid >= 2*NF*NH) return;
    int which = (wid >= NF*NH);
    int r = wid - which*NF*NH;
    int f_in = r / NH, hh = r - f_in*NH;
    const float* att = which ? att_dst : att_src;
    float s = 0.f;
    for (int f = lane; f < NF; f += 32)
        s += gat_W[(size_t)f_in*HF + hh*NF + f] * att[hh*NF + f];
    #pragma unroll
    for (int o = 16; o > 0; o >>= 1) s += __shfl_down_sync(~0u, s, o);
    if (!lane){
        if (which) d_wdst[f_in*NH + hh] = s;
        else       d_wsrc[f_in*NH + hh] = s;
    }
}
__global__ void k_asrcdst(const float* __restrict__ x){
    __shared__ float ws[NF*NH], wd[NF*NH];
    int tid = threadIdx.x;
    for (int i = tid; i < NF*NH; i += 256){ ws[i] = d_wsrc[i]; wd[i] = d_wdst[i]; }
    __syncthreads();
    int n = blockIdx.x*256 + tid;
    if (n >= NN) return;
    float as[NH], ad[NH];
    #pragma unroll
    for (int hh = 0; hh < NH; hh++){ as[hh] = 0.f; ad[hh] = 0.f; }
    const float* xr = x + (size_t)n*NF;
    for (int f = 0; f < NF; f++){
        float xv = xr[f];
        #pragma unroll
        for (int hh = 0; hh < NH; hh++){
            as[hh] += xv * ws[f*NH + hh];
            ad[hh] += xv * wd[f*NH + hh];
        }
    }
    #pragma unroll
    for (int hh = 0; hh < NH; hh++){
        d_asrc[n*NH + hh] = as[hh];
        d_adst[n*NH + hh] = ad[hh];
    }
}

__global__ void k_gat_soft(){
    int w    = (blockIdx.x*blockDim.x + threadIdx.x) >> 5;
    int lane = threadIdx.x & 31;
    if (w >= NN || lane >= NH) return;
    int s0 = d_roff[w], s1 = d_roff[w+1];
    float ad = d_adst[w*NH + lane];
    float mx = -1e30f;
    for (int p = s0; p < s1; p++){
        float a = d_asrc[d_csrc[p]*NH + lane] + ad;
        a = a > 0.f ? a : 0.2f*a;
        mx = fmaxf(mx, a);
    }
    float sum = 0.f;
    for (int p = s0; p < s1; p++){
        float a = d_asrc[d_csrc[p]*NH + lane] + ad;
        a = a > 0.f ? a : 0.2f*a;
        float e = expf(a - mx);
        d_alpha[(size_t)p*NH + lane] = e;
        sum += e;
    }
    d_invden[w*NH + lane] = 1.f / (sum + 1e-16f);
}
__global__ void k_gat_agg(const float* __restrict__ gat_b){
    int n = blockIdx.x;
    int tid = threadIdx.x;
    __shared__ float invd[NH];
    __shared__ int   csrc_c[25];
    __shared__ float coef_c[25][NH];
    if (tid < NH) invd[tid] = d_invden[n*NH + tid];
    __syncthreads();
    int s0 = d_roff[n], s1 = d_roff[n+1];
    float4 acc = make_float4(0.f,0.f,0.f,0.f);
    int c0 = tid*4;
    int h0 = c0/NF, h1 = (c0+1)/NF, h2 = (c0+2)/NF, h3 = (c0+3)/NF;
    for (int base = s0; base < s1; base += 25){
        int cnt = s1 - base; if (cnt > 25) cnt = 25;
        if (tid < cnt) csrc_c[tid] = d_csrc[base + tid];
        if (tid < cnt*NH){
            int p = tid / NH, hh = tid - p*NH;
            coef_c[p][hh] = d_alpha[(size_t)(base+p)*NH + hh] * invd[hh];
        }
        __syncthreads();
        if (tid < 195){
            #pragma unroll 2
            for (int j = 0; j < cnt; j++){
                float4 v = *(const float4*)(d_h + (size_t)csrc_c[j]*HF + c0);
                acc.x += coef_c[j][h0]*v.x;
                acc.y += coef_c[j][h1]*v.y;
                acc.z += coef_c[j][h2]*v.z;
                acc.w += coef_c[j][h3]*v.w;
            }
        }
        __syncthreads();
    }
    if (tid < 195){
        float4 bb = *(const float4*)(gat_b + c0);
        float r[4] = { fmaxf(acc.x + bb.x, 0.f), fmaxf(acc.y + bb.y, 0.f),
                       fmaxf(acc.z + bb.z, 0.f), fmaxf(acc.w + bb.w, 0.f) };
        #pragma unroll
        for (int q = 0; q < 4; q++){
            __nv_bfloat16 h, l; split_bf16(r[q], h, l);
            d_x1h[(size_t)n*KP_GCN + c0 + q] = h;
            d_x1l[(size_t)n*KP_GCN + c0 + q] = l;
        }
    } else if (tid < 208){
        #pragma unroll
        for (int q = 0; q < 4; q++){
            d_x1h[(size_t)n*KP_GCN + c0 + q] = __float2bfloat16(0.f);
            d_x1l[(size_t)n*KP_GCN + c0 + q] = __float2bfloat16(0.f);
        }
    }
}

// ================= GCN aggregate =================
__global__ void k_gcn_agg(const float* __restrict__ gcn_b){
    int n = blockIdx.x;
    int tid = threadIdx.x;
    __shared__ int   csrc_c[64];
    __shared__ float coef_c[64];
    int s0 = d_roff[n], s1 = d_roff[n+1];
    float dn = d_dinv[n];
    float4 acc = make_float4(0.f,0.f,0.f,0.f);
    int c0 = tid*4;
    for (int base = s0; base < s1; base += 64){
        int cnt = s1 - base; if (cnt > 64) cnt = 64;
        if (tid < cnt){
            int s = d_csrc[base + tid];
            csrc_c[tid] = s;
            coef_c[tid] = dn * d_dinv[s];
        }
        __syncthreads();
        if (tid < 195){
            #pragma unroll 2
            for (int j = 0; j < cnt; j++){
                float4 v = *(const float4*)(d_h2 + (size_t)csrc_c[j]*HF + c0);
                float cf = coef_c[j];
                acc.x += cf*v.x; acc.y += cf*v.y; acc.z += cf*v.z; acc.w += cf*v.w;
            }
        }
        __syncthreads();
    }
    if (tid < 195){
        float4 bb = *(const float4*)(gcn_b + c0);
        float4 r = make_float4(fmaxf(acc.x + bb.x, 0.f), fmaxf(acc.y + bb.y, 0.f),
                               fmaxf(acc.z + bb.z, 0.f), fmaxf(acc.w + bb.w, 0.f));
        *(float4*)(d_x2 + (size_t)n*HF + c0) = r;
    }
}

// ================= pooling =================
__global__ void k_start(const int* __restrict__ batch){
    int g = blockIdx.x*blockDim.x + threadIdx.x;
    if (g > NG) return;
    if (g == NG){ d_start[NG] = NN; return; }
    int lo = 0, hi = NN;
    while (lo < hi){ int mid = (lo+hi) >> 1; if (batch[mid] < g) lo = mid+1; else hi = mid; }
    d_start[g] = lo;
}
__global__ void k_pool(){
    int g = blockIdx.x;
    int s = d_start[g], e = d_start[g+1];
    int cnt = e - s;
    size_t rb = (size_t)g*KP_POOL;
    for (int c = threadIdx.x; c < HF; c += blockDim.x){
        float mx = -1e30f, sm = 0.f;
        #pragma unroll 4
        for (int n = s; n < e; n++){
            float v = d_x2[(size_t)n*HF + c];
            mx = fmaxf(mx, v); sm += v;
        }
        float vmax = (cnt > 0) ? mx : 0.f;
        float vmean = sm / fmaxf((float)cnt, 1.f);
        __nv_bfloat16 h, l;
        split_bf16(vmax, h, l);  d_poolh[rb + c] = h;      d_pooll[rb + c] = l;
        split_bf16(vmean, h, l); d_poolh[rb + HF + c] = h; d_pooll[rb + HF + c] = l;
    }
    if (threadIdx.x < KP_POOL - 2*HF){
        d_poolh[rb + 2*HF + threadIdx.x] = __float2bfloat16(0.f);
        d_pooll[rb + 2*HF + threadIdx.x] = __float2bfloat16(0.f);
    }
}

// ================= small GEMM (f32x2, split-K) =================
__global__ void gemm2_kernel(const float* __restrict__ A, const float* __restrict__ B,
                             const float* __restrict__ bias, float* __restrict__ C,
                             int M, int N, int K, int ldc, int act)
{
    __shared__ float As[16*64];
    __shared__ float Bs[16*64];
    int tid = threadIdx.x;
    int row0 = blockIdx.y*64, col0 = blockIdx.x*64;
    int tx = tid & 15, ty = tid >> 4;
    int Z = gridDim.z, z = blockIdx.z;
    int T = (K + 15) / 16;
    int kc0 = (int)((long long)T * z / Z), kc1 = (int)((long long)T * (z+1) / Z);
    unsigned long long acc2[4][2];
    #pragma unroll
    for (int i=0;i<4;i++){ acc2[i][0] = 0ull; acc2[i][1] = 0ull; }
    for (int kc = kc0; kc < kc1; kc++){
        int k0 = kc*16;
        #pragma unroll
        for (int i=0;i<4;i++){
            int l = tid + i*256;
            int m = l >> 4, kk = l & 15;
            int r = row0 + m, kg = k0 + kk;
            As[kk*64+m] = (r < M && kg < K) ? A[(size_t)r*K + kg] : 0.f;
        }
        #pragma unroll
        for (int i=0;i<4;i++){
            int l = tid + i*256;
            int kk = l >> 6, n = l & 63;
            int kg = k0 + kk, c = col0 + n;
            Bs[kk*64+n] = (kg < K && c < N) ? B[(size_t)kg*N + c] : 0.f;
        }
        __syncthreads();
        #pragma unroll
        for (int kk=0; kk<16; kk++){
            float ra[4];
            #pragma unroll
            for (int i=0;i<4;i++) ra[i] = As[kk*64 + ty*4 + i];
            unsigned long long rb0 = *(const unsigned long long*)&Bs[kk*64 + tx*4];
            unsigned long long rb1 = *(const unsigned long long*)&Bs[kk*64 + tx*4 + 2];
            #pragma unroll
            for (int i=0;i<4;i++){
                unsigned long long ad;
                asm("mov.b64 %0, {%1, %1};" : "=l"(ad) : "r"(__float_as_uint(ra[i])));
                asm("fma.rn.f32x2 %0, %1, %2, %0;" : "+l"(acc2[i][0]) : "l"(ad), "l"(rb0));
                asm("fma.rn.f32x2 %0, %1, %2, %0;" : "+l"(acc2[i][1]) : "l"(ad), "l"(rb1));
            }
        }
        __syncthreads();
    }
    #pragma unroll
    for (int i=0;i<4;i++){
        int r = row0 + ty*4 + i;
        if (r >= M) continue;
        #pragma unroll
        for (int jp=0;jp<2;jp++){
            unsigned int lo, hi;
            asm("mov.b64 {%0, %1}, %2;" : "=r"(lo), "=r"(hi) : "l"(acc2[i][jp]));
            float vv[2] = { __uint_as_float(lo), __uint_as_float(hi) };
            int c = col0 + tx*4 + jp*2;
            #pragma unroll
            for (int q=0;q<2;q++){
                int cc = c + q;
                if (cc >= N) continue;
                if (Z == 1){
                    float v = vv[q];
                    if (bias) v += bias[cc];
                    if (act)  v = fmaxf(v, 0.f);
                    C[(size_t)r*ldc + cc] = v;
                } else {
                    atomicAdd(&C[(size_t)r*ldc + cc], vv[q]);
                }
            }
        }
    }
}

__global__ void k_binit(float* __restrict__ C, const float* __restrict__ bias,
                        int M, int N, int ldc){
    int i = blockIdx.x*blockDim.x + threadIdx.x;
    if (i >= M*N) return;
    int r = i / N, c = i - r*N;
    C[(size_t)r*ldc + c] = bias[c];
}
__global__ void k_relu(float* __restrict__ C, int total){
    int i = blockIdx.x*blockDim.x + threadIdx.x;
    if (i < total) C[i] = fmaxf(C[i], 0.f);
}

// ================= target branch =================
__global__ void k_buildM(const float* __restrict__ emb){
    int i = blockIdx.x*blockDim.x + threadIdx.x;
    if (i >= 128*KP_U) return;
    int p = i / KP_U, kidx = i - p*KP_U;
    float val = 0.f;
    if (p < CONVOUT && kidx < UCOLS){
        int v = kidx >> 3, kk = kidx & 7;
        val = emb[v*EMB + p + kk];
    }
    __nv_bfloat16 h, l; split_bf16(val, h, l);
    d_Mmh[i] = h; d_Mml[i] = l;
}
__global__ void k_transW(const float* __restrict__ W){
    int i = blockIdx.x*blockDim.x + threadIdx.x;
    if (i >= NFILT*SEQL*8) return;
    int o = i / (SEQL*8), c = (i >> 3) % SEQL, k = i & 7;
    d_Wt[c*(NFILT*8) + o*8 + k] = W[i];
}
__global__ void k_buildU(const int* __restrict__ target){
    __shared__ float sU[USZ];
    __shared__ int   st[SEQL];
    int g = blockIdx.x;
    for (int i = threadIdx.x; i < USZ;  i += blockDim.x) sU[i] = 0.f;
    for (int i = threadIdx.x; i < SEQL; i += blockDim.x) st[i] = target[g*SEQL + i];
    __syncthreads();
    int o = threadIdx.x >> 3, k = threadIdx.x & 7;
    for (int c = 0; c < SEQL; c++){
        int v = st[c];
        sU[o*UCOLS + v*8 + k] += d_Wt[c*(NFILT*8) + threadIdx.x];
    }
    __syncthreads();
    for (int i = threadIdx.x; i < NFILT*KP_U; i += blockDim.x){
        int oo = i / KP_U, col = i - oo*KP_U;
        float v = (col < UCOLS) ? sU[oo*UCOLS + col] : 0.f;
        __nv_bfloat16 h, l; split_bf16(v, h, l);
        size_t idx = ((size_t)g*NFILT + oo)*KP_U + col;
        d_Uh[idx] = h; d_Ul[idx] = l;
    }
}
__global__ void k_fcxtb2(const float* __restrict__ fcxt_W,
                         const float* __restrict__ fcxt_b,
                         const float* __restrict__ conv_b){
    int j = blockIdx.x;
    __shared__ float red[128];
    float s = 0.f;
    for (int r = threadIdx.x; r < NFILT*CONVOUT; r += blockDim.x)
        s += conv_b[r / CONVOUT] * fcxt_W[(size_t)r*128 + j];
    red[threadIdx.x] = s; __syncthreads();
    for (int o = 64; o > 0; o >>= 1){
        if (threadIdx.x < o) red[threadIdx.x] += red[threadIdx.x + o];
        __syncthreads();
    }
    if (!threadIdx.x) d_fcxtb2[j] = fcxt_b[j] + red[0];
}

// ================= final projection =================
__global__ void k_out(const float* __restrict__ oW, const float* __restrict__ ob,
                      float* __restrict__ out){
    int g    = (blockIdx.x*blockDim.x + threadIdx.x) >> 5;
    int lane = threadIdx.x & 31;
    if (g >= NG) return;
    float s = 0.f;
    for (int k = lane; k < 512; k += 32) s += d_f2[g*512 + k] * oW[k];
    #pragma unroll
    for (int o = 16; o > 0; o >>= 1) s += __shfl_down_sync(~0u, s, o);
    if (!lane) out[g] = s + ob[0];
}

extern "C" void kernel_launch(void* const* d_in, const int* in_sizes, int n_in,
                              void* d_out, int out_size){
    const float* x        = (const float*)d_in[0];
    const int*   ei       = (const int*)  d_in[1];
    const int*   batch    = (const int*)  d_in[2];
    const int*   target   = (const int*)  d_in[3];
    const float* gat_W    = (const float*)d_in[4];
    const float* gat_asrc = (const float*)d_in[5];
    const float* gat_adst = (const float*)d_in[6];
    const float* gat_b    = (const float*)d_in[7];
    const float* gcn_W    = (const float*)d_in[8];
    const float* gcn_b    = (const float*)d_in[9];
    const float* fcg1_W   = (const float*)d_in[10];
    const float* fcg1_b   = (const float*)d_in[11];
    const float* fcg2_W   = (const float*)d_in[12];
    const float* fcg2_b   = (const float*)d_in[13];
    const float* emb      = (const float*)d_in[14];
    const float* conv_W   = (const float*)d_in[15];
    const float* conv_b   = (const float*)d_in[16];
    const float* fcxt_W   = (const float*)d_in[17];
    const float* fcxt_b   = (const float*)d_in[18];
    const float* fc1_W    = (const float*)d_in[19];
    const float* fc1_b    = (const float*)d_in[20];
    const float* fc2_W    = (const float*)d_in[21];
    const float* fc2_b    = (const float*)d_in[22];
    const float* out_W    = (const float*)d_in[23];
    const float* out_b    = (const float*)d_in[24];

    float *p_h, *p_h2, *p_xg1, *p_xc, *p_conv, *p_f1, *p_f2, *p_fcxtb2;
    __nv_bfloat16 *p_xh, *p_xl, *p_x1h, *p_x1l, *p_gWh, *p_gWl, *p_cWh, *p_cWl;
    __nv_bfloat16 *p_poolh, *p_pooll, *p_fWh, *p_fWl, *p_Uh, *p_Ul, *p_Mmh, *p_Mml;
    cudaGetSymbolAddress((void**)&p_h,    d_h);
    cudaGetSymbolAddress((void**)&p_h2,   d_h2);
    cudaGetSymbolAddress((void**)&p_xg1,  d_xg1);
    cudaGetSymbolAddress((void**)&p_xc,   d_xc);
    cudaGetSymbolAddress((void**)&p_conv, d_conv);
    cudaGetSymbolAddress((void**)&p_f1,   d_f1);
    cudaGetSymbolAddress((void**)&p_f2,   d_f2);
    cudaGetSymbolAddress((void**)&p_fcxtb2, d_fcxtb2);
    cudaGetSymbolAddress((void**)&p_xh,  d_xh);
    cudaGetSymbolAddress((void**)&p_xl,  d_xl);
    cudaGetSymbolAddress((void**)&p_x1h, d_x1h);
    cudaGetSymbolAddress((void**)&p_x1l, d_x1l);
    cudaGetSymbolAddress((void**)&p_gWh, d_gWh);
    cudaGetSymbolAddress((void**)&p_gWl, d_gWl);
    cudaGetSymbolAddress((void**)&p_cWh, d_cWh);
    cudaGetSymbolAddress((void**)&p_cWl, d_cWl);
    cudaGetSymbolAddress((void**)&p_poolh, d_poolh);
    cudaGetSymbolAddress((void**)&p_pooll, d_pooll);
    cudaGetSymbolAddress((void**)&p_fWh, d_fWh);
    cudaGetSymbolAddress((void**)&p_fWl, d_fWl);
    cudaGetSymbolAddress((void**)&p_Uh, d_Uh);
    cudaGetSymbolAddress((void**)&p_Ul, d_Ul);
    cudaGetSymbolAddress((void**)&p_Mmh, d_Mmh);
    cudaGetSymbolAddress((void**)&p_Mml, d_Mml);

    cudaFuncSetAttribute(gemm_mma, cudaFuncAttributeMaxDynamicSharedMemorySize, 2*STG);

    // launches 0..2: splits (launch 3 = gemm_mma GAT lands under ncu -s 5)
    k_split_x<<<(NN*KP_GAT + 255)/256, 256>>>(x);
    k_splitB<<<(NPADG*KP_GAT + 255)/256, 256>>>(gat_W, p_gWh, p_gWl, NF, HF, KP_GAT, NPADG);
    k_splitB<<<(NPADG*KP_GCN + 255)/256, 256>>>(gcn_W, p_cWh, p_cWl, HF, HF, KP_GCN, NPADG);

    // launch 3: GAT transform (profiled) — Ksteps=5 covers K=78
    {
        dim3 grid(NPADG/64, (NN + 127)/128);
        gemm_mma<<<grid, 256, 2*STG>>>(p_xh, p_xl, p_gWh, p_gWl, p_h, NN, HF, KP_GAT, HF, nullptr, 0, NPADG, 5);
    }

    // CSR build
    k_deg_init<<<(NN + 255)/256, 256>>>();
    k_count<<<(NE + 255)/256, 256>>>(ei);
    k_scan<<<1, 1024>>>();
    k_fill<<<(NEP + 255)/256, 256>>>(ei);
    k_dinv<<<(NN + 255)/256, 256>>>();

    // remaining prep
    k_splitB<<<(NP_FCG1*KP_POOL + 255)/256, 256>>>(fcg1_W, p_fWh, p_fWl, 2*HF, 1024, KP_POOL, NP_FCG1);
    k_buildM<<<(128*KP_U + 255)/256, 256>>>(emb);
    k_transW<<<(NFILT*SEQL*8 + 255)/256, 256>>>(conv_W);

    // GAT attention (folded) + aggregation
    k_attw<<<(2*NF*NH*32 + 255)/256, 256>>>(gat_W, gat_asrc, gat_adst);
    k_asrcdst<<<(NN + 255)/256, 256>>>(x);
    k_gat_soft<<<(NN*32 + 255)/256, 256>>>();
    k_gat_agg<<<NN, 256>>>(gat_b);

    // GCN — Ksteps=49 covers K=780
    {
        dim3 grid(NPADG/64, (NN + 127)/128);
        gemm_mma<<<grid, 256, 2*STG>>>(p_x1h, p_x1l, p_cWh, p_cWl, p_h2, NN, HF, KP_GCN, HF, nullptr, 0, NPADG, 49);
    }
    k_gcn_agg<<<NN, 256>>>(gcn_b);

    // pooling + graph head
    k_start<<<3, 256>>>(batch);
    k_pool<<<NG, 256>>>();
    {   // fcg1 — Ksteps=98 covers K=1560
        dim3 grid(1024/64, NG/128);
        gemm_mma<<<grid, 256, 2*STG>>>(p_poolh, p_pooll, p_fWh, p_fWl, p_xg1, NG, 1024, KP_POOL, 1024, fcg1_b, 1, NP_FCG1, 98);
    }
    {
        k_binit<<<(NG*128 + 255)/256, 256>>>(p_xc, fcg2_b, NG, 128, 256);
        dim3 grid(2, 8, 4);
        gemm2_kernel<<<grid, 256>>>(p_xg1, fcg2_W, nullptr, p_xc, NG, 128, 1024, 256, 0);
    }

    // target branch
    k_buildU<<<NG, 256>>>(target);
    {   // conv GEMM — Ksteps=13 covers K=208
        dim3 grid(2, (NG*NFILT)/128);
        gemm_mma<<<grid, 256, 2*STG>>>(p_Uh, p_Ul, p_Mmh, p_Mml, p_conv, NG*NFILT, CONVOUT, KP_U, CONVOUT, nullptr, 0, 128, 13);
    }
    k_fcxtb2<<<128, 128>>>(fcxt_W, fcxt_b, conv_b);
    {
        k_binit<<<(NG*128 + 255)/256, 256>>>(p_xc + 128, p_fcxtb2, NG, 128, 256);
        dim3 grid(2, 8, 4);
        gemm2_kernel<<<grid, 256>>>(p_conv, fcxt_W, nullptr, p_xc + 128, NG, 128, NFILT*CONVOUT, 256, 0);
    }

    // fusion head
    {
        dim3 grid(16, 8, 1);
        gemm2_kernel<<<grid, 256>>>(p_xc, fc1_W, fc1_b, p_f1, NG, 1024, 256, 1024, 1);
    }
    {
        k_binit<<<(NG*512 + 255)/256, 256>>>(p_f2, fc2_b, NG, 512, 512);
        dim3 grid(8, 8, 2);
        gemm2_kernel<<<grid, 256>>>(p_f1, fc2_W, nullptr, p_f2, NG, 512, 1024, 512, 0);
        k_relu<<<(NG*512 + 255)/256, 256>>>(p_f2, NG*512);
    }
    k_out<<<(NG*32 + 255)/256, 256>>>(out_W, out_b, (float*)d_out);
}

// round 12
// speedup vs baseline: 1.1681x; 1.1014x over previous
#include <cuda_runtime.h>
#include <cuda_fp16.h>
#include <math.h>
#include <stdint.h>

#define NN      25000
#define NE      100000
#define NEP     125000
#define NG      512
#define NH      10
#define NF      78
#define HF      780
#define SEQL    1000
#define EMB     128
#define NFILT   32
#define CONVOUT 121
#define VOCAB   26
#define UCOLS   (VOCAB*8)        // 208
#define USZ     (NFILT*UCOLS)

#define KP_GAT  128
#define KP_GCN  832
#define NPADG   832
#define KP_POOL 1600
#define NP_FCG1 1024
#define KP_U    256

// ---------------- device scratch ----------------
__device__ float d_h[NN*HF];
__device__ float d_asrc[NN*NH];
__device__ float d_adst[NN*NH];
__device__ float d_wsrc[NF*NH];
__device__ float d_wdst[NF*NH];
__device__ float d_invden[NN*NH];
__device__ float d_alpha[(size_t)NEP*NH];
__device__ float d_h2[NN*HF];
__device__ float d_x2[NN*HF];
__device__ float d_dinv[NN];
__device__ int   d_deg[NN];
__device__ int   d_roff[NN+1];
__device__ int   d_rpos[NN];
__device__ int   d_csrc[NEP];
__device__ int   d_start[NG+1];
__device__ float d_xg1[NG*1024];
__device__ float d_Wt[SEQL*NFILT*8];
__device__ float d_conv[(size_t)NG*NFILT*CONVOUT];
__device__ float d_fcxtb2[128];
__device__ float d_xc[NG*256];
__device__ float d_f1[NG*1024];
__device__ float d_f2[NG*512];
__device__ __half d_xA[(size_t)NN*KP_GAT];
__device__ __half d_xAl[(size_t)NN*KP_GAT];
__device__ __half d_x1A[(size_t)NN*KP_GCN];
__device__ __half d_gWh[(size_t)NPADG*KP_GAT];
__device__ __half d_gWl[(size_t)NPADG*KP_GAT];
__device__ __half d_cWh[(size_t)NPADG*KP_GCN];
__device__ __half d_cWl[(size_t)NPADG*KP_GCN];
__device__ __half d_poolh[(size_t)NG*KP_POOL];
__device__ __half d_pooll[(size_t)NG*KP_POOL];
__device__ __half d_fWh[(size_t)NP_FCG1*KP_POOL];
__device__ __half d_fWl[(size_t)NP_FCG1*KP_POOL];
__device__ __half d_Uh[(size_t)NG*NFILT*KP_U];
__device__ __half d_Ul[(size_t)NG*NFILT*KP_U];
__device__ __half d_Mmh[128*KP_U];
__device__ __half d_Mml[128*KP_U];

// ================= helpers =================
__device__ __forceinline__ uint32_t smem_u32(const void* p){
    uint32_t a;
    asm("{ .reg .u64 t; cvta.to.shared.u64 t, %1; cvt.u32.u64 %0, t; }" : "=r"(a) : "l"(p));
    return a;
}
#define LDMX4(r, a) \
    asm volatile("ldmatrix.sync.aligned.m8n8.x4.shared.b16 {%0,%1,%2,%3}, [%4];" \
        : "=r"((r)[0]), "=r"((r)[1]), "=r"((r)[2]), "=r"((r)[3]) : "r"(a))
#define MMA16816(d, a, b0, b1) \
    asm volatile("mma.sync.aligned.m16n8k16.row.col.f32.f16.f16.f32 " \
        "{%0,%1,%2,%3}, {%4,%5,%6,%7}, {%8,%9}, {%0,%1,%2,%3};" \
        : "+f"((d)[0]), "+f"((d)[1]), "+f"((d)[2]), "+f"((d)[3]) \
        : "r"((a)[0]), "r"((a)[1]), "r"((a)[2]), "r"((a)[3]), "r"(b0), "r"(b1))
#define CPA_COMMIT() asm volatile("cp.async.commit_group;" ::: "memory")
#define CPA_WAIT0()  asm volatile("cp.async.wait_group 0;" ::: "memory")

__device__ __forceinline__ void cpa16(uint32_t dst, const void* src, int sz){
    size_t g;
    asm("cvta.to.global.u64 %0, %1;" : "=l"(g) : "l"(src));
    asm volatile("cp.async.cg.shared.global [%0], [%1], 16, %2;" :: "r"(dst), "l"(g), "r"(sz) : "memory");
}
__device__ __forceinline__ void split_fp16(float v, __half& h, __half& l){
    h = __float2half_rn(v);
    l = __float2half_rn(v - __half2float(h));
}

// ================= mma.sync fp16 split GEMM (128x64 tile, Ksteps-masked) =================
#define GPITCH 72
#define ATILEB 18432
#define BTILEB 9216

__device__ __forceinline__ void ld_tileA(uint32_t sdst, const __half* G,
                                         int row0, int k0, int KP, int rlim, int tid){
    #pragma unroll
    for (int i = 0; i < 4; i++){
        int v = tid + i*256;
        int r = v >> 3, cq = v & 7;
        int row = row0 + r;
        int sz = (row < rlim) ? 16 : 0;
        cpa16(sdst + r*144 + cq*16, G + (size_t)(sz ? row : row0)*KP + k0 + cq*8, sz);
    }
}
__device__ __forceinline__ void ld_tileB(uint32_t sdst, const __half* G,
                                         int row0, int k0, int KP, int rlim, int tid){
    #pragma unroll
    for (int i = 0; i < 2; i++){
        int v = tid + i*256;
        int r = v >> 3, cq = v & 7;
        int row = row0 + r;
        int sz = (row < rlim) ? 16 : 0;
        cpa16(sdst + r*144 + cq*16, G + (size_t)(sz ? row : row0)*KP + k0 + cq*8, sz);
    }
}

// TERMS=3: C = (A+Al)(Bh+Bl) - AlBl ; TERMS=2: C = A(Bh+Bl), A single fp16.
template<int TERMS>
__global__ void __launch_bounds__(256, 2) gemm_mma_t(
    const __half* __restrict__ A, const __half* __restrict__ Al,
    const __half* __restrict__ Bh, const __half* __restrict__ Bl,
    float* __restrict__ C, int M, int Nout, int KP, int ldc,
    const float* __restrict__ bias, int act, int Brows, int Ksteps)
{
    constexpr int STGT = (TERMS == 3) ? (2*ATILEB + 2*BTILEB) : (ATILEB + 2*BTILEB);
    extern __shared__ char sm[];
    uint32_t sb = smem_u32(sm);
    int tid = threadIdx.x;
    int m0 = blockIdx.y*128, n0 = blockIdx.x*64;
    int w = tid >> 5, lane = tid & 31;
    int wm = (w >> 1) * 32;
    int wn = (w & 1) * 32;
    int NC = KP / 64;

    float acc[2][4][4];
    #pragma unroll
    for (int i=0;i<2;i++)
        #pragma unroll
        for (int j=0;j<4;j++)
            #pragma unroll
            for (int q=0;q<4;q++) acc[i][j][q] = 0.f;

    int a_row = (lane & 15);
    int a_kc  = (lane >> 4) * 8;
    int b_row = ((lane >> 4) * 8) + (lane & 7);
    int b_kc  = ((lane >> 3) & 1) * 8;

    ld_tileA(sb + 0,               A,  m0, 0, KP, M, tid);
    ld_tileB(sb + ATILEB,          Bh, n0, 0, KP, Brows, tid);
    ld_tileB(sb + ATILEB + BTILEB, Bl, n0, 0, KP, Brows, tid);
    if (TERMS == 3) ld_tileA(sb + ATILEB + 2*BTILEB, Al, m0, 0, KP, M, tid);
    CPA_COMMIT();

    for (int ci = 0; ci < NC; ci++){
        int b = ci & 1;
        uint32_t st = sb + b*STGT;
        CPA_WAIT0();
        __syncthreads();
        if (ci + 1 < NC){
            uint32_t s2 = sb + (1-b)*STGT;
            int k0n = (ci+1)*64;
            ld_tileA(s2 + 0,               A,  m0, k0n, KP, M, tid);
            ld_tileB(s2 + ATILEB,          Bh, n0, k0n, KP, Brows, tid);
            ld_tileB(s2 + ATILEB + BTILEB, Bl, n0, k0n, KP, Brows, tid);
            if (TERMS == 3) ld_tileA(s2 + ATILEB + 2*BTILEB, Al, m0, k0n, KP, M, tid);
            CPA_COMMIT();
        }
        uint32_t bA = st, bBh = st + ATILEB, bBl = st + ATILEB + BTILEB;
        uint32_t bAl = st + ATILEB + 2*BTILEB;
        #pragma unroll
        for (int kk = 0; kk < 64; kk += 16){
            if (ci*4 + (kk >> 4) >= Ksteps) break;
            uint32_t ah[2][4], al[2][4];
            #pragma unroll
            for (int mt = 0; mt < 2; mt++){
                uint32_t off = (uint32_t)((wm + mt*16 + a_row)*GPITCH + kk + a_kc) * 2;
                LDMX4(ah[mt], bA + off);
                if (TERMS == 3) LDMX4(al[mt], bAl + off);
            }
            #pragma unroll
            for (int nt2 = 0; nt2 < 2; nt2++){
                uint32_t offb = (uint32_t)((wn + nt2*16 + b_row)*GPITCH + kk + b_kc) * 2;
                uint32_t bhf[4], blf[4];
                LDMX4(bhf, bBh + offb);
                LDMX4(blf, bBl + offb);
                #pragma unroll
                for (int mt = 0; mt < 2; mt++){
                    MMA16816(acc[mt][nt2*2],   ah[mt], bhf[0], bhf[1]);
                    MMA16816(acc[mt][nt2*2+1], ah[mt], bhf[2], bhf[3]);
                }
                #pragma unroll
                for (int mt = 0; mt < 2; mt++){
                    MMA16816(acc[mt][nt2*2],   ah[mt], blf[0], blf[1]);
                    MMA16816(acc[mt][nt2*2+1], ah[mt], blf[2], blf[3]);
                }
                if (TERMS == 3){
                    #pragma unroll
                    for (int mt = 0; mt < 2; mt++){
                        MMA16816(acc[mt][nt2*2],   al[mt], bhf[0], bhf[1]);
                        MMA16816(acc[mt][nt2*2+1], al[mt], bhf[2], bhf[3]);
                    }
                }
            }
        }
    }
    #pragma unroll
    for (int mt = 0; mt < 2; mt++){
        int r0 = m0 + wm + mt*16 + (lane >> 2);
        #pragma unroll
        for (int nt = 0; nt < 4; nt++){
            int c = n0 + wn + nt*8 + (lane & 3)*2;
            #pragma unroll
            for (int half2 = 0; half2 < 2; half2++){
                int rr = r0 + half2*8;
                if (rr >= M) continue;
                #pragma unroll
                for (int q = 0; q < 2; q++){
                    int cc = c + q;
                    if (cc >= Nout) continue;
                    float v = acc[mt][nt][half2*2 + q];
                    if (bias) v += bias[cc];
                    if (act)  v = fmaxf(v, 0.f);
                    C[(size_t)rr*ldc + cc] = v;
                }
            }
        }
    }
}

// ================= split-prep =================
__global__ void k_split_x(const float* __restrict__ x){
    int i = blockIdx.x*blockDim.x + threadIdx.x;
    if (i >= NN*KP_GAT) return;
    int r = i >> 7, k = i & (KP_GAT-1);
    float v = (k < NF) ? x[r*NF + k] : 0.f;
    __half h, l; split_fp16(v, h, l);
    d_xA[i] = h; d_xAl[i] = l;
}
__global__ void k_splitB(const float* __restrict__ W, __half* __restrict__ bh,
                         __half* __restrict__ bl, int K, int N, int KP, int NR){
    int i = blockIdx.x*blockDim.x + threadIdx.x;
    if (i >= NR*KP) return;
    int n = i / KP, k = i - n*KP;
    float v = (k < K && n < N) ? W[(size_t)k*N + n] : 0.f;
    __half h, l; split_fp16(v, h, l);
    bh[i] = h; bl[i] = l;
}

// ================= CSR build =================
__global__ void k_deg_init(){
    int n = blockIdx.x*blockDim.x + threadIdx.x;
    if (n < NN) d_deg[n] = 1;
}
__global__ void k_count(const int* __restrict__ ei){
    int e = blockIdx.x*blockDim.x + threadIdx.x;
    if (e < NE) atomicAdd(&d_deg[ei[NE+e]], 1);
}
__global__ void k_scan(){
    __shared__ int part[1024];
    int t = threadIdx.x;
    const int PER = 25;
    int base = t*PER, sum = 0;
    for (int i = 0; i < PER; i++){ int idx = base+i; if (idx < NN) sum += d_deg[idx]; }
    part[t] = sum; __syncthreads();
    for (int off = 1; off < 1024; off <<= 1){
        int v = (t >= off) ? part[t-off] : 0; __syncthreads();
        part[t] += v; __syncthreads();
    }
    int run = part[t] - sum;
    for (int i = 0; i < PER; i++){
        int idx = base+i;
        if (idx < NN){ d_roff[idx] = run; d_rpos[idx] = run; run += d_deg[idx]; }
    }
    if (t == 1023) d_roff[NN] = NEP;
}
__global__ void k_fill(const int* __restrict__ ei){
    int e = blockIdx.x*blockDim.x + threadIdx.x;
    if (e >= NEP) return;
    int s, d;
    if (e < NE){ s = ei[e]; d = ei[NE+e]; } else { s = d = e - NE; }
    int pos = atomicAdd(&d_rpos[d], 1);
    d_csrc[pos] = s;
}
__global__ void k_dinv(){
    int n = blockIdx.x*blockDim.x + threadIdx.x;
    if (n < NN) d_dinv[n] = rsqrtf((float)d_deg[n]);
}

// ================= GAT attention (folded) =================
__global__ void k_attw(const float* __restrict__ gat_W,
                       const float* __restrict__ att_src,
                       const float* __restrict__ att_dst){
    int wid  = (blockIdx.x*blockDim.x + threadIdx.x) >> 5;
    int lane = threadIdx.x & 31;
    if (wid >= 2*NF*NH) return;
    int which = (wid >= NF*NH);
    int r = wid - which*NF*NH;
    int f_in = r / NH, hh = r - f_in*NH;
    const float* att = which ? att_dst : att_src;
    float s = 0.f;
    for (int f = lane; f < NF; f += 32)
        s += gat_W[(size_t)f_in*HF + hh*NF + f] * att[hh*NF + f];
    #pragma unroll
    for (int o = 16; o > 0; o >>= 1) s += __shfl_down_sync(~0u, s, o);
    if (!lane){
        if (which) d_wdst[f_in*NH + hh] = s;
        else       d_wsrc[f_in*NH + hh] = s;
    }
}
__global__ void k_asrcdst(const float* __restrict__ x){
    __shared__ float ws[NF*NH], wd[NF*NH];
    int tid = threadIdx.x;
    for (int i = tid; i < NF*NH; i += 256){ ws[i] = d_wsrc[i]; wd[i] = d_wdst[i]; }
    __syncthreads();
    int n = blockIdx.x*256 + tid;
    if (n >= NN) return;
    float as[NH], ad[NH];
    #pragma unroll
    for (int hh = 0; hh < NH; hh++){ as[hh] = 0.f; ad[hh] = 0.f; }
    const float* xr = x + (size_t)n*NF;
    for (int f = 0; f < NF; f++){
        float xv = xr[f];
        #pragma unroll
        for (int hh = 0; hh < NH; hh++){
            as[hh] += xv * ws[f*NH + hh];
            ad[hh] += xv * wd[f*NH + hh];
        }
    }
    #pragma unroll
    for (int hh = 0; hh < NH; hh++){
        d_asrc[n*NH + hh] = as[hh];
        d_adst[n*NH + hh] = ad[hh];
    }
}

__global__ void k_gat_soft(){
    int w    = (blockIdx.x*blockDim.x + threadIdx.x) >> 5;
    int lane = threadIdx.x & 31;
    if (w >= NN || lane >= NH) return;
    int s0 = d_roff[w], s1 = d_roff[w+1];
    float ad = d_adst[w*NH + lane];
    float mx = -1e30f;
    for (int p = s0; p < s1; p++){
        float a = d_asrc[d_csrc[p]*NH + lane] + ad;
        a = a > 0.f ? a : 0.2f*a;
        mx = fmaxf(mx, a);
    }
    float sum = 0.f;
    for (int p = s0; p < s1; p++){
        float a = d_asrc[d_csrc[p]*NH + lane] + ad;
        a = a > 0.f ? a : 0.2f*a;
        float e = expf(a - mx);
        d_alpha[(size_t)p*NH + lane] = e;
        sum += e;
    }
    d_invden[w*NH + lane] = 1.f / (sum + 1e-16f);
}
__global__ void k_gat_agg(const float* __restrict__ gat_b){
    int n = blockIdx.x;
    int tid = threadIdx.x;
    __shared__ float invd[NH];
    __shared__ int   csrc_c[25];
    __shared__ float coef_c[25][NH];
    if (tid < NH) invd[tid] = d_invden[n*NH + tid];
    __syncthreads();
    int s0 = d_roff[n], s1 = d_roff[n+1];
    float4 acc = make_float4(0.f,0.f,0.f,0.f);
    int c0 = tid*4;
    int h0 = c0/NF, h1 = (c0+1)/NF, h2 = (c0+2)/NF, h3 = (c0+3)/NF;
    for (int base = s0; base < s1; base += 25){
        int cnt = s1 - base; if (cnt > 25) cnt = 25;
        if (tid < cnt) csrc_c[tid] = d_csrc[base + tid];
        if (tid < cnt*NH){
            int p = tid / NH, hh = tid - p*NH;
            coef_c[p][hh] = d_alpha[(size_t)(base+p)*NH + hh] * invd[hh];
        }
        __syncthreads();
        if (tid < 195){
            #pragma unroll 2
            for (int j = 0; j < cnt; j++){
                float4 v = *(const float4*)(d_h + (size_t)csrc_c[j]*HF + c0);
                acc.x += coef_c[j][h0]*v.x;
                acc.y += coef_c[j][h1]*v.y;
                acc.z += coef_c[j][h2]*v.z;
                acc.w += coef_c[j][h3]*v.w;
            }
        }
        __syncthreads();
    }
    if (tid < 195){
        float4 bb = *(const float4*)(gat_b + c0);
        #pragma unroll
        for (int q = 0; q < 4; q++){
            float r = fmaxf(((float*)&acc)[q] + ((float*)&bb)[q], 0.f);
            d_x1A[(size_t)n*KP_GCN + c0 + q] = __float2half_rn(r);
        }
    } else if (tid < 208){
        #pragma unroll
        for (int q = 0; q < 4; q++)
            d_x1A[(size_t)n*KP_GCN + c0 + q] = __float2half_rn(0.f);
    }
}

// ================= GCN aggregate =================
__global__ void k_gcn_agg(const float* __restrict__ gcn_b){
    int n = blockIdx.x;
    int tid = threadIdx.x;
    __shared__ int   csrc_c[64];
    __shared__ float coef_c[64];
    int s0 = d_roff[n], s1 = d_roff[n+1];
    float dn = d_dinv[n];
    float4 acc = make_float4(0.f,0.f,0.f,0.f);
    int c0 = tid*4;
    for (int base = s0; base < s1; base += 64){
        int cnt = s1 - base; if (cnt > 64) cnt = 64;
        if (tid < cnt){
            int s = d_csrc[base + tid];
            csrc_c[tid] = s;
            coef_c[tid] = dn * d_dinv[s];
        }
        __syncthreads();
        if (tid < 195){
            #pragma unroll 2
            for (int j = 0; j < cnt; j++){
                float4 v = *(const float4*)(d_h2 + (size_t)csrc_c[j]*HF + c0);
                float cf = coef_c[j];
                acc.x += cf*v.x; acc.y += cf*v.y; acc.z += cf*v.z; acc.w += cf*v.w;
            }
        }
        __syncthreads();
    }
    if (tid < 195){
        float4 bb = *(const float4*)(gcn_b + c0);
        float4 r = make_float4(fmaxf(acc.x + bb.x, 0.f), fmaxf(acc.y + bb.y, 0.f),
                               fmaxf(acc.z + bb.z, 0.f), fmaxf(acc.w + bb.w, 0.f));
        *(float4*)(d_x2 + (size_t)n*HF + c0) = r;
    }
}

// ================= pooling =================
__global__ void k_start(const int* __restrict__ batch){
    int g = blockIdx.x*blockDim.x + threadIdx.x;
    if (g > NG) return;
    if (g == NG){ d_start[NG] = NN; return; }
    int lo = 0, hi = NN;
    while (lo < hi){ int mid = (lo+hi) >> 1; if (batch[mid] < g) lo = mid+1; else hi = mid; }
    d_start[g] = lo;
}
__global__ void k_pool(){
    int g = blockIdx.x;
    int s = d_start[g], e = d_start[g+1];
    int cnt = e - s;
    size_t rb = (size_t)g*KP_POOL;
    for (int c = threadIdx.x; c < HF; c += blockDim.x){
        float mx = -1e30f, sm = 0.f;
        #pragma unroll 4
        for (int n = s; n < e; n++){
            float v = d_x2[(size_t)n*HF + c];
            mx = fmaxf(mx, v); sm += v;
        }
        float vmax = (cnt > 0) ? mx : 0.f;
        float vmean = sm / fmaxf((float)cnt, 1.f);
        __half h, l;
        split_fp16(vmax, h, l);  d_poolh[rb + c] = h;      d_pooll[rb + c] = l;
        split_fp16(vmean, h, l); d_poolh[rb + HF + c] = h; d_pooll[rb + HF + c] = l;
    }
    if (threadIdx.x < KP_POOL - 2*HF){
        d_poolh[rb + 2*HF + threadIdx.x] = __float2half_rn(0.f);
        d_pooll[rb + 2*HF + threadIdx.x] = __float2half_rn(0.f);
    }
}

// ================= small GEMM (f32x2, split-K) =================
__global__ void gemm2_kernel(const float* __restrict__ A, const float* __restrict__ B,
                             const float* __restrict__ bias, float* __restrict__ C,
                             int M, int N, int K, int ldc, int act)
{
    __shared__ float As[16*64];
    __shared__ float Bs[16*64];
    int tid = threadIdx.x;
    int row0 = blockIdx.y*64, col0 = blockIdx.x*64;
    int tx = tid & 15, ty = tid >> 4;
    int Z = gridDim.z, z = blockIdx.z;
    int T = (K + 15) / 16;
    int kc0 = (int)((long long)T * z / Z), kc1 = (int)((long long)T * (z+1) / Z);
    unsigned long long acc2[4][2];
    #pragma unroll
    for (int i=0;i<4;i++){ acc2[i][0] = 0ull; acc2[i][1] = 0ull; }
    for (int kc = kc0; kc < kc1; kc++){
        int k0 = kc*16;
        #pragma unroll
        for (int i=0;i<4;i++){
            int l = tid + i*256;
            int m = l >> 4, kk = l & 15;
            int r = row0 + m, kg = k0 + kk;
            As[kk*64+m] = (r < M && kg < K) ? A[(size_t)r*K + kg] : 0.f;
        }
        #pragma unroll
        for (int i=0;i<4;i++){
            int l = tid + i*256;
            int kk = l >> 6, n = l & 63;
            int kg = k0 + kk, c = col0 + n;
            Bs[kk*64+n] = (kg < K && c < N) ? B[(size_t)kg*N + c] : 0.f;
        }
        __syncthreads();
        #pragma unroll
        for (int kk=0; kk<16; kk++){
            float ra[4];
            #pragma unroll
            for (int i=0;i<4;i++) ra[i] = As[kk*64 + ty*4 + i];
            unsigned long long rb0 = *(const unsigned long long*)&Bs[kk*64 + tx*4];
            unsigned long long rb1 = *(const unsigned long long*)&Bs[kk*64 + tx*4 + 2];
            #pragma unroll
            for (int i=0;i<4;i++){
                unsigned long long ad;
                asm("mov.b64 %0, {%1, %1};" : "=l"(ad) : "r"(__float_as_uint(ra[i])));
                asm("fma.rn.f32x2 %0, %1, %2, %0;" : "+l"(acc2[i][0]) : "l"(ad), "l"(rb0));
                asm("fma.rn.f32x2 %0, %1, %2, %0;" : "+l"(acc2[i][1]) : "l"(ad), "l"(rb1));
            }
        }
        __syncthreads();
    }
    #pragma unroll
    for (int i=0;i<4;i++){
        int r = row0 + ty*4 + i;
        if (r >= M) continue;
        #pragma unroll
        for (int jp=0;jp<2;jp++){
            unsigned int lo, hi;
            asm("mov.b64 {%0, %1}, %2;" : "=r"(lo), "=r"(hi) : "l"(acc2[i][jp]));
            float vv[2] = { __uint_as_float(lo), __uint_as_float(hi) };
            int c = col0 + tx*4 + jp*2;
            #pragma unroll
            for (int q=0;q<2;q++){
                int cc = c + q;
                if (cc >= N) continue;
                if (Z == 1){
                    float v = vv[q];
                    if (bias) v += bias[cc];
                    if (act)  v = fmaxf(v, 0.f);
                    C[(size_t)r*ldc + cc] = v;
                } else {
                    atomicAdd(&C[(size_t)r*ldc + cc], vv[q]);
                }
            }
        }
    }
}

__global__ void k_binit(float* __restrict__ C, const float* __restrict__ bias,
                        int M, int N, int ldc){
    int i = blockIdx.x*blockDim.x + threadIdx.x;
    if (i >= M*N) return;
    int r = i / N, c = i - r*N;
    C[(size_t)r*ldc + c] = bias[c];
}
__global__ void k_relu(float* __restrict__ C, int total){
    int i = blockIdx.x*blockDim.x + threadIdx.x;
    if (i < total) C[i] = fmaxf(C[i], 0.f);
}

// ================= target branch =================
__global__ void k_buildM(const float* __restrict__ emb){
    int i = blockIdx.x*blockDim.x + threadIdx.x;
    if (i >= 128*KP_U) return;
    int p = i / KP_U, kidx = i - p*KP_U;
    float val = 0.f;
    if (p < CONVOUT && kidx < UCOLS){
        int v = kidx >> 3, kk = kidx & 7;
        val = emb[v*EMB + p + kk];
    }
    __half h, l; split_fp16(val, h, l);
    d_Mmh[i] = h; d_Mml[i] = l;
}
__global__ void k_transW(const float* __restrict__ W){
    int i = blockIdx.x*blockDim.x + threadIdx.x;
    if (i >= NFILT*SEQL*8) return;
    int o = i / (SEQL*8), c = (i >> 3) % SEQL, k = i & 7;
    d_Wt[c*(NFILT*8) + o*8 + k] = W[i];
}
__global__ void k_buildU(const int* __restrict__ target){
    __shared__ float sU[USZ];
    __shared__ int   st[SEQL];
    int g = blockIdx.x;
    for (int i = threadIdx.x; i < USZ;  i += blockDim.x) sU[i] = 0.f;
    for (int i = threadIdx.x; i < SEQL; i += blockDim.x) st[i] = target[g*SEQL + i];
    __syncthreads();
    int o = threadIdx.x >> 3, k = threadIdx.x & 7;
    for (int c = 0; c < SEQL; c++){
        int v = st[c];
        sU[o*UCOLS + v*8 + k] += d_Wt[c*(NFILT*8) + threadIdx.x];
    }
    __syncthreads();
    for (int i = threadIdx.x; i < NFILT*KP_U; i += blockDim.x){
        int oo = i / KP_U, col = i - oo*KP_U;
        float v = (col < UCOLS) ? sU[oo*UCOLS + col] : 0.f;
        __half h, l; split_fp16(v, h, l);
        size_t idx = ((size_t)g*NFILT + oo)*KP_U + col;
        d_Uh[idx] = h; d_Ul[idx] = l;
    }
}
__global__ void k_fcxtb2(const float* __restrict__ fcxt_W,
                         const float* __restrict__ fcxt_b,
                         const float* __restrict__ conv_b){
    int j = blockIdx.x;
    __shared__ float red[128];
    float s = 0.f;
    for (int r = threadIdx.x; r < NFILT*CONVOUT; r += blockDim.x)
        s += conv_b[r / CONVOUT] * fcxt_W[(size_t)r*128 + j];
    red[threadIdx.x] = s; __syncthreads();
    for (int o = 64; o > 0; o >>= 1){
        if (threadIdx.x < o) red[threadIdx.x] += red[threadIdx.x + o];
        __syncthreads();
    }
    if (!threadIdx.x) d_fcxtb2[j] = fcxt_b[j] + red[0];
}

// ================= final projection =================
__global__ void k_out(const float* __restrict__ oW, const float* __restrict__ ob,
                      float* __restrict__ out){
    int g    = (blockIdx.x*blockDim.x + threadIdx.x) >> 5;
    int lane = threadIdx.x & 31;
    if (g >= NG) return;
    float s = 0.f;
    for (int k = lane; k < 512; k += 32) s += d_f2[g*512 + k] * oW[k];
    #pragma unroll
    for (int o = 16; o > 0; o >>= 1) s += __shfl_down_sync(~0u, s, o);
    if (!lane) out[g] = s + ob[0];
}

extern "C" void kernel_launch(void* const* d_in, const int* in_sizes, int n_in,
                              void* d_out, int out_size){
    const float* x        = (const float*)d_in[0];
    const int*   ei       = (const int*)  d_in[1];
    const int*   batch    = (const int*)  d_in[2];
    const int*   target   = (const int*)  d_in[3];
    const float* gat_W    = (const float*)d_in[4];
    const float* gat_asrc = (const float*)d_in[5];
    const float* gat_adst = (const float*)d_in[6];
    const float* gat_b    = (const float*)d_in[7];
    const float* gcn_W    = (const float*)d_in[8];
    const float* gcn_b    = (const float*)d_in[9];
    const float* fcg1_W   = (const float*)d_in[10];
    const float* fcg1_b   = (const float*)d_in[11];
    const float* fcg2_W   = (const float*)d_in[12];
    const float* fcg2_b   = (const float*)d_in[13];
    const float* emb      = (const float*)d_in[14];
    const float* conv_W   = (const float*)d_in[15];
    const float* conv_b   = (const float*)d_in[16];
    const float* fcxt_W   = (const float*)d_in[17];
    const float* fcxt_b   = (const float*)d_in[18];
    const float* fc1_W    = (const float*)d_in[19];
    const float* fc1_b    = (const float*)d_in[20];
    const float* fc2_W    = (const float*)d_in[21];
    const float* fc2_b    = (const float*)d_in[22];
    const float* out_W    = (const float*)d_in[23];
    const float* out_b    = (const float*)d_in[24];

    float *p_h, *p_h2, *p_xg1, *p_xc, *p_conv, *p_f1, *p_f2, *p_fcxtb2;
    __half *p_xA, *p_xAl, *p_x1A, *p_gWh, *p_gWl, *p_cWh, *p_cWl;
    __half *p_poolh, *p_pooll, *p_fWh, *p_fWl, *p_Uh, *p_Ul, *p_Mmh, *p_Mml;
    cudaGetSymbolAddress((void**)&p_h,    d_h);
    cudaGetSymbolAddress((void**)&p_h2,   d_h2);
    cudaGetSymbolAddress((void**)&p_xg1,  d_xg1);
    cudaGetSymbolAddress((void**)&p_xc,   d_xc);
    cudaGetSymbolAddress((void**)&p_conv, d_conv);
    cudaGetSymbolAddress((void**)&p_f1,   d_f1);
    cudaGetSymbolAddress((void**)&p_f2,   d_f2);
    cudaGetSymbolAddress((void**)&p_fcxtb2, d_fcxtb2);
    cudaGetSymbolAddress((void**)&p_xA,  d_xA);
    cudaGetSymbolAddress((void**)&p_xAl, d_xAl);
    cudaGetSymbolAddress((void**)&p_x1A, d_x1A);
    cudaGetSymbolAddress((void**)&p_gWh, d_gWh);
    cudaGetSymbolAddress((void**)&p_gWl, d_gWl);
    cudaGetSymbolAddress((void**)&p_cWh, d_cWh);
    cudaGetSymbolAddress((void**)&p_cWl, d_cWl);
    cudaGetSymbolAddress((void**)&p_poolh, d_poolh);
    cudaGetSymbolAddress((void**)&p_pooll, d_pooll);
    cudaGetSymbolAddress((void**)&p_fWh, d_fWh);
    cudaGetSymbolAddress((void**)&p_fWl, d_fWl);
    cudaGetSymbolAddress((void**)&p_Uh, d_Uh);
    cudaGetSymbolAddress((void**)&p_Ul, d_Ul);
    cudaGetSymbolAddress((void**)&p_Mmh, d_Mmh);
    cudaGetSymbolAddress((void**)&p_Mml, d_Mml);

    const int STG3 = 2*ATILEB + 2*BTILEB;   // 55296
    const int STG2 = ATILEB + 2*BTILEB;     // 36864
    cudaFuncSetAttribute(gemm_mma_t<3>, cudaFuncAttributeMaxDynamicSharedMemorySize, 2*STG3);
    cudaFuncSetAttribute(gemm_mma_t<2>, cudaFuncAttributeMaxDynamicSharedMemorySize, 2*STG2);

    // launches 0..2: splits (launch 3 = gemm GAT lands under ncu -s 5)
    k_split_x<<<(NN*KP_GAT + 255)/256, 256>>>(x);
    k_splitB<<<(NPADG*KP_GAT + 255)/256, 256>>>(gat_W, p_gWh, p_gWl, NF, HF, KP_GAT, NPADG);
    k_splitB<<<(NPADG*KP_GCN + 255)/256, 256>>>(gcn_W, p_cWh, p_cWl, HF, HF, KP_GCN, NPADG);

    // launch 3: GAT transform (3-term fp16), Ksteps=5
    {
        dim3 grid(NPADG/64, (NN + 127)/128);
        gemm_mma_t<3><<<grid, 256, 2*STG3>>>(p_xA, p_xAl, p_gWh, p_gWl, p_h, NN, HF, KP_GAT, HF, nullptr, 0, NPADG, 5);
    }

    // CSR build
    k_deg_init<<<(NN + 255)/256, 256>>>();
    k_count<<<(NE + 255)/256, 256>>>(ei);
    k_scan<<<1, 1024>>>();
    k_fill<<<(NEP + 255)/256, 256>>>(ei);
    k_dinv<<<(NN + 255)/256, 256>>>();

    // remaining prep
    k_splitB<<<(NP_FCG1*KP_POOL + 255)/256, 256>>>(fcg1_W, p_fWh, p_fWl, 2*HF, 1024, KP_POOL, NP_FCG1);
    k_buildM<<<(128*KP_U + 255)/256, 256>>>(emb);
    k_transW<<<(NFILT*SEQL*8 + 255)/256, 256>>>(conv_W);

    // GAT attention (folded) + aggregation
    k_attw<<<(2*NF*NH*32 + 255)/256, 256>>>(gat_W, gat_asrc, gat_adst);
    k_asrcdst<<<(NN + 255)/256, 256>>>(x);
    k_gat_soft<<<(NN*32 + 255)/256, 256>>>();
    k_gat_agg<<<NN, 256>>>(gat_b);

    // GCN (2-term fp16: x1 single precision-quantized), Ksteps=49
    {
        dim3 grid(NPADG/64, (NN + 127)/128);
        gemm_mma_t<2><<<grid, 256, 2*STG2>>>(p_x1A, nullptr, p_cWh, p_cWl, p_h2, NN, HF, KP_GCN, HF, nullptr, 0, NPADG, 49);
    }
    k_gcn_agg<<<NN, 256>>>(gcn_b);

    // pooling + graph head
    k_start<<<3, 256>>>(batch);
    k_pool<<<NG, 256>>>();
    {   // fcg1 (3-term), Ksteps=98
        dim3 grid(1024/64, NG/128);
        gemm_mma_t<3><<<grid, 256, 2*STG3>>>(p_poolh, p_pooll, p_fWh, p_fWl, p_xg1, NG, 1024, KP_POOL, 1024, fcg1_b, 1, NP_FCG1, 98);
    }
    {
        k_binit<<<(NG*128 + 255)/256, 256>>>(p_xc, fcg2_b, NG, 128, 256);
        dim3 grid(2, 8, 4);
        gemm2_kernel<<<grid, 256>>>(p_xg1, fcg2_W, nullptr, p_xc, NG, 128, 1024, 256, 0);
    }

    // target branch
    k_buildU<<<NG, 256>>>(target);
    {   // conv GEMM (3-term), Ksteps=13
        dim3 grid(2, (NG*NFILT)/128);
        gemm_mma_t<3><<<grid, 256, 2*STG3>>>(p_Uh, p_Ul, p_Mmh, p_Mml, p_conv, NG*NFILT, CONVOUT, KP_U, CONVOUT, nullptr, 0, 128, 13);
    }
    k_fcxtb2<<<128, 128>>>(fcxt_W, fcxt_b, conv_b);
    {
        k_binit<<<(NG*128 + 255)/256, 256>>>(p_xc + 128, p_fcxtb2, NG, 128, 256);
        dim3 grid(2, 8, 4);
        gemm2_kernel<<<grid, 256>>>(p_conv, fcxt_W, nullptr, p_xc + 128, NG, 128, NFILT*CONVOUT, 256, 0);
    }

    // fusion head
    {
        dim3 grid(16, 8, 1);
        gemm2_kernel<<<grid, 256>>>(p_xc, fc1_W, fc1_b, p_f1, NG, 1024, 256, 1024, 1);
    }
    {
        k_binit<<<(NG*512 + 255)/256, 256>>>(p_f2, fc2_b, NG, 512, 512);
        dim3 grid(8, 8, 2);
        gemm2_kernel<<<grid, 256>>>(p_f1, fc2_W, nullptr, p_f2, NG, 512, 1024, 512, 0);
        k_relu<<<(NG*512 + 255)/256, 256>>>(p_f2, NG*512);
    }
    k_out<<<(NG*32 + 255)/256, 256>>>(out_W, out_b, (float*)d_out);
}

// round 13
// speedup vs baseline: 1.2201x; 1.0444x over previous
#include <cuda_runtime.h>
#include <cuda_fp16.h>
#include <math.h>
#include <stdint.h>

#define NN      25000
#define NE      100000
#define NEP     125000
#define NG      512
#define NH      10
#define NF      78
#define HF      780
#define SEQL    1000
#define EMB     128
#define NFILT   32
#define CONVOUT 121
#define VOCAB   26
#define UCOLS   (VOCAB*8)        // 208
#define USZ     (NFILT*UCOLS)

#define KP_GAT  128
#define KP_GCN  832
#define NPADG   832
#define KP_POOL 1600
#define NP_FCG1 1024
#define KP_U    256

// ---------------- device scratch ----------------
__device__ __half d_hh[(size_t)NN*HF];
__device__ __half d_h2h[(size_t)NN*HF];
__device__ float d_asrc[NN*NH];
__device__ float d_adst[NN*NH];
__device__ float d_wsrc[NF*NH];
__device__ float d_wdst[NF*NH];
__device__ float d_invden[NN*NH];
__device__ float d_alpha[(size_t)NEP*NH];
__device__ float d_x2[NN*HF];
__device__ float d_dinv[NN];
__device__ int   d_deg[NN];
__device__ int   d_roff[NN+1];
__device__ int   d_rpos[NN];
__device__ int   d_csrc[NEP];
__device__ int   d_start[NG+1];
__device__ float d_xg1[NG*1024];
__device__ float d_Wt[SEQL*NFILT*8];
__device__ float d_conv[(size_t)NG*NFILT*CONVOUT];
__device__ float d_fcxtb2[128];
__device__ float d_xc[NG*256];
__device__ float d_f1[NG*1024];
__device__ float d_f2[NG*512];
__device__ __half d_xA[(size_t)NN*KP_GAT];
__device__ __half d_x1A[(size_t)NN*KP_GCN];
__device__ __half d_gWh[(size_t)NPADG*KP_GAT];
__device__ __half d_gWl[(size_t)NPADG*KP_GAT];
__device__ __half d_cWh[(size_t)NPADG*KP_GCN];
__device__ __half d_cWl[(size_t)NPADG*KP_GCN];
__device__ __half d_poolA[(size_t)NG*KP_POOL];
__device__ __half d_fWh[(size_t)NP_FCG1*KP_POOL];
__device__ __half d_fWl[(size_t)NP_FCG1*KP_POOL];
__device__ __half d_UA[(size_t)NG*NFILT*KP_U];
__device__ __half d_Mmh[128*KP_U];
__device__ __half d_Mml[128*KP_U];

// ================= helpers =================
__device__ __forceinline__ uint32_t smem_u32(const void* p){
    uint32_t a;
    asm("{ .reg .u64 t; cvta.to.shared.u64 t, %1; cvt.u32.u64 %0, t; }" : "=r"(a) : "l"(p));
    return a;
}
#define LDMX4(r, a) \
    asm volatile("ldmatrix.sync.aligned.m8n8.x4.shared.b16 {%0,%1,%2,%3}, [%4];" \
        : "=r"((r)[0]), "=r"((r)[1]), "=r"((r)[2]), "=r"((r)[3]) : "r"(a))
#define MMA16816(d, a, b0, b1) \
    asm volatile("mma.sync.aligned.m16n8k16.row.col.f32.f16.f16.f32 " \
        "{%0,%1,%2,%3}, {%4,%5,%6,%7}, {%8,%9}, {%0,%1,%2,%3};" \
        : "+f"((d)[0]), "+f"((d)[1]), "+f"((d)[2]), "+f"((d)[3]) \
        : "r"((a)[0]), "r"((a)[1]), "r"((a)[2]), "r"((a)[3]), "r"(b0), "r"(b1))
#define CPA_COMMIT() asm volatile("cp.async.commit_group;" ::: "memory")
#define CPA_WAIT0()  asm volatile("cp.async.wait_group 0;" ::: "memory")

__device__ __forceinline__ void cpa16(uint32_t dst, const void* src, int sz){
    size_t g;
    asm("cvta.to.global.u64 %0, %1;" : "=l"(g) : "l"(src));
    asm volatile("cp.async.cg.shared.global [%0], [%1], 16, %2;" :: "r"(dst), "l"(g), "r"(sz) : "memory");
}
__device__ __forceinline__ void split_fp16(float v, __half& h, __half& l){
    h = __float2half_rn(v);
    l = __float2half_rn(v - __half2float(h));
}

// ================= mma.sync fp16 2-term GEMM (128x64 tile, Ksteps-masked) =================
// C = A (Bh + Bl), A single fp16, B split. OUTH selects fp16/fp32 output.
#define GPITCH 72
#define ATILEB 18432
#define BTILEB 9216
#define STG2   (ATILEB + 2*BTILEB)   // 36864

__device__ __forceinline__ void ld_tileA(uint32_t sdst, const __half* G,
                                         int row0, int k0, int KP, int rlim, int tid){
    #pragma unroll
    for (int i = 0; i < 4; i++){
        int v = tid + i*256;
        int r = v >> 3, cq = v & 7;
        int row = row0 + r;
        int sz = (row < rlim) ? 16 : 0;
        cpa16(sdst + r*144 + cq*16, G + (size_t)(sz ? row : row0)*KP + k0 + cq*8, sz);
    }
}
__device__ __forceinline__ void ld_tileB(uint32_t sdst, const __half* G,
                                         int row0, int k0, int KP, int rlim, int tid){
    #pragma unroll
    for (int i = 0; i < 2; i++){
        int v = tid + i*256;
        int r = v >> 3, cq = v & 7;
        int row = row0 + r;
        int sz = (row < rlim) ? 16 : 0;
        cpa16(sdst + r*144 + cq*16, G + (size_t)(sz ? row : row0)*KP + k0 + cq*8, sz);
    }
}

template<int OUTH>
__global__ void __launch_bounds__(256, 2) gemm_mma_t(
    const __half* __restrict__ A,
    const __half* __restrict__ Bh, const __half* __restrict__ Bl,
    void* __restrict__ Cv, int M, int Nout, int KP, int ldc,
    const float* __restrict__ bias, int act, int Brows, int Ksteps)
{
    extern __shared__ char sm[];
    uint32_t sb = smem_u32(sm);
    int tid = threadIdx.x;
    int m0 = blockIdx.y*128, n0 = blockIdx.x*64;
    int w = tid >> 5, lane = tid & 31;
    int wm = (w >> 1) * 32;
    int wn = (w & 1) * 32;
    int NC = KP / 64;

    float acc[2][4][4];
    #pragma unroll
    for (int i=0;i<2;i++)
        #pragma unroll
        for (int j=0;j<4;j++)
            #pragma unroll
            for (int q=0;q<4;q++) acc[i][j][q] = 0.f;

    int a_row = (lane & 15);
    int a_kc  = (lane >> 4) * 8;
    int b_row = ((lane >> 4) * 8) + (lane & 7);
    int b_kc  = ((lane >> 3) & 1) * 8;

    ld_tileA(sb + 0,               A,  m0, 0, KP, M, tid);
    ld_tileB(sb + ATILEB,          Bh, n0, 0, KP, Brows, tid);
    ld_tileB(sb + ATILEB + BTILEB, Bl, n0, 0, KP, Brows, tid);
    CPA_COMMIT();

    for (int ci = 0; ci < NC; ci++){
        int b = ci & 1;
        uint32_t st = sb + b*STG2;
        CPA_WAIT0();
        __syncthreads();
        if (ci + 1 < NC){
            uint32_t s2 = sb + (1-b)*STG2;
            int k0n = (ci+1)*64;
            ld_tileA(s2 + 0,               A,  m0, k0n, KP, M, tid);
            ld_tileB(s2 + ATILEB,          Bh, n0, k0n, KP, Brows, tid);
            ld_tileB(s2 + ATILEB + BTILEB, Bl, n0, k0n, KP, Brows, tid);
            CPA_COMMIT();
        }
        uint32_t bA = st, bBh = st + ATILEB, bBl = st + ATILEB + BTILEB;
        #pragma unroll
        for (int kk = 0; kk < 64; kk += 16){
            if (ci*4 + (kk >> 4) >= Ksteps) break;
            uint32_t ah[2][4];
            #pragma unroll
            for (int mt = 0; mt < 2; mt++){
                uint32_t off = (uint32_t)((wm + mt*16 + a_row)*GPITCH + kk + a_kc) * 2;
                LDMX4(ah[mt], bA + off);
            }
            #pragma unroll
            for (int nt2 = 0; nt2 < 2; nt2++){
                uint32_t offb = (uint32_t)((wn + nt2*16 + b_row)*GPITCH + kk + b_kc) * 2;
                uint32_t bhf[4], blf[4];
                LDMX4(bhf, bBh + offb);
                LDMX4(blf, bBl + offb);
                #pragma unroll
                for (int mt = 0; mt < 2; mt++){
                    MMA16816(acc[mt][nt2*2],   ah[mt], bhf[0], bhf[1]);
                    MMA16816(acc[mt][nt2*2+1], ah[mt], bhf[2], bhf[3]);
                }
                #pragma unroll
                for (int mt = 0; mt < 2; mt++){
                    MMA16816(acc[mt][nt2*2],   ah[mt], blf[0], blf[1]);
                    MMA16816(acc[mt][nt2*2+1], ah[mt], blf[2], blf[3]);
                }
            }
        }
    }
    #pragma unroll
    for (int mt = 0; mt < 2; mt++){
        int r0 = m0 + wm + mt*16 + (lane >> 2);
        #pragma unroll
        for (int nt = 0; nt < 4; nt++){
            int c = n0 + wn + nt*8 + (lane & 3)*2;
            #pragma unroll
            for (int half2q = 0; half2q < 2; half2q++){
                int rr = r0 + half2q*8;
                if (rr >= M) continue;
                #pragma unroll
                for (int q = 0; q < 2; q++){
                    int cc = c + q;
                    if (cc >= Nout) continue;
                    float v = acc[mt][nt][half2q*2 + q];
                    if (bias) v += bias[cc];
                    if (act)  v = fmaxf(v, 0.f);
                    if (OUTH) ((__half*)Cv)[(size_t)rr*ldc + cc] = __float2half_rn(v);
                    else      ((float*)Cv)[(size_t)rr*ldc + cc] = v;
                }
            }
        }
    }
}

// ================= split-prep =================
__global__ void k_split_x(const float* __restrict__ x){
    int i = blockIdx.x*blockDim.x + threadIdx.x;
    if (i >= NN*KP_GAT) return;
    int r = i >> 7, k = i & (KP_GAT-1);
    float v = (k < NF) ? x[r*NF + k] : 0.f;
    d_xA[i] = __float2half_rn(v);
}
__global__ void k_splitB(const float* __restrict__ W, __half* __restrict__ bh,
                         __half* __restrict__ bl, int K, int N, int KP, int NR){
    int i = blockIdx.x*blockDim.x + threadIdx.x;
    if (i >= NR*KP) return;
    int n = i / KP, k = i - n*KP;
    float v = (k < K && n < N) ? W[(size_t)k*N + n] : 0.f;
    __half h, l; split_fp16(v, h, l);
    bh[i] = h; bl[i] = l;
}

// ================= CSR build =================
__global__ void k_deg_init(){
    int n = blockIdx.x*blockDim.x + threadIdx.x;
    if (n < NN) d_deg[n] = 1;
}
__global__ void k_count(const int* __restrict__ ei){
    int e = blockIdx.x*blockDim.x + threadIdx.x;
    if (e < NE) atomicAdd(&d_deg[ei[NE+e]], 1);
}
__global__ void k_scan(){
    __shared__ int part[1024];
    int t = threadIdx.x;
    const int PER = 25;
    int base = t*PER, sum = 0;
    for (int i = 0; i < PER; i++){ int idx = base+i; if (idx < NN) sum += d_deg[idx]; }
    part[t] = sum; __syncthreads();
    for (int off = 1; off < 1024; off <<= 1){
        int v = (t >= off) ? part[t-off] : 0; __syncthreads();
        part[t] += v; __syncthreads();
    }
    int run = part[t] - sum;
    for (int i = 0; i < PER; i++){
        int idx = base+i;
        if (idx < NN){ d_roff[idx] = run; d_rpos[idx] = run; run += d_deg[idx]; }
    }
    if (t == 1023) d_roff[NN] = NEP;
}
__global__ void k_fill(const int* __restrict__ ei){
    int e = blockIdx.x*blockDim.x + threadIdx.x;
    if (e >= NEP) return;
    int s, d;
    if (e < NE){ s = ei[e]; d = ei[NE+e]; } else { s = d = e - NE; }
    int pos = atomicAdd(&d_rpos[d], 1);
    d_csrc[pos] = s;
}
__global__ void k_dinv(){
    int n = blockIdx.x*blockDim.x + threadIdx.x;
    if (n < NN) d_dinv[n] = rsqrtf((float)d_deg[n]);
}

// ================= GAT attention (folded) =================
__global__ void k_attw(const float* __restrict__ gat_W,
                       const float* __restrict__ att_src,
                       const float* __restrict__ att_dst){
    int wid  = (blockIdx.x*blockDim.x + threadIdx.x) >> 5;
    int lane = threadIdx.x & 31;
    if (wid >= 2*NF*NH) return;
    int which = (wid >= NF*NH);
    int r = wid - which*NF*NH;
    int f_in = r / NH, hh = r - f_in*NH;
    const float* att = which ? att_dst : att_src;
    float s = 0.f;
    for (int f = lane; f < NF; f += 32)
        s += gat_W[(size_t)f_in*HF + hh*NF + f] * att[hh*NF + f];
    #pragma unroll
    for (int o = 16; o > 0; o >>= 1) s += __shfl_down_sync(~0u, s, o);
    if (!lane){
        if (which) d_wdst[f_in*NH + hh] = s;
        else       d_wsrc[f_in*NH + hh] = s;
    }
}
__global__ void k_asrcdst(const float* __restrict__ x){
    __shared__ float ws[NF*NH], wd[NF*NH];
    int tid = threadIdx.x;
    for (int i = tid; i < NF*NH; i += 256){ ws[i] = d_wsrc[i]; wd[i] = d_wdst[i]; }
    __syncthreads();
    int n = blockIdx.x*256 + tid;
    if (n >= NN) return;
    float as[NH], ad[NH];
    #pragma unroll
    for (int hh = 0; hh < NH; hh++){ as[hh] = 0.f; ad[hh] = 0.f; }
    const float* xr = x + (size_t)n*NF;
    for (int f = 0; f < NF; f++){
        float xv = xr[f];
        #pragma unroll
        for (int hh = 0; hh < NH; hh++){
            as[hh] += xv * ws[f*NH + hh];
            ad[hh] += xv * wd[f*NH + hh];
        }
    }
    #pragma unroll
    for (int hh = 0; hh < NH; hh++){
        d_asrc[n*NH + hh] = as[hh];
        d_adst[n*NH + hh] = ad[hh];
    }
}

__global__ void k_gat_soft(){
    int w    = (blockIdx.x*blockDim.x + threadIdx.x) >> 5;
    int lane = threadIdx.x & 31;
    if (w >= NN || lane >= NH) return;
    int s0 = d_roff[w], s1 = d_roff[w+1];
    float ad = d_adst[w*NH + lane];
    float mx = -1e30f;
    for (int p = s0; p < s1; p++){
        float a = d_asrc[d_csrc[p]*NH + lane] + ad;
        a = a > 0.f ? a : 0.2f*a;
        mx = fmaxf(mx, a);
    }
    float sum = 0.f;
    for (int p = s0; p < s1; p++){
        float a = d_asrc[d_csrc[p]*NH + lane] + ad;
        a = a > 0.f ? a : 0.2f*a;
        float e = expf(a - mx);
        d_alpha[(size_t)p*NH + lane] = e;
        sum += e;
    }
    d_invden[w*NH + lane] = 1.f / (sum + 1e-16f);
}
__global__ void k_gat_agg(const float* __restrict__ gat_b){
    int n = blockIdx.x;
    int tid = threadIdx.x;
    __shared__ float invd[NH];
    __shared__ int   csrc_c[25];
    __shared__ float coef_c[25][NH];
    if (tid < NH) invd[tid] = d_invden[n*NH + tid];
    __syncthreads();
    int s0 = d_roff[n], s1 = d_roff[n+1];
    float4 acc = make_float4(0.f,0.f,0.f,0.f);
    int c0 = tid*4;
    int h0 = c0/NF, h1 = (c0+1)/NF, h2 = (c0+2)/NF, h3 = (c0+3)/NF;
    for (int base = s0; base < s1; base += 25){
        int cnt = s1 - base; if (cnt > 25) cnt = 25;
        if (tid < cnt) csrc_c[tid] = d_csrc[base + tid];
        if (tid < cnt*NH){
            int p = tid / NH, hh = tid - p*NH;
            coef_c[p][hh] = d_alpha[(size_t)(base+p)*NH + hh] * invd[hh];
        }
        __syncthreads();
        if (tid < 195){
            #pragma unroll 2
            for (int j = 0; j < cnt; j++){
                uint2 raw = *(const uint2*)(d_hh + (size_t)csrc_c[j]*HF + c0);
                float2 v01 = __half22float2(*(const __half2*)&raw.x);
                float2 v23 = __half22float2(*(const __half2*)&raw.y);
                acc.x += coef_c[j][h0]*v01.x;
                acc.y += coef_c[j][h1]*v01.y;
                acc.z += coef_c[j][h2]*v23.x;
                acc.w += coef_c[j][h3]*v23.y;
            }
        }
        __syncthreads();
    }
    if (tid < 195){
        float4 bb = *(const float4*)(gat_b + c0);
        #pragma unroll
        for (int q = 0; q < 4; q++){
            float r = fmaxf(((float*)&acc)[q] + ((float*)&bb)[q], 0.f);
            d_x1A[(size_t)n*KP_GCN + c0 + q] = __float2half_rn(r);
        }
    } else if (tid < 208){
        #pragma unroll
        for (int q = 0; q < 4; q++)
            d_x1A[(size_t)n*KP_GCN + c0 + q] = __float2half_rn(0.f);
    }
}

// ================= GCN aggregate =================
__global__ void k_gcn_agg(const float* __restrict__ gcn_b){
    int n = blockIdx.x;
    int tid = threadIdx.x;
    __shared__ int   csrc_c[64];
    __shared__ float coef_c[64];
    int s0 = d_roff[n], s1 = d_roff[n+1];
    float dn = d_dinv[n];
    float4 acc = make_float4(0.f,0.f,0.f,0.f);
    int c0 = tid*4;
    for (int base = s0; base < s1; base += 64){
        int cnt = s1 - base; if (cnt > 64) cnt = 64;
        if (tid < cnt){
            int s = d_csrc[base + tid];
            csrc_c[tid] = s;
            coef_c[tid] = dn * d_dinv[s];
        }
        __syncthreads();
        if (tid < 195){
            #pragma unroll 2
            for (int j = 0; j < cnt; j++){
                uint2 raw = *(const uint2*)(d_h2h + (size_t)csrc_c[j]*HF + c0);
                float2 v01 = __half22float2(*(const __half2*)&raw.x);
                float2 v23 = __half22float2(*(const __half2*)&raw.y);
                float cf = coef_c[j];
                acc.x += cf*v01.x; acc.y += cf*v01.y;
                acc.z += cf*v23.x; acc.w += cf*v23.y;
            }
        }
        __syncthreads();
    }
    if (tid < 195){
        float4 bb = *(const float4*)(gcn_b + c0);
        float4 r = make_float4(fmaxf(acc.x + bb.x, 0.f), fmaxf(acc.y + bb.y, 0.f),
                               fmaxf(acc.z + bb.z, 0.f), fmaxf(acc.w + bb.w, 0.f));
        *(float4*)(d_x2 + (size_t)n*HF + c0) = r;
    }
}

// ================= pooling =================
__global__ void k_start(const int* __restrict__ batch){
    int g = blockIdx.x*blockDim.x + threadIdx.x;
    if (g > NG) return;
    if (g == NG){ d_start[NG] = NN; return; }
    int lo = 0, hi = NN;
    while (lo < hi){ int mid = (lo+hi) >> 1; if (batch[mid] < g) lo = mid+1; else hi = mid; }
    d_start[g] = lo;
}
__global__ void k_pool(){
    int g = blockIdx.x;
    int s = d_start[g], e = d_start[g+1];
    int cnt = e - s;
    size_t rb = (size_t)g*KP_POOL;
    for (int c = threadIdx.x; c < HF; c += blockDim.x){
        float mx = -1e30f, sm = 0.f;
        #pragma unroll 4
        for (int n = s; n < e; n++){
            float v = d_x2[(size_t)n*HF + c];
            mx = fmaxf(mx, v); sm += v;
        }
        float vmax = (cnt > 0) ? mx : 0.f;
        float vmean = sm / fmaxf((float)cnt, 1.f);
        d_poolA[rb + c]      = __float2half_rn(vmax);
        d_poolA[rb + HF + c] = __float2half_rn(vmean);
    }
    if (threadIdx.x < KP_POOL - 2*HF)
        d_poolA[rb + 2*HF + threadIdx.x] = __float2half_rn(0.f);
}

// ================= small GEMM (f32x2, split-K) =================
__global__ void gemm2_kernel(const float* __restrict__ A, const float* __restrict__ B,
                             const float* __restrict__ bias, float* __restrict__ C,
                             int M, int N, int K, int ldc, int act)
{
    __shared__ float As[16*64];
    __shared__ float Bs[16*64];
    int tid = threadIdx.x;
    int row0 = blockIdx.y*64, col0 = blockIdx.x*64;
    int tx = tid & 15, ty = tid >> 4;
    int Z = gridDim.z, z = blockIdx.z;
    int T = (K + 15) / 16;
    int kc0 = (int)((long long)T * z / Z), kc1 = (int)((long long)T * (z+1) / Z);
    unsigned long long acc2[4][2];
    #pragma unroll
    for (int i=0;i<4;i++){ acc2[i][0] = 0ull; acc2[i][1] = 0ull; }
    for (int kc = kc0; kc < kc1; kc++){
        int k0 = kc*16;
        #pragma unroll
        for (int i=0;i<4;i++){
            int l = tid + i*256;
            int m = l >> 4, kk = l & 15;
            int r = row0 + m, kg = k0 + kk;
            As[kk*64+m] = (r < M && kg < K) ? A[(size_t)r*K + kg] : 0.f;
        }
        #pragma unroll
        for (int i=0;i<4;i++){
            int l = tid + i*256;
            int kk = l >> 6, n = l & 63;
            int kg = k0 + kk, c = col0 + n;
            Bs[kk*64+n] = (kg < K && c < N) ? B[(size_t)kg*N + c] : 0.f;
        }
        __syncthreads();
        #pragma unroll
        for (int kk=0; kk<16; kk++){
            float ra[4];
            #pragma unroll
            for (int i=0;i<4;i++) ra[i] = As[kk*64 + ty*4 + i];
            unsigned long long rb0 = *(const unsigned long long*)&Bs[kk*64 + tx*4];
            unsigned long long rb1 = *(const unsigned long long*)&Bs[kk*64 + tx*4 + 2];
            #pragma unroll
            for (int i=0;i<4;i++){
                unsigned long long ad;
                asm("mov.b64 %0, {%1, %1};" : "=l"(ad) : "r"(__float_as_uint(ra[i])));
                asm("fma.rn.f32x2 %0, %1, %2, %0;" : "+l"(acc2[i][0]) : "l"(ad), "l"(rb0));
                asm("fma.rn.f32x2 %0, %1, %2, %0;" : "+l"(acc2[i][1]) : "l"(ad), "l"(rb1));
            }
        }
        __syncthreads();
    }
    #pragma unroll
    for (int i=0;i<4;i++){
        int r = row0 + ty*4 + i;
        if (r >= M) continue;
        #pragma unroll
        for (int jp=0;jp<2;jp++){
            unsigned int lo, hi;
            asm("mov.b64 {%0, %1}, %2;" : "=r"(lo), "=r"(hi) : "l"(acc2[i][jp]));
            float vv[2] = { __uint_as_float(lo), __uint_as_float(hi) };
            int c = col0 + tx*4 + jp*2;
            #pragma unroll
            for (int q=0;q<2;q++){
                int cc = c + q;
                if (cc >= N) continue;
                if (Z == 1){
                    float v = vv[q];
                    if (bias) v += bias[cc];
                    if (act)  v = fmaxf(v, 0.f);
                    C[(size_t)r*ldc + cc] = v;
                } else {
                    atomicAdd(&C[(size_t)r*ldc + cc], vv[q]);
                }
            }
        }
    }
}

__global__ void k_binit(float* __restrict__ C, const float* __restrict__ bias,
                        int M, int N, int ldc){
    int i = blockIdx.x*blockDim.x + threadIdx.x;
    if (i >= M*N) return;
    int r = i / N, c = i - r*N;
    C[(size_t)r*ldc + c] = bias[c];
}
__global__ void k_relu(float* __restrict__ C, int total){
    int i = blockIdx.x*blockDim.x + threadIdx.x;
    if (i < total) C[i] = fmaxf(C[i], 0.f);
}

// ================= target branch =================
__global__ void k_buildM(const float* __restrict__ emb){
    int i = blockIdx.x*blockDim.x + threadIdx.x;
    if (i >= 128*KP_U) return;
    int p = i / KP_U, kidx = i - p*KP_U;
    float val = 0.f;
    if (p < CONVOUT && kidx < UCOLS){
        int v = kidx >> 3, kk = kidx & 7;
        val = emb[v*EMB + p + kk];
    }
    __half h, l; split_fp16(val, h, l);
    d_Mmh[i] = h; d_Mml[i] = l;
}
__global__ void k_transW(const float* __restrict__ W){
    int i = blockIdx.x*blockDim.x + threadIdx.x;
    if (i >= NFILT*SEQL*8) return;
    int o = i / (SEQL*8), c = (i >> 3) % SEQL, k = i & 7;
    d_Wt[c*(NFILT*8) + o*8 + k] = W[i];
}
__global__ void k_buildU(const int* __restrict__ target){
    __shared__ float sU[USZ];
    __shared__ int   st[SEQL];
    int g = blockIdx.x;
    for (int i = threadIdx.x; i < USZ;  i += blockDim.x) sU[i] = 0.f;
    for (int i = threadIdx.x; i < SEQL; i += blockDim.x) st[i] = target[g*SEQL + i];
    __syncthreads();
    int o = threadIdx.x >> 3, k = threadIdx.x & 7;
    for (int c = 0; c < SEQL; c++){
        int v = st[c];
        sU[o*UCOLS + v*8 + k] += d_Wt[c*(NFILT*8) + threadIdx.x];
    }
    __syncthreads();
    for (int i = threadIdx.x; i < NFILT*KP_U; i += blockDim.x){
        int oo = i / KP_U, col = i - oo*KP_U;
        float v = (col < UCOLS) ? sU[oo*UCOLS + col] : 0.f;
        d_UA[((size_t)g*NFILT + oo)*KP_U + col] = __float2half_rn(v);
    }
}
__global__ void k_fcxtb2(const float* __restrict__ fcxt_W,
                         const float* __restrict__ fcxt_b,
                         const float* __restrict__ conv_b){
    int j = blockIdx.x;
    __shared__ float red[128];
    float s = 0.f;
    for (int r = threadIdx.x; r < NFILT*CONVOUT; r += blockDim.x)
        s += conv_b[r / CONVOUT] * fcxt_W[(size_t)r*128 + j];
    red[threadIdx.x] = s; __syncthreads();
    for (int o = 64; o > 0; o >>= 1){
        if (threadIdx.x < o) red[threadIdx.x] += red[threadIdx.x + o];
        __syncthreads();
    }
    if (!threadIdx.x) d_fcxtb2[j] = fcxt_b[j] + red[0];
}

// ================= final projection =================
__global__ void k_out(const float* __restrict__ oW, const float* __restrict__ ob,
                      float* __restrict__ out){
    int g    = (blockIdx.x*blockDim.x + threadIdx.x) >> 5;
    int lane = threadIdx.x & 31;
    if (g >= NG) return;
    float s = 0.f;
    for (int k = lane; k < 512; k += 32) s += d_f2[g*512 + k] * oW[k];
    #pragma unroll
    for (int o = 16; o > 0; o >>= 1) s += __shfl_down_sync(~0u, s, o);
    if (!lane) out[g] = s + ob[0];
}

extern "C" void kernel_launch(void* const* d_in, const int* in_sizes, int n_in,
                              void* d_out, int out_size){
    const float* x        = (const float*)d_in[0];
    const int*   ei       = (const int*)  d_in[1];
    const int*   batch    = (const int*)  d_in[2];
    const int*   target   = (const int*)  d_in[3];
    const float* gat_W    = (const float*)d_in[4];
    const float* gat_asrc = (const float*)d_in[5];
    const float* gat_adst = (const float*)d_in[6];
    const float* gat_b    = (const float*)d_in[7];
    const float* gcn_W    = (const float*)d_in[8];
    const float* gcn_b    = (const float*)d_in[9];
    const float* fcg1_W   = (const float*)d_in[10];
    const float* fcg1_b   = (const float*)d_in[11];
    const float* fcg2_W   = (const float*)d_in[12];
    const float* fcg2_b   = (const float*)d_in[13];
    const float* emb      = (const float*)d_in[14];
    const float* conv_W   = (const float*)d_in[15];
    const float* conv_b   = (const float*)d_in[16];
    const float* fcxt_W   = (const float*)d_in[17];
    const float* fcxt_b   = (const float*)d_in[18];
    const float* fc1_W    = (const float*)d_in[19];
    const float* fc1_b    = (const float*)d_in[20];
    const float* fc2_W    = (const float*)d_in[21];
    const float* fc2_b    = (const float*)d_in[22];
    const float* out_W    = (const float*)d_in[23];
    const float* out_b    = (const float*)d_in[24];

    float *p_xg1, *p_xc, *p_conv, *p_f1, *p_f2, *p_fcxtb2;
    __half *p_hh, *p_h2h, *p_xA, *p_x1A, *p_gWh, *p_gWl, *p_cWh, *p_cWl;
    __half *p_poolA, *p_fWh, *p_fWl, *p_UA, *p_Mmh, *p_Mml;
    cudaGetSymbolAddress((void**)&p_hh,   d_hh);
    cudaGetSymbolAddress((void**)&p_h2h,  d_h2h);
    cudaGetSymbolAddress((void**)&p_xg1,  d_xg1);
    cudaGetSymbolAddress((void**)&p_xc,   d_xc);
    cudaGetSymbolAddress((void**)&p_conv, d_conv);
    cudaGetSymbolAddress((void**)&p_f1,   d_f1);
    cudaGetSymbolAddress((void**)&p_f2,   d_f2);
    cudaGetSymbolAddress((void**)&p_fcxtb2, d_fcxtb2);
    cudaGetSymbolAddress((void**)&p_xA,  d_xA);
    cudaGetSymbolAddress((void**)&p_x1A, d_x1A);
    cudaGetSymbolAddress((void**)&p_gWh, d_gWh);
    cudaGetSymbolAddress((void**)&p_gWl, d_gWl);
    cudaGetSymbolAddress((void**)&p_cWh, d_cWh);
    cudaGetSymbolAddress((void**)&p_cWl, d_cWl);
    cudaGetSymbolAddress((void**)&p_poolA, d_poolA);
    cudaGetSymbolAddress((void**)&p_fWh, d_fWh);
    cudaGetSymbolAddress((void**)&p_fWl, d_fWl);
    cudaGetSymbolAddress((void**)&p_UA, d_UA);
    cudaGetSymbolAddress((void**)&p_Mmh, d_Mmh);
    cudaGetSymbolAddress((void**)&p_Mml, d_Mml);

    cudaFuncSetAttribute(gemm_mma_t<0>, cudaFuncAttributeMaxDynamicSharedMemorySize, 2*STG2);
    cudaFuncSetAttribute(gemm_mma_t<1>, cudaFuncAttributeMaxDynamicSharedMemorySize, 2*STG2);

    // launches 0..2: splits (launch 3 = gemm GAT lands under ncu -s 5)
    k_split_x<<<(NN*KP_GAT + 255)/256, 256>>>(x);
    k_splitB<<<(NPADG*KP_GAT + 255)/256, 256>>>(gat_W, p_gWh, p_gWl, NF, HF, KP_GAT, NPADG);
    k_splitB<<<(NPADG*KP_GCN + 255)/256, 256>>>(gcn_W, p_cWh, p_cWl, HF, HF, KP_GCN, NPADG);

    // launch 3: GAT transform (2-term, fp16 out), Ksteps=5
    {
        dim3 grid(NPADG/64, (NN + 127)/128);
        gemm_mma_t<1><<<grid, 256, 2*STG2>>>(p_xA, p_gWh, p_gWl, p_hh, NN, HF, KP_GAT, HF, nullptr, 0, NPADG, 5);
    }

    // CSR build
    k_deg_init<<<(NN + 255)/256, 256>>>();
    k_count<<<(NE + 255)/256, 256>>>(ei);
    k_scan<<<1, 1024>>>();
    k_fill<<<(NEP + 255)/256, 256>>>(ei);
    k_dinv<<<(NN + 255)/256, 256>>>();

    // remaining prep
    k_splitB<<<(NP_FCG1*KP_POOL + 255)/256, 256>>>(fcg1_W, p_fWh, p_fWl, 2*HF, 1024, KP_POOL, NP_FCG1);
    k_buildM<<<(128*KP_U + 255)/256, 256>>>(emb);
    k_transW<<<(NFILT*SEQL*8 + 255)/256, 256>>>(conv_W);

    // GAT attention (folded) + aggregation
    k_attw<<<(2*NF*NH*32 + 255)/256, 256>>>(gat_W, gat_asrc, gat_adst);
    k_asrcdst<<<(NN + 255)/256, 256>>>(x);
    k_gat_soft<<<(NN*32 + 255)/256, 256>>>();
    k_gat_agg<<<NN, 256>>>(gat_b);

    // GCN (2-term, fp16 out), Ksteps=49
    {
        dim3 grid(NPADG/64, (NN + 127)/128);
        gemm_mma_t<1><<<grid, 256, 2*STG2>>>(p_x1A, p_cWh, p_cWl, p_h2h, NN, HF, KP_GCN, HF, nullptr, 0, NPADG, 49);
    }
    k_gcn_agg<<<NN, 256>>>(gcn_b);

    // pooling + graph head
    k_start<<<3, 256>>>(batch);
    k_pool<<<NG, 256>>>();
    {   // fcg1 (2-term, f32 out + bias/relu), Ksteps=98
        dim3 grid(1024/64, NG/128);
        gemm_mma_t<0><<<grid, 256, 2*STG2>>>(p_poolA, p_fWh, p_fWl, p_xg1, NG, 1024, KP_POOL, 1024, fcg1_b, 1, NP_FCG1, 98);
    }
    {
        k_binit<<<(NG*128 + 255)/256, 256>>>(p_xc, fcg2_b, NG, 128, 256);
        dim3 grid(2, 8, 4);
        gemm2_kernel<<<grid, 256>>>(p_xg1, fcg2_W, nullptr, p_xc, NG, 128, 1024, 256, 0);
    }

    // target branch
    k_buildU<<<NG, 256>>>(target);
    {   // conv GEMM (2-term, f32 out), Ksteps=13
        dim3 grid(2, (NG*NFILT)/128);
        gemm_mma_t<0><<<grid, 256, 2*STG2>>>(p_UA, p_Mmh, p_Mml, p_conv, NG*NFILT, CONVOUT, KP_U, CONVOUT, nullptr, 0, 128, 13);
    }
    k_fcxtb2<<<128, 128>>>(fcxt_W, fcxt_b, conv_b);
    {
        k_binit<<<(NG*128 + 255)/256, 256>>>(p_xc + 128, p_fcxtb2, NG, 128, 256);
        dim3 grid(2, 8, 4);
        gemm2_kernel<<<grid, 256>>>(p_conv, fcxt_W, nullptr, p_xc + 128, NG, 128, NFILT*CONVOUT, 256, 0);
    }

    // fusion head
    {
        dim3 grid(16, 8, 1);
        gemm2_kernel<<<grid, 256>>>(p_xc, fc1_W, fc1_b, p_f1, NG, 1024, 256, 1024, 1);
    }
    {
        k_binit<<<(NG*512 + 255)/256, 256>>>(p_f2, fc2_b, NG, 512, 512);
        dim3 grid(8, 8, 2);
        gemm2_kernel<<<grid, 256>>>(p_f1, fc2_W, nullptr, p_f2, NG, 512, 1024, 512, 0);
        k_relu<<<(NG*512 + 255)/256, 256>>>(p_f2, NG*512);
    }
    k_out<<<(NG*32 + 255)/256, 256>>>(out_W, out_b, (float*)d_out);
}

// round 16
// speedup vs baseline: 1.2620x; 1.0344x over previous
#include <cuda_runtime.h>
#include <cuda_fp16.h>
#include <math.h>
#include <stdint.h>

#define NN      25000
#define NE      100000
#define NEP     125000
#define NG      512
#define NH      10
#define NF      78
#define HF      780
#define SEQL    1000
#define EMB     128
#define NFILT   32
#define CONVOUT 121
#define VOCAB   26
#define UCOLS   (VOCAB*8)        // 208
#define USZ     (NFILT*UCOLS)

#define KP_GAT  128
#define KP_GCN  832
#define NPADG   832
#define KP_POOL 1600
#define NP_FCG1 1024
#define KP_U    256

// ---------------- device scratch ----------------
__device__ __half d_hh[(size_t)NN*HF];
__device__ __half d_h2h[(size_t)NN*HF];
__device__ float d_asrc[NN*NH];
__device__ float d_adst[NN*NH];
__device__ float d_wsrc[NF*NH];
__device__ float d_wdst[NF*NH];
__device__ float d_x2[NN*HF];
__device__ float d_dinv[NN];
__device__ int   d_deg[NN];
__device__ int   d_roff[NN+1];
__device__ int   d_rpos[NN];
__device__ int   d_csrc[NEP];
__device__ int   d_start[NG+1];
__device__ float d_xg1[NG*1024];
__device__ float d_Wt[SEQL*NFILT*8];
__device__ float d_conv[(size_t)NG*NFILT*CONVOUT];
__device__ float d_fcxtb2[128];
__device__ float d_xc[NG*256];
__device__ float d_f1[NG*1024];
__device__ float d_f2[NG*512];
__device__ __half d_xA[(size_t)NN*KP_GAT];
__device__ __half d_x1A[(size_t)NN*KP_GCN];
__device__ __half d_gWh[(size_t)NPADG*KP_GAT];
__device__ __half d_gWl[(size_t)NPADG*KP_GAT];
__device__ __half d_cWh[(size_t)NPADG*KP_GCN];
__device__ __half d_cWl[(size_t)NPADG*KP_GCN];
__device__ __half d_poolA[(size_t)NG*KP_POOL];
__device__ __half d_fWh[(size_t)NP_FCG1*KP_POOL];
__device__ __half d_fWl[(size_t)NP_FCG1*KP_POOL];
__device__ __half d_UA[(size_t)NG*NFILT*KP_U];
__device__ __half d_Mmh[128*KP_U];
__device__ __half d_Mml[128*KP_U];

// ================= helpers =================
__device__ __forceinline__ uint32_t smem_u32(const void* p){
    uint32_t a;
    asm("{ .reg .u64 t; cvta.to.shared.u64 t, %1; cvt.u32.u64 %0, t; }" : "=r"(a) : "l"(p));
    return a;
}
#define LDMX4(r, a) \
    asm volatile("ldmatrix.sync.aligned.m8n8.x4.shared.b16 {%0,%1,%2,%3}, [%4];" \
        : "=r"((r)[0]), "=r"((r)[1]), "=r"((r)[2]), "=r"((r)[3]) : "r"(a))
#define MMA16816(d, a, b0, b1) \
    asm volatile("mma.sync.aligned.m16n8k16.row.col.f32.f16.f16.f32 " \
        "{%0,%1,%2,%3}, {%4,%5,%6,%7}, {%8,%9}, {%0,%1,%2,%3};" \
        : "+f"((d)[0]), "+f"((d)[1]), "+f"((d)[2]), "+f"((d)[3]) \
        : "r"((a)[0]), "r"((a)[1]), "r"((a)[2]), "r"((a)[3]), "r"(b0), "r"(b1))
#define CPA_COMMIT() asm volatile("cp.async.commit_group;" ::: "memory")
#define CPA_WAIT0()  asm volatile("cp.async.wait_group 0;" ::: "memory")

__device__ __forceinline__ void cpa16(uint32_t dst, const void* src, int sz){
    size_t g;
    asm("cvta.to.global.u64 %0, %1;" : "=l"(g) : "l"(src));
    asm volatile("cp.async.cg.shared.global [%0], [%1], 16, %2;" :: "r"(dst), "l"(g), "r"(sz) : "memory");
}
__device__ __forceinline__ void split_fp16(float v, __half& h, __half& l){
    h = __float2half_rn(v);
    l = __float2half_rn(v - __half2float(h));
}

// ================= mma.sync fp16 2-term GEMM (128x64 tile, Ksteps-masked) =================
#define GPITCH 72
#define ATILEB 18432
#define BTILEB 9216
#define STG2   (ATILEB + 2*BTILEB)   // 36864

__device__ __forceinline__ void ld_tileA(uint32_t sdst, const __half* G,
                                         int row0, int k0, int KP, int rlim, int tid){
    #pragma unroll
    for (int i = 0; i < 4; i++){
        int v = tid + i*256;
        int r = v >> 3, cq = v & 7;
        int row = row0 + r;
        int sz = (row < rlim) ? 16 : 0;
        cpa16(sdst + r*144 + cq*16, G + (size_t)(sz ? row : row0)*KP + k0 + cq*8, sz);
    }
}
__device__ __forceinline__ void ld_tileB(uint32_t sdst, const __half* G,
                                         int row0, int k0, int KP, int rlim, int tid){
    #pragma unroll
    for (int i = 0; i < 2; i++){
        int v = tid + i*256;
        int r = v >> 3, cq = v & 7;
        int row = row0 + r;
        int sz = (row < rlim) ? 16 : 0;
        cpa16(sdst + r*144 + cq*16, G + (size_t)(sz ? row : row0)*KP + k0 + cq*8, sz);
    }
}

template<int OUTH>
__global__ void __launch_bounds__(256, 2) gemm_mma_t(
    const __half* __restrict__ A,
    const __half* __restrict__ Bh, const __half* __restrict__ Bl,
    void* __restrict__ Cv, int M, int Nout, int KP, int ldc,
    const float* __restrict__ bias, int act, int Brows, int Ksteps)
{
    extern __shared__ char sm[];
    uint32_t sb = smem_u32(sm);
    int tid = threadIdx.x;
    int m0 = blockIdx.y*128, n0 = blockIdx.x*64;
    int w = tid >> 5, lane = tid & 31;
    int wm = (w >> 1) * 32;
    int wn = (w & 1) * 32;
    int NC = KP / 64;

    float acc[2][4][4];
    #pragma unroll
    for (int i=0;i<2;i++)
        #pragma unroll
        for (int j=0;j<4;j++)
            #pragma unroll
            for (int q=0;q<4;q++) acc[i][j][q] = 0.f;

    int a_row = (lane & 15);
    int a_kc  = (lane >> 4) * 8;
    int b_row = ((lane >> 4) * 8) + (lane & 7);
    int b_kc  = ((lane >> 3) & 1) * 8;

    ld_tileA(sb + 0,               A,  m0, 0, KP, M, tid);
    ld_tileB(sb + ATILEB,          Bh, n0, 0, KP, Brows, tid);
    ld_tileB(sb + ATILEB + BTILEB, Bl, n0, 0, KP, Brows, tid);
    CPA_COMMIT();

    for (int ci = 0; ci < NC; ci++){
        int b = ci & 1;
        uint32_t st = sb + b*STG2;
        CPA_WAIT0();
        __syncthreads();
        if (ci + 1 < NC){
            uint32_t s2 = sb + (1-b)*STG2;
            int k0n = (ci+1)*64;
            ld_tileA(s2 + 0,               A,  m0, k0n, KP, M, tid);
            ld_tileB(s2 + ATILEB,          Bh, n0, k0n, KP, Brows, tid);
            ld_tileB(s2 + ATILEB + BTILEB, Bl, n0, k0n, KP, Brows, tid);
            CPA_COMMIT();
        }
        uint32_t bA = st, bBh = st + ATILEB, bBl = st + ATILEB + BTILEB;
        #pragma unroll
        for (int kk = 0; kk < 64; kk += 16){
            if (ci*4 + (kk >> 4) >= Ksteps) break;
            uint32_t ah[2][4];
            #pragma unroll
            for (int mt = 0; mt < 2; mt++){
                uint32_t off = (uint32_t)((wm + mt*16 + a_row)*GPITCH + kk + a_kc) * 2;
                LDMX4(ah[mt], bA + off);
            }
            #pragma unroll
            for (int nt2 = 0; nt2 < 2; nt2++){
                uint32_t offb = (uint32_t)((wn + nt2*16 + b_row)*GPITCH + kk + b_kc) * 2;
                uint32_t bhf[4], blf[4];
                LDMX4(bhf, bBh + offb);
                LDMX4(blf, bBl + offb);
                #pragma unroll
                for (int mt = 0; mt < 2; mt++){
                    MMA16816(acc[mt][nt2*2],   ah[mt], bhf[0], bhf[1]);
                    MMA16816(acc[mt][nt2*2+1], ah[mt], bhf[2], bhf[3]);
                }
                #pragma unroll
                for (int mt = 0; mt < 2; mt++){
                    MMA16816(acc[mt][nt2*2],   ah[mt], blf[0], blf[1]);
                    MMA16816(acc[mt][nt2*2+1], ah[mt], blf[2], blf[3]);
                }
            }
        }
    }
    #pragma unroll
    for (int mt = 0; mt < 2; mt++){
        int r0 = m0 + wm + mt*16 + (lane >> 2);
        #pragma unroll
        for (int nt = 0; nt < 4; nt++){
            int c = n0 + wn + nt*8 + (lane & 3)*2;
            #pragma unroll
            for (int hq = 0; hq < 2; hq++){
                int rr = r0 + hq*8;
                if (rr >= M) continue;
                float v0 = acc[mt][nt][hq*2 + 0];
                float v1 = acc[mt][nt][hq*2 + 1];
                if (bias){ v0 += bias[c]; if (c+1 < Nout) v1 += bias[c+1]; }
                if (act){ v0 = fmaxf(v0, 0.f); v1 = fmaxf(v1, 0.f); }
                size_t idx = (size_t)rr*ldc + c;
                if (c + 1 < Nout && ((idx & 1) == 0)){
                    if (OUTH){
                        __half2 hv = __floats2half2_rn(v0, v1);
                        *(__half2*)&((__half*)Cv)[idx] = hv;
                    } else {
                        float2 fv = make_float2(v0, v1);
                        *(float2*)&((float*)Cv)[idx] = fv;
                    }
                } else {
                    if (c < Nout){
                        if (OUTH) ((__half*)Cv)[idx] = __float2half_rn(v0);
                        else      ((float*)Cv)[idx] = v0;
                    }
                    if (c + 1 < Nout){
                        if (OUTH) ((__half*)Cv)[idx + 1] = __float2half_rn(v1);
                        else      ((float*)Cv)[idx + 1] = v1;
                    }
                }
            }
        }
    }
}

// ================= split-prep =================
__global__ void k_split_x(const float* __restrict__ x){
    int i = blockIdx.x*blockDim.x + threadIdx.x;
    if (i >= NN*KP_GAT) return;
    int r = i >> 7, k = i & (KP_GAT-1);
    float v = (k < NF) ? x[r*NF + k] : 0.f;
    d_xA[i] = __float2half_rn(v);
}
__global__ void k_splitB(const float* __restrict__ W, __half* __restrict__ bh,
                         __half* __restrict__ bl, int K, int N, int KP, int NR){
    int i = blockIdx.x*blockDim.x + threadIdx.x;
    if (i >= NR*KP) return;
    int n = i / KP, k = i - n*KP;
    float v = (k < K && n < N) ? W[(size_t)k*N + n] : 0.f;
    __half h, l; split_fp16(v, h, l);
    bh[i] = h; bl[i] = l;
}

// ================= CSR build =================
__global__ void k_deg_init(){
    int n = blockIdx.x*blockDim.x + threadIdx.x;
    if (n < NN) d_deg[n] = 1;
}
__global__ void k_count(const int* __restrict__ ei){
    int e = blockIdx.x*blockDim.x + threadIdx.x;
    if (e < NE) atomicAdd(&d_deg[ei[NE+e]], 1);
}
__global__ void k_scan(){
    __shared__ int part[1024];
    int t = threadIdx.x;
    const int PER = 25;
    int base = t*PER, sum = 0;
    for (int i = 0; i < PER; i++){ int idx = base+i; if (idx < NN) sum += d_deg[idx]; }
    part[t] = sum; __syncthreads();
    for (int off = 1; off < 1024; off <<= 1){
        int v = (t >= off) ? part[t-off] : 0; __syncthreads();
        part[t] += v; __syncthreads();
    }
    int run = part[t] - sum;
    for (int i = 0; i < PER; i++){
        int idx = base+i;
        if (idx < NN){ d_roff[idx] = run; d_rpos[idx] = run; run += d_deg[idx]; }
    }
    if (t == 1023) d_roff[NN] = NEP;
}
__global__ void k_fill(const int* __restrict__ ei){
    int e = blockIdx.x*blockDim.x + threadIdx.x;
    if (e >= NEP) return;
    int s, d;
    if (e < NE){ s = ei[e]; d = ei[NE+e]; } else { s = d = e - NE; }
    int pos = atomicAdd(&d_rpos[d], 1);
    d_csrc[pos] = s;
}
__global__ void k_dinv(){
    int n = blockIdx.x*blockDim.x + threadIdx.x;
    if (n < NN) d_dinv[n] = rsqrtf((float)d_deg[n]);
}

// ================= GAT attention (folded) =================
__global__ void k_attw(const float* __restrict__ gat_W,
                       const float* __restrict__ att_src,
                       const float* __restrict__ att_dst){
    int wid  = (blockIdx.x*blockDim.x + threadIdx.x) >> 5;
    int lane = threadIdx.x & 31;
    if (wid >= 2*NF*NH) return;
    int which = (wid >= NF*NH);
    int r = wid - which*NF*NH;
    int f_in = r / NH, hh = r - f_in*NH;
    const float* att = which ? att_dst : att_src;
    float s = 0.f;
    for (int f = lane; f < NF; f += 32)
        s += gat_W[(size_t)f_in*HF + hh*NF + f] * att[hh*NF + f];
    #pragma unroll
    for (int o = 16; o > 0; o >>= 1) s += __shfl_down_sync(~0u, s, o);
    if (!lane){
        if (which) d_wdst[f_in*NH + hh] = s;
        else       d_wsrc[f_in*NH + hh] = s;
    }
}
__global__ void k_asrcdst(const float* __restrict__ x){
    __shared__ float ws[NF*NH], wd[NF*NH];
    int tid = threadIdx.x;
    for (int i = tid; i < NF*NH; i += 256){ ws[i] = d_wsrc[i]; wd[i] = d_wdst[i]; }
    __syncthreads();
    int n = blockIdx.x*256 + tid;
    if (n >= NN) return;
    float as[NH], ad[NH];
    #pragma unroll
    for (int hh = 0; hh < NH; hh++){ as[hh] = 0.f; ad[hh] = 0.f; }
    const float* xr = x + (size_t)n*NF;
    for (int f = 0; f < NF; f++){
        float xv = xr[f];
        #pragma unroll
        for (int hh = 0; hh < NH; hh++){
            as[hh] += xv * ws[f*NH + hh];
            ad[hh] += xv * wd[f*NH + hh];
        }
    }
    #pragma unroll
    for (int hh = 0; hh < NH; hh++){
        d_asrc[n*NH + hh] = as[hh];
        d_adst[n*NH + hh] = ad[hh];
    }
}

// fused softmax + aggregation (one block per node)
__global__ void k_gat_agg(const float* __restrict__ gat_b){
    int n = blockIdx.x;
    int tid = threadIdx.x;
    __shared__ float smx[NH], sinv[NH];
    __shared__ int   csrc_c[25];
    __shared__ float coef_c[25][NH];
    int s0 = d_roff[n], s1 = d_roff[n+1];
    if (tid < NH){
        float ad = d_adst[n*NH + tid];
        float mx = -1e30f;
        for (int p = s0; p < s1; p++){
            float a = d_asrc[d_csrc[p]*NH + tid] + ad;
            a = a > 0.f ? a : 0.2f*a;
            mx = fmaxf(mx, a);
        }
        float sum = 0.f;
        for (int p = s0; p < s1; p++){
            float a = d_asrc[d_csrc[p]*NH + tid] + ad;
            a = a > 0.f ? a : 0.2f*a;
            sum += expf(a - mx);
        }
        smx[tid]  = mx;
        sinv[tid] = 1.f / (sum + 1e-16f);
    }
    __syncthreads();
    float4 acc = make_float4(0.f,0.f,0.f,0.f);
    int c0 = tid*4;
    int h0 = c0/NF, h1 = (c0+1)/NF, h2 = (c0+2)/NF, h3 = (c0+3)/NF;
    for (int base = s0; base < s1; base += 25){
        int cnt = s1 - base; if (cnt > 25) cnt = 25;
        if (tid < cnt) csrc_c[tid] = d_csrc[base + tid];
        __syncthreads();
        if (tid < cnt*NH){
            int p = tid / NH, hh = tid - p*NH;
            float a = d_asrc[csrc_c[p]*NH + hh] + d_adst[n*NH + hh];
            a = a > 0.f ? a : 0.2f*a;
            coef_c[p][hh] = expf(a - smx[hh]) * sinv[hh];
        }
        __syncthreads();
        if (tid < 195){
            #pragma unroll 2
            for (int j = 0; j < cnt; j++){
                uint2 raw = *(const uint2*)(d_hh + (size_t)csrc_c[j]*HF + c0);
                float2 v01 = __half22float2(*(const __half2*)&raw.x);
                float2 v23 = __half22float2(*(const __half2*)&raw.y);
                acc.x += coef_c[j][h0]*v01.x;
                acc.y += coef_c[j][h1]*v01.y;
                acc.z += coef_c[j][h2]*v23.x;
                acc.w += coef_c[j][h3]*v23.y;
            }
        }
        __syncthreads();
    }
    if (tid < 195){
        float4 bb = *(const float4*)(gat_b + c0);
        #pragma unroll
        for (int q = 0; q < 4; q++){
            float r = fmaxf(((float*)&acc)[q] + ((float*)&bb)[q], 0.f);
            d_x1A[(size_t)n*KP_GCN + c0 + q] = __float2half_rn(r);
        }
    } else if (tid < 208){
        #pragma unroll
        for (int q = 0; q < 4; q++)
            d_x1A[(size_t)n*KP_GCN + c0 + q] = __float2half_rn(0.f);
    }
}

// ================= GCN aggregate =================
__global__ void k_gcn_agg(const float* __restrict__ gcn_b){
    int n = blockIdx.x;
    int tid = threadIdx.x;
    __shared__ int   csrc_c[64];
    __shared__ float coef_c[64];
    int s0 = d_roff[n], s1 = d_roff[n+1];
    float dn = d_dinv[n];
    float4 acc = make_float4(0.f,0.f,0.f,0.f);
    int c0 = tid*4;
    for (int base = s0; base < s1; base += 64){
        int cnt = s1 - base; if (cnt > 64) cnt = 64;
        if (tid < cnt){
            int s = d_csrc[base + tid];
            csrc_c[tid] = s;
            coef_c[tid] = dn * d_dinv[s];
        }
        __syncthreads();
        if (tid < 195){
            #pragma unroll 2
            for (int j = 0; j < cnt; j++){
                uint2 raw = *(const uint2*)(d_h2h + (size_t)csrc_c[j]*HF + c0);
                float2 v01 = __half22float2(*(const __half2*)&raw.x);
                float2 v23 = __half22float2(*(const __half2*)&raw.y);
                float cf = coef_c[j];
                acc.x += cf*v01.x; acc.y += cf*v01.y;
                acc.z += cf*v23.x; acc.w += cf*v23.y;
            }
        }
        __syncthreads();
    }
    if (tid < 195){
        float4 bb = *(const float4*)(gcn_b + c0);
        float4 r = make_float4(fmaxf(acc.x + bb.x, 0.f), fmaxf(acc.y + bb.y, 0.f),
                               fmaxf(acc.z + bb.z, 0.f), fmaxf(acc.w + bb.w, 0.f));
        *(float4*)(d_x2 + (size_t)n*HF + c0) = r;
    }
}

// ================= pooling =================
__global__ void k_start(const int* __restrict__ batch){
    int g = blockIdx.x*blockDim.x + threadIdx.x;
    if (g > NG) return;
    if (g == NG){ d_start[NG] = NN; return; }
    int lo = 0, hi = NN;
    while (lo < hi){ int mid = (lo+hi) >> 1; if (batch[mid] < g) lo = mid+1; else hi = mid; }
    d_start[g] = lo;
}
__global__ void k_pool(){
    int g = blockIdx.x;
    int s = d_start[g], e = d_start[g+1];
    int cnt = e - s;
    size_t rb = (size_t)g*KP_POOL;
    for (int c = threadIdx.x; c < HF; c += blockDim.x){
        float mx = -1e30f, sm = 0.f;
        #pragma unroll 4
        for (int n = s; n < e; n++){
            float v = d_x2[(size_t)n*HF + c];
            mx = fmaxf(mx, v); sm += v;
        }
        float vmax = (cnt > 0) ? mx : 0.f;
        float vmean = sm / fmaxf((float)cnt, 1.f);
        d_poolA[rb + c]      = __float2half_rn(vmax);
        d_poolA[rb + HF + c] = __float2half_rn(vmean);
    }
    if (threadIdx.x < KP_POOL - 2*HF)
        d_poolA[rb + 2*HF + threadIdx.x] = __float2half_rn(0.f);
}

// ================= small GEMM (f32x2, split-K) =================
__global__ void gemm2_kernel(const float* __restrict__ A, const float* __restrict__ B,
                             const float* __restrict__ bias, float* __restrict__ C,
                             int M, int N, int K, int ldc, int act)
{
    __shared__ float As[16*64];
    __shared__ float Bs[16*64];
    int tid = threadIdx.x;
    int row0 = blockIdx.y*64, col0 = blockIdx.x*64;
    int tx = tid & 15, ty = tid >> 4;
    int Z = gridDim.z, z = blockIdx.z;
    int T = (K + 15) / 16;
    int kc0 = (int)((long long)T * z / Z), kc1 = (int)((long long)T * (z+1) / Z);
    unsigned long long acc2[4][2];
    #pragma unroll
    for (int i=0;i<4;i++){ acc2[i][0] = 0ull; acc2[i][1] = 0ull; }
    for (int kc = kc0; kc < kc1; kc++){
        int k0 = kc*16;
        #pragma unroll
        for (int i=0;i<4;i++){
            int l = tid + i*256;
            int m = l >> 4, kk = l & 15;
            int r = row0 + m, kg = k0 + kk;
            As[kk*64+m] = (r < M && kg < K) ? A[(size_t)r*K + kg] : 0.f;
        }
        #pragma unroll
        for (int i=0;i<4;i++){
            int l = tid + i*256;
            int kk = l >> 6, n = l & 63;
            int kg = k0 + kk, c = col0 + n;
            Bs[kk*64+n] = (kg < K && c < N) ? B[(size_t)kg*N + c] : 0.f;
        }
        __syncthreads();
        #pragma unroll
        for (int kk=0; kk<16; kk++){
            float ra[4];
            #pragma unroll
            for (int i=0;i<4;i++) ra[i] = As[kk*64 + ty*4 + i];
            unsigned long long rb0 = *(const unsigned long long*)&Bs[kk*64 + tx*4];
            unsigned long long rb1 = *(const unsigned long long*)&Bs[kk*64 + tx*4 + 2];
            #pragma unroll
            for (int i=0;i<4;i++){
                unsigned long long ad;
                asm("mov.b64 %0, {%1, %1};" : "=l"(ad) : "r"(__float_as_uint(ra[i])));
                asm("fma.rn.f32x2 %0, %1, %2, %0;" : "+l"(acc2[i][0]) : "l"(ad), "l"(rb0));
                asm("fma.rn.f32x2 %0, %1, %2, %0;" : "+l"(acc2[i][1]) : "l"(ad), "l"(rb1));
            }
        }
        __syncthreads();
    }
    #pragma unroll
    for (int i=0;i<4;i++){
        int r = row0 + ty*4 + i;
        if (r >= M) continue;
        #pragma unroll
        for (int jp=0;jp<2;jp++){
            unsigned int lo, hi;
            asm("mov.b64 {%0, %1}, %2;" : "=r"(lo), "=r"(hi) : "l"(acc2[i][jp]));
            float vv[2] = { __uint_as_float(lo), __uint_as_float(hi) };
            int c = col0 + tx*4 + jp*2;
            #pragma unroll
            for (int q=0;q<2;q++){
                int cc = c + q;
                if (cc >= N) continue;
                if (Z == 1){
                    float v = vv[q];
                    if (bias) v += bias[cc];
                    if (act)  v = fmaxf(v, 0.f);
                    C[(size_t)r*ldc + cc] = v;
                } else {
                    atomicAdd(&C[(size_t)r*ldc + cc], vv[q]);
                }
            }
        }
    }
}

__global__ void k_binit(float* __restrict__ C, const float* __restrict__ bias,
                        int M, int N, int ldc){
    int i = blockIdx.x*blockDim.x + threadIdx.x;
    if (i >= M*N) return;
    int r = i / N, c = i - r*N;
    C[(size_t)r*ldc + c] = bias[c];
}

// ================= target branch =================
__global__ void k_buildM(const float* __restrict__ emb){
    int i = blockIdx.x*blockDim.x + threadIdx.x;
    if (i >= 128*KP_U) return;
    int p = i / KP_U, kidx = i - p*KP_U;
    float val = 0.f;
    if (p < CONVOUT && kidx < UCOLS){
        int v = kidx >> 3, kk = kidx & 7;
        val = emb[v*EMB + p + kk];
    }
    __half h, l; split_fp16(val, h, l);
    d_Mmh[i] = h; d_Mml[i] = l;
}
__global__ void k_transW(const float* __restrict__ W){
    int i = blockIdx.x*blockDim.x + threadIdx.x;
    if (i >= NFILT*SEQL*8) return;
    int o = i / (SEQL*8), c = (i >> 3) % SEQL, k = i & 7;
    d_Wt[c*(NFILT*8) + o*8 + k] = W[i];
}
__global__ void k_buildU(const int* __restrict__ target){
    __shared__ float sU[USZ];
    __shared__ int   st[SEQL];
    int g = blockIdx.x;
    for (int i = threadIdx.x; i < USZ;  i += blockDim.x) sU[i] = 0.f;
    for (int i = threadIdx.x; i < SEQL; i += blockDim.x) st[i] = target[g*SEQL + i];
    __syncthreads();
    int o = threadIdx.x >> 3, k = threadIdx.x & 7;
    for (int c = 0; c < SEQL; c++){
        int v = st[c];
        sU[o*UCOLS + v*8 + k] += d_Wt[c*(NFILT*8) + threadIdx.x];
    }
    __syncthreads();
    for (int i = threadIdx.x; i < NFILT*KP_U; i += blockDim.x){
        int oo = i / KP_U, col = i - oo*KP_U;
        float v = (col < UCOLS) ? sU[oo*UCOLS + col] : 0.f;
        d_UA[((size_t)g*NFILT + oo)*KP_U + col] = __float2half_rn(v);
    }
}
__global__ void k_fcxtb2(const float* __restrict__ fcxt_W,
                         const float* __restrict__ fcxt_b,
                         const float* __restrict__ conv_b){
    int j = blockIdx.x;
    __shared__ float red[128];
    float s = 0.f;
    for (int r = threadIdx.x; r < NFILT*CONVOUT; r += blockDim.x)
        s += conv_b[r / CONVOUT] * fcxt_W[(size_t)r*128 + j];
    red[threadIdx.x] = s; __syncthreads();
    for (int o = 64; o > 0; o >>= 1){
        if (threadIdx.x < o) red[threadIdx.x] += red[threadIdx.x + o];
        __syncthreads();
    }
    if (!threadIdx.x) d_fcxtb2[j] = fcxt_b[j] + red[0];
}

// ================= final projection (ReLU fused) =================
__global__ void k_out(const float* __restrict__ oW, const float* __restrict__ ob,
                      float* __restrict__ out){
    int g    = (blockIdx.x*blockDim.x + threadIdx.x) >> 5;
    int lane = threadIdx.x & 31;
    if (g >= NG) return;
    float s = 0.f;
    for (int k = lane; k < 512; k += 32)
        s += fmaxf(d_f2[g*512 + k], 0.f) * oW[k];
    #pragma unroll
    for (int o = 16; o > 0; o >>= 1) s += __shfl_down_sync(~0u, s, o);
    if (!lane) out[g] = s + ob[0];
}

extern "C" void kernel_launch(void* const* d_in, const int* in_sizes, int n_in,
                              void* d_out, int out_size){
    const float* x        = (const float*)d_in[0];
    const int*   ei       = (const int*)  d_in[1];
    const int*   batch    = (const int*)  d_in[2];
    const int*   target   = (const int*)  d_in[3];
    const float* gat_W    = (const float*)d_in[4];
    const float* gat_asrc = (const float*)d_in[5];
    const float* gat_adst = (const float*)d_in[6];
    const float* gat_b    = (const float*)d_in[7];
    const float* gcn_W    = (const float*)d_in[8];
    const float* gcn_b    = (const float*)d_in[9];
    const float* fcg1_W   = (const float*)d_in[10];
    const float* fcg1_b   = (const float*)d_in[11];
    const float* fcg2_W   = (const float*)d_in[12];
    const float* fcg2_b   = (const float*)d_in[13];
    const float* emb      = (const float*)d_in[14];
    const float* conv_W   = (const float*)d_in[15];
    const float* conv_b   = (const float*)d_in[16];
    const float* fcxt_W   = (const float*)d_in[17];
    const float* fcxt_b   = (const float*)d_in[18];
    const float* fc1_W    = (const float*)d_in[19];
    const float* fc1_b    = (const float*)d_in[20];
    const float* fc2_W    = (const float*)d_in[21];
    const float* fc2_b    = (const float*)d_in[22];
    const float* out_W    = (const float*)d_in[23];
    const float* out_b    = (const float*)d_in[24];

    float *p_xg1, *p_xc, *p_conv, *p_f1, *p_f2, *p_fcxtb2;
    __half *p_hh, *p_h2h, *p_xA, *p_x1A, *p_gWh, *p_gWl, *p_cWh, *p_cWl;
    __half *p_poolA, *p_fWh, *p_fWl, *p_UA, *p_Mmh, *p_Mml;
    cudaGetSymbolAddress((void**)&p_hh,   d_hh);
    cudaGetSymbolAddress((void**)&p_h2h,  d_h2h);
    cudaGetSymbolAddress((void**)&p_xg1,  d_xg1);
    cudaGetSymbolAddress((void**)&p_xc,   d_xc);
    cudaGetSymbolAddress((void**)&p_conv, d_conv);
    cudaGetSymbolAddress((void**)&p_f1,   d_f1);
    cudaGetSymbolAddress((void**)&p_f2,   d_f2);
    cudaGetSymbolAddress((void**)&p_fcxtb2, d_fcxtb2);
    cudaGetSymbolAddress((void**)&p_xA,  d_xA);
    cudaGetSymbolAddress((void**)&p_x1A, d_x1A);
    cudaGetSymbolAddress((void**)&p_gWh, d_gWh);
    cudaGetSymbolAddress((void**)&p_gWl, d_gWl);
    cudaGetSymbolAddress((void**)&p_cWh, d_cWh);
    cudaGetSymbolAddress((void**)&p_cWl, d_cWl);
    cudaGetSymbolAddress((void**)&p_poolA, d_poolA);
    cudaGetSymbolAddress((void**)&p_fWh, d_fWh);
    cudaGetSymbolAddress((void**)&p_fWl, d_fWl);
    cudaGetSymbolAddress((void**)&p_UA, d_UA);
    cudaGetSymbolAddress((void**)&p_Mmh, d_Mmh);
    cudaGetSymbolAddress((void**)&p_Mml, d_Mml);

    cudaFuncSetAttribute(gemm_mma_t<0>, cudaFuncAttributeMaxDynamicSharedMemorySize, 2*STG2);
    cudaFuncSetAttribute(gemm_mma_t<1>, cudaFuncAttributeMaxDynamicSharedMemorySize, 2*STG2);

    // launches 0..2: splits (launch 3 = gemm GAT lands under ncu -s 5)
    k_split_x<<<(NN*KP_GAT + 255)/256, 256>>>(x);
    k_splitB<<<(NPADG*KP_GAT + 255)/256, 256>>>(gat_W, p_gWh, p_gWl, NF, HF, KP_GAT, NPADG);
    k_splitB<<<(NPADG*KP_GCN + 255)/256, 256>>>(gcn_W, p_cWh, p_cWl, HF, HF, KP_GCN, NPADG);

    // launch 3: GAT transform (2-term, fp16 out), Ksteps=5
    {
        dim3 grid(NPADG/64, (NN + 127)/128);
        gemm_mma_t<1><<<grid, 256, 2*STG2>>>(p_xA, p_gWh, p_gWl, p_hh, NN, HF, KP_GAT, HF, nullptr, 0, NPADG, 5);
    }

    // CSR build
    k_deg_init<<<(NN + 255)/256, 256>>>();
    k_count<<<(NE + 255)/256, 256>>>(ei);
    k_scan<<<1, 1024>>>();
    k_fill<<<(NEP + 255)/256, 256>>>(ei);
    k_dinv<<<(NN + 255)/256, 256>>>();

    // remaining prep
    k_splitB<<<(NP_FCG1*KP_POOL + 255)/256, 256>>>(fcg1_W, p_fWh, p_fWl, 2*HF, 1024, KP_POOL, NP_FCG1);
    k_buildM<<<(128*KP_U + 255)/256, 256>>>(emb);
    k_transW<<<(NFILT*SEQL*8 + 255)/256, 256>>>(conv_W);

    // GAT attention (folded) + fused softmax/aggregation
    k_attw<<<(2*NF*NH*32 + 255)/256, 256>>>(gat_W, gat_asrc, gat_adst);
    k_asrcdst<<<(NN + 255)/256, 256>>>(x);
    k_gat_agg<<<NN, 256>>>(gat_b);

    // GCN (2-term, fp16 out), Ksteps=49
    {
        dim3 grid(NPADG/64, (NN + 127)/128);
        gemm_mma_t<1><<<grid, 256, 2*STG2>>>(p_x1A, p_cWh, p_cWl, p_h2h, NN, HF, KP_GCN, HF, nullptr, 0, NPADG, 49);
    }
    k_gcn_agg<<<NN, 256>>>(gcn_b);

    // pooling + graph head
    k_start<<<3, 256>>>(batch);
    k_pool<<<NG, 256>>>();
    {   // fcg1 (2-term, f32 out + bias/relu), Ksteps=98
        dim3 grid(1024/64, NG/128);
        gemm_mma_t<0><<<grid, 256, 2*STG2>>>(p_poolA, p_fWh, p_fWl, p_xg1, NG, 1024, KP_POOL, 1024, fcg1_b, 1, NP_FCG1, 98);
    }
    {
        k_binit<<<(NG*128 + 255)/256, 256>>>(p_xc, fcg2_b, NG, 128, 256);
        dim3 grid(2, 8, 4);
        gemm2_kernel<<<grid, 256>>>(p_xg1, fcg2_W, nullptr, p_xc, NG, 128, 1024, 256, 0);
    }

    // target branch
    k_buildU<<<NG, 256>>>(target);
    {   // conv GEMM (2-term, f32 out), Ksteps=13; ldc=121 odd -> guarded epilogue
        dim3 grid(2, (NG*NFILT)/128);
        gemm_mma_t<0><<<grid, 256, 2*STG2>>>(p_UA, p_Mmh, p_Mml, p_conv, NG*NFILT, CONVOUT, KP_U, CONVOUT, nullptr, 0, 128, 13);
    }
    k_fcxtb2<<<128, 128>>>(fcxt_W, fcxt_b, conv_b);
    {
        k_binit<<<(NG*128 + 255)/256, 256>>>(p_xc + 128, p_fcxtb2, NG, 128, 256);
        dim3 grid(2, 8, 4);
        gemm2_kernel<<<grid, 256>>>(p_conv, fcxt_W, nullptr, p_xc + 128, NG, 128, NFILT*CONVOUT, 256, 0);
    }

    // fusion head (fc2 ReLU fused into k_out)
    {
        dim3 grid(16, 8, 1);
        gemm2_kernel<<<grid, 256>>>(p_xc, fc1_W, fc1_b, p_f1, NG, 1024, 256, 1024, 1);
    }
    {
        k_binit<<<(NG*512 + 255)/256, 256>>>(p_f2, fc2_b, NG, 512, 512);
        dim3 grid(8, 8, 2);
        gemm2_kernel<<<grid, 256>>>(p_f1, fc2_W, nullptr, p_f2, NG, 512, 1024, 512, 0);
    }
    k_out<<<(NG*32 + 255)/256, 256>>>(out_W, out_b, (float*)d_out);
}

// round 17
// speedup vs baseline: 1.2872x; 1.0199x over previous
#include <cuda_runtime.h>
#include <cuda_fp16.h>
#include <math.h>
#include <stdint.h>

#define NN      25000
#define NE      100000
#define NEP     125000
#define NG      512
#define NH      10
#define NF      78
#define HF      780
#define SEQL    1000
#define EMB     128
#define NFILT   32
#define CONVOUT 121
#define VOCAB   26
#define UCOLS   (VOCAB*8)        // 208
#define USZ     (NFILT*UCOLS)

#define KP_GAT  128
#define KP_GCN  832
#define NPADG   832
#define KP_POOL 1600
#define NP_FCG1 1024
#define KP_U    256

// ---------------- device scratch ----------------
__device__ __half d_hh[(size_t)NN*HF];
__device__ __half d_h2h[(size_t)NN*HF];
__device__ float d_asrc[NN*NH];
__device__ float d_adst[NN*NH];
__device__ float d_wsrc[NF*NH];
__device__ float d_wdst[NF*NH];
__device__ float d_x2[NN*HF];
__device__ float d_dinv[NN];
__device__ int   d_deg[NN];
__device__ int   d_roff[NN+1];
__device__ int   d_rpos[NN];
__device__ int   d_csrc[NEP];
__device__ int   d_start[NG+1];
__device__ float d_xg1[NG*1024];
__device__ float d_Wt[SEQL*NFILT*8];
__device__ float d_conv[(size_t)NG*NFILT*CONVOUT];
__device__ float d_fcxtb2[128];
__device__ float d_xc[NG*256];
__device__ float d_f1[NG*1024];
__device__ float d_f2[NG*512];
__device__ __half d_xA[(size_t)NN*KP_GAT];
__device__ __half d_x1A[(size_t)NN*KP_GCN];
__device__ __half d_gWh[(size_t)NPADG*KP_GAT];
__device__ __half d_gWl[(size_t)NPADG*KP_GAT];
__device__ __half d_cWh[(size_t)NPADG*KP_GCN];
__device__ __half d_cWl[(size_t)NPADG*KP_GCN];
__device__ __half d_poolA[(size_t)NG*KP_POOL];
__device__ __half d_fWh[(size_t)NP_FCG1*KP_POOL];
__device__ __half d_fWl[(size_t)NP_FCG1*KP_POOL];
__device__ __half d_UA[(size_t)NG*NFILT*KP_U];
__device__ __half d_Mmh[128*KP_U];
__device__ __half d_Mml[128*KP_U];

// ================= helpers =================
__device__ __forceinline__ uint32_t smem_u32(const void* p){
    uint32_t a;
    asm("{ .reg .u64 t; cvta.to.shared.u64 t, %1; cvt.u32.u64 %0, t; }" : "=r"(a) : "l"(p));
    return a;
}
#define LDMX4(r, a) \
    asm volatile("ldmatrix.sync.aligned.m8n8.x4.shared.b16 {%0,%1,%2,%3}, [%4];" \
        : "=r"((r)[0]), "=r"((r)[1]), "=r"((r)[2]), "=r"((r)[3]) : "r"(a))
#define MMA16816(d, a, b0, b1) \
    asm volatile("mma.sync.aligned.m16n8k16.row.col.f32.f16.f16.f32 " \
        "{%0,%1,%2,%3}, {%4,%5,%6,%7}, {%8,%9}, {%0,%1,%2,%3};" \
        : "+f"((d)[0]), "+f"((d)[1]), "+f"((d)[2]), "+f"((d)[3]) \
        : "r"((a)[0]), "r"((a)[1]), "r"((a)[2]), "r"((a)[3]), "r"(b0), "r"(b1))
#define CPA_COMMIT() asm volatile("cp.async.commit_group;" ::: "memory")
#define CPA_WAIT0()  asm volatile("cp.async.wait_group 0;" ::: "memory")

__device__ __forceinline__ void cpa16(uint32_t dst, const void* src, int sz){
    size_t g;
    asm("cvta.to.global.u64 %0, %1;" : "=l"(g) : "l"(src));
    asm volatile("cp.async.cg.shared.global [%0], [%1], 16, %2;" :: "r"(dst), "l"(g), "r"(sz) : "memory");
}
__device__ __forceinline__ void split_fp16(float v, __half& h, __half& l){
    h = __float2half_rn(v);
    l = __float2half_rn(v - __half2float(h));
}

// ================= mma.sync fp16 2-term GEMM (128x64 tile, Ksteps-masked) =================
#define GPITCH 72
#define ATILEB 18432
#define BTILEB 9216
#define STG2   (ATILEB + 2*BTILEB)   // 36864

__device__ __forceinline__ void ld_tileA(uint32_t sdst, const __half* G,
                                         int row0, int k0, int KP, int rlim, int tid){
    #pragma unroll
    for (int i = 0; i < 4; i++){
        int v = tid + i*256;
        int r = v >> 3, cq = v & 7;
        int row = row0 + r;
        int sz = (row < rlim) ? 16 : 0;
        cpa16(sdst + r*144 + cq*16, G + (size_t)(sz ? row : row0)*KP + k0 + cq*8, sz);
    }
}
__device__ __forceinline__ void ld_tileB(uint32_t sdst, const __half* G,
                                         int row0, int k0, int KP, int rlim, int tid){
    #pragma unroll
    for (int i = 0; i < 2; i++){
        int v = tid + i*256;
        int r = v >> 3, cq = v & 7;
        int row = row0 + r;
        int sz = (row < rlim) ? 16 : 0;
        cpa16(sdst + r*144 + cq*16, G + (size_t)(sz ? row : row0)*KP + k0 + cq*8, sz);
    }
}

template<int OUTH>
__global__ void __launch_bounds__(256, 2) gemm_mma_t(
    const __half* __restrict__ A,
    const __half* __restrict__ Bh, const __half* __restrict__ Bl,
    void* __restrict__ Cv, int M, int Nout, int KP, int ldc,
    const float* __restrict__ bias, int act, int Brows, int Ksteps)
{
    extern __shared__ char sm[];
    uint32_t sb = smem_u32(sm);
    int tid = threadIdx.x;
    int m0 = blockIdx.y*128, n0 = blockIdx.x*64;
    int w = tid >> 5, lane = tid & 31;
    int wm = (w >> 1) * 32;
    int wn = (w & 1) * 32;
    int NC = KP / 64;

    float acc[2][4][4];
    #pragma unroll
    for (int i=0;i<2;i++)
        #pragma unroll
        for (int j=0;j<4;j++)
            #pragma unroll
            for (int q=0;q<4;q++) acc[i][j][q] = 0.f;

    int a_row = (lane & 15);
    int a_kc  = (lane >> 4) * 8;
    int b_row = ((lane >> 4) * 8) + (lane & 7);
    int b_kc  = ((lane >> 3) & 1) * 8;

    ld_tileA(sb + 0,               A,  m0, 0, KP, M, tid);
    ld_tileB(sb + ATILEB,          Bh, n0, 0, KP, Brows, tid);
    ld_tileB(sb + ATILEB + BTILEB, Bl, n0, 0, KP, Brows, tid);
    CPA_COMMIT();

    for (int ci = 0; ci < NC; ci++){
        int b = ci & 1;
        uint32_t st = sb + b*STG2;
        CPA_WAIT0();
        __syncthreads();
        if (ci + 1 < NC){
            uint32_t s2 = sb + (1-b)*STG2;
            int k0n = (ci+1)*64;
            ld_tileA(s2 + 0,               A,  m0, k0n, KP, M, tid);
            ld_tileB(s2 + ATILEB,          Bh, n0, k0n, KP, Brows, tid);
            ld_tileB(s2 + ATILEB + BTILEB, Bl, n0, k0n, KP, Brows, tid);
            CPA_COMMIT();
        }
        uint32_t bA = st, bBh = st + ATILEB, bBl = st + ATILEB + BTILEB;
        #pragma unroll
        for (int kk = 0; kk < 64; kk += 16){
            if (ci*4 + (kk >> 4) >= Ksteps) break;
            uint32_t ah[2][4];
            #pragma unroll
            for (int mt = 0; mt < 2; mt++){
                uint32_t off = (uint32_t)((wm + mt*16 + a_row)*GPITCH + kk + a_kc) * 2;
                LDMX4(ah[mt], bA + off);
            }
            #pragma unroll
            for (int nt2 = 0; nt2 < 2; nt2++){
                uint32_t offb = (uint32_t)((wn + nt2*16 + b_row)*GPITCH + kk + b_kc) * 2;
                uint32_t bhf[4], blf[4];
                LDMX4(bhf, bBh + offb);
                LDMX4(blf, bBl + offb);
                #pragma unroll
                for (int mt = 0; mt < 2; mt++){
                    MMA16816(acc[mt][nt2*2],   ah[mt], bhf[0], bhf[1]);
                    MMA16816(acc[mt][nt2*2+1], ah[mt], bhf[2], bhf[3]);
                }
                #pragma unroll
                for (int mt = 0; mt < 2; mt++){
                    MMA16816(acc[mt][nt2*2],   ah[mt], blf[0], blf[1]);
                    MMA16816(acc[mt][nt2*2+1], ah[mt], blf[2], blf[3]);
                }
            }
        }
    }
    #pragma unroll
    for (int mt = 0; mt < 2; mt++){
        int r0 = m0 + wm + mt*16 + (lane >> 2);
        #pragma unroll
        for (int nt = 0; nt < 4; nt++){
            int c = n0 + wn + nt*8 + (lane & 3)*2;
            #pragma unroll
            for (int hq = 0; hq < 2; hq++){
                int rr = r0 + hq*8;
                if (rr >= M) continue;
                float v0 = acc[mt][nt][hq*2 + 0];
                float v1 = acc[mt][nt][hq*2 + 1];
                if (bias){ v0 += bias[c]; if (c+1 < Nout) v1 += bias[c+1]; }
                if (act){ v0 = fmaxf(v0, 0.f); v1 = fmaxf(v1, 0.f); }
                size_t idx = (size_t)rr*ldc + c;
                if (c + 1 < Nout && ((idx & 1) == 0)){
                    if (OUTH){
                        __half2 hv = __floats2half2_rn(v0, v1);
                        *(__half2*)&((__half*)Cv)[idx] = hv;
                    } else {
                        float2 fv = make_float2(v0, v1);
                        *(float2*)&((float*)Cv)[idx] = fv;
                    }
                } else {
                    if (c < Nout){
                        if (OUTH) ((__half*)Cv)[idx] = __float2half_rn(v0);
                        else      ((float*)Cv)[idx] = v0;
                    }
                    if (c + 1 < Nout){
                        if (OUTH) ((__half*)Cv)[idx + 1] = __float2half_rn(v1);
                        else      ((float*)Cv)[idx + 1] = v1;
                    }
                }
            }
        }
    }
}

// ================= split-prep =================
__global__ void k_split_x(const float* __restrict__ x){
    int i = blockIdx.x*blockDim.x + threadIdx.x;
    if (i >= NN*KP_GAT) return;
    int r = i >> 7, k = i & (KP_GAT-1);
    float v = (k < NF) ? x[r*NF + k] : 0.f;
    d_xA[i] = __float2half_rn(v);
}
// tiled-transpose split: W[K x N] row-major -> bh/bl[NR x KP] (K-major rows)
__global__ void k_splitBT(const float* __restrict__ W, __half* __restrict__ bh,
                          __half* __restrict__ bl, int K, int N, int KP, int NR){
    __shared__ float tile[32][33];
    int k0 = blockIdx.x*32, n0 = blockIdx.y*32;
    int tx = threadIdx.x, ty = threadIdx.y;   // 32 x 8
    #pragma unroll
    for (int j = 0; j < 4; j++){
        int k = k0 + ty + j*8, n = n0 + tx;
        tile[ty + j*8][tx] = (k < K && n < N) ? W[(size_t)k*N + n] : 0.f;
    }
    __syncthreads();
    #pragma unroll
    for (int j = 0; j < 4; j++){
        int n = n0 + ty + j*8, k = k0 + tx;
        if (n < NR && k < KP){
            float v = tile[tx][ty + j*8];
            __half h, l; split_fp16(v, h, l);
            bh[(size_t)n*KP + k] = h;
            bl[(size_t)n*KP + k] = l;
        }
    }
}

// ================= CSR build =================
__global__ void k_deg_init(){
    int n = blockIdx.x*blockDim.x + threadIdx.x;
    if (n < NN) d_deg[n] = 1;
}
__global__ void k_count(const int* __restrict__ ei){
    int e = blockIdx.x*blockDim.x + threadIdx.x;
    if (e < NE) atomicAdd(&d_deg[ei[NE+e]], 1);
}
__global__ void k_scan(){
    __shared__ int part[1024];
    int t = threadIdx.x;
    const int PER = 25;
    int base = t*PER, sum = 0;
    for (int i = 0; i < PER; i++){ int idx = base+i; if (idx < NN) sum += d_deg[idx]; }
    part[t] = sum; __syncthreads();
    for (int off = 1; off < 1024; off <<= 1){
        int v = (t >= off) ? part[t-off] : 0; __syncthreads();
        part[t] += v; __syncthreads();
    }
    int run = part[t] - sum;
    for (int i = 0; i < PER; i++){
        int idx = base+i;
        if (idx < NN){ d_roff[idx] = run; d_rpos[idx] = run; run += d_deg[idx]; }
    }
    if (t == 1023) d_roff[NN] = NEP;
}
__global__ void k_fill(const int* __restrict__ ei){
    int e = blockIdx.x*blockDim.x + threadIdx.x;
    if (e >= NEP) return;
    int s, d;
    if (e < NE){ s = ei[e]; d = ei[NE+e]; } else { s = d = e - NE; }
    int pos = atomicAdd(&d_rpos[d], 1);
    d_csrc[pos] = s;
}
__global__ void k_dinv(){
    int n = blockIdx.x*blockDim.x + threadIdx.x;
    if (n < NN) d_dinv[n] = rsqrtf((float)d_deg[n]);
}

// ================= GAT attention (folded) =================
__global__ void k_attw(const float* __restrict__ gat_W,
                       const float* __restrict__ att_src,
                       const float* __restrict__ att_dst){
    int wid  = (blockIdx.x*blockDim.x + threadIdx.x) >> 5;
    int lane = threadIdx.x & 31;
    if (wid >= 2*NF*NH) return;
    int which = (wid >= NF*NH);
    int r = wid - which*NF*NH;
    int f_in = r / NH, hh = r - f_in*NH;
    const float* att = which ? att_dst : att_src;
    float s = 0.f;
    for (int f = lane; f < NF; f += 32)
        s += gat_W[(size_t)f_in*HF + hh*NF + f] * att[hh*NF + f];
    #pragma unroll
    for (int o = 16; o > 0; o >>= 1) s += __shfl_down_sync(~0u, s, o);
    if (!lane){
        if (which) d_wdst[f_in*NH + hh] = s;
        else       d_wsrc[f_in*NH + hh] = s;
    }
}
__global__ void k_asrcdst(const float* __restrict__ x){
    __shared__ float ws[NF*NH], wd[NF*NH];
    int tid = threadIdx.x;
    for (int i = tid; i < NF*NH; i += 256){ ws[i] = d_wsrc[i]; wd[i] = d_wdst[i]; }
    __syncthreads();
    int n = blockIdx.x*256 + tid;
    if (n >= NN) return;
    float as[NH], ad[NH];
    #pragma unroll
    for (int hh = 0; hh < NH; hh++){ as[hh] = 0.f; ad[hh] = 0.f; }
    const float* xr = x + (size_t)n*NF;
    for (int f = 0; f < NF; f++){
        float xv = xr[f];
        #pragma unroll
        for (int hh = 0; hh < NH; hh++){
            as[hh] += xv * ws[f*NH + hh];
            ad[hh] += xv * wd[f*NH + hh];
        }
    }
    #pragma unroll
    for (int hh = 0; hh < NH; hh++){
        d_asrc[n*NH + hh] = as[hh];
        d_adst[n*NH + hh] = ad[hh];
    }
}

// fused softmax + aggregation (one block per node)
__global__ void k_gat_agg(const float* __restrict__ gat_b){
    int n = blockIdx.x;
    int tid = threadIdx.x;
    __shared__ float smx[NH], sinv[NH];
    __shared__ int   csrc_c[25];
    __shared__ float coef_c[25][NH];
    int s0 = d_roff[n], s1 = d_roff[n+1];
    if (tid < NH){
        float ad = d_adst[n*NH + tid];
        float mx = -1e30f;
        for (int p = s0; p < s1; p++){
            float a = d_asrc[d_csrc[p]*NH + tid] + ad;
            a = a > 0.f ? a : 0.2f*a;
            mx = fmaxf(mx, a);
        }
        float sum = 0.f;
        for (int p = s0; p < s1; p++){
            float a = d_asrc[d_csrc[p]*NH + tid] + ad;
            a = a > 0.f ? a : 0.2f*a;
            sum += expf(a - mx);
        }
        smx[tid]  = mx;
        sinv[tid] = 1.f / (sum + 1e-16f);
    }
    __syncthreads();
    float4 acc = make_float4(0.f,0.f,0.f,0.f);
    int c0 = tid*4;
    int h0 = c0/NF, h1 = (c0+1)/NF, h2 = (c0+2)/NF, h3 = (c0+3)/NF;
    for (int base = s0; base < s1; base += 25){
        int cnt = s1 - base; if (cnt > 25) cnt = 25;
        if (tid < cnt) csrc_c[tid] = d_csrc[base + tid];
        __syncthreads();
        if (tid < cnt*NH){
            int p = tid / NH, hh = tid - p*NH;
            float a = d_asrc[csrc_c[p]*NH + hh] + d_adst[n*NH + hh];
            a = a > 0.f ? a : 0.2f*a;
            coef_c[p][hh] = expf(a - smx[hh]) * sinv[hh];
        }
        __syncthreads();
        if (tid < 195){
            #pragma unroll 2
            for (int j = 0; j < cnt; j++){
                uint2 raw = *(const uint2*)(d_hh + (size_t)csrc_c[j]*HF + c0);
                float2 v01 = __half22float2(*(const __half2*)&raw.x);
                float2 v23 = __half22float2(*(const __half2*)&raw.y);
                acc.x += coef_c[j][h0]*v01.x;
                acc.y += coef_c[j][h1]*v01.y;
                acc.z += coef_c[j][h2]*v23.x;
                acc.w += coef_c[j][h3]*v23.y;
            }
        }
        __syncthreads();
    }
    if (tid < 195){
        float4 bb = *(const float4*)(gat_b + c0);
        #pragma unroll
        for (int q = 0; q < 4; q++){
            float r = fmaxf(((float*)&acc)[q] + ((float*)&bb)[q], 0.f);
            d_x1A[(size_t)n*KP_GCN + c0 + q] = __float2half_rn(r);
        }
    } else if (tid < 208){
        #pragma unroll
        for (int q = 0; q < 4; q++)
            d_x1A[(size_t)n*KP_GCN + c0 + q] = __float2half_rn(0.f);
    }
}

// ================= GCN aggregate =================
__global__ void k_gcn_agg(const float* __restrict__ gcn_b){
    int n = blockIdx.x;
    int tid = threadIdx.x;
    __shared__ int   csrc_c[64];
    __shared__ float coef_c[64];
    int s0 = d_roff[n], s1 = d_roff[n+1];
    float dn = d_dinv[n];
    float4 acc = make_float4(0.f,0.f,0.f,0.f);
    int c0 = tid*4;
    for (int base = s0; base < s1; base += 64){
        int cnt = s1 - base; if (cnt > 64) cnt = 64;
        if (tid < cnt){
            int s = d_csrc[base + tid];
            csrc_c[tid] = s;
            coef_c[tid] = dn * d_dinv[s];
        }
        __syncthreads();
        if (tid < 195){
            #pragma unroll 2
            for (int j = 0; j < cnt; j++){
                uint2 raw = *(const uint2*)(d_h2h + (size_t)csrc_c[j]*HF + c0);
                float2 v01 = __half22float2(*(const __half2*)&raw.x);
                float2 v23 = __half22float2(*(const __half2*)&raw.y);
                float cf = coef_c[j];
                acc.x += cf*v01.x; acc.y += cf*v01.y;
                acc.z += cf*v23.x; acc.w += cf*v23.y;
            }
        }
        __syncthreads();
    }
    if (tid < 195){
        float4 bb = *(const float4*)(gcn_b + c0);
        float4 r = make_float4(fmaxf(acc.x + bb.x, 0.f), fmaxf(acc.y + bb.y, 0.f),
                               fmaxf(acc.z + bb.z, 0.f), fmaxf(acc.w + bb.w, 0.f));
        *(float4*)(d_x2 + (size_t)n*HF + c0) = r;
    }
}

// ================= pooling =================
__global__ void k_start(const int* __restrict__ batch){
    int g = blockIdx.x*blockDim.x + threadIdx.x;
    if (g > NG) return;
    if (g == NG){ d_start[NG] = NN; return; }
    int lo = 0, hi = NN;
    while (lo < hi){ int mid = (lo+hi) >> 1; if (batch[mid] < g) lo = mid+1; else hi = mid; }
    d_start[g] = lo;
}
__global__ void k_pool(){
    int g = blockIdx.x;
    int s = d_start[g], e = d_start[g+1];
    int cnt = e - s;
    size_t rb = (size_t)g*KP_POOL;
    for (int c = threadIdx.x; c < HF; c += blockDim.x){
        float mx = -1e30f, sm = 0.f;
        #pragma unroll 4
        for (int n = s; n < e; n++){
            float v = d_x2[(size_t)n*HF + c];
            mx = fmaxf(mx, v); sm += v;
        }
        float vmax = (cnt > 0) ? mx : 0.f;
        float vmean = sm / fmaxf((float)cnt, 1.f);
        d_poolA[rb + c]      = __float2half_rn(vmax);
        d_poolA[rb + HF + c] = __float2half_rn(vmean);
    }
    if (threadIdx.x < KP_POOL - 2*HF)
        d_poolA[rb + 2*HF + threadIdx.x] = __float2half_rn(0.f);
}

// ================= small GEMM (f32x2, split-K) =================
__global__ void gemm2_kernel(const float* __restrict__ A, const float* __restrict__ B,
                             const float* __restrict__ bias, float* __restrict__ C,
                             int M, int N, int K, int ldc, int act)
{
    __shared__ float As[16*64];
    __shared__ float Bs[16*64];
    int tid = threadIdx.x;
    int row0 = blockIdx.y*64, col0 = blockIdx.x*64;
    int tx = tid & 15, ty = tid >> 4;
    int Z = gridDim.z, z = blockIdx.z;
    int T = (K + 15) / 16;
    int kc0 = (int)((long long)T * z / Z), kc1 = (int)((long long)T * (z+1) / Z);
    unsigned long long acc2[4][2];
    #pragma unroll
    for (int i=0;i<4;i++){ acc2[i][0] = 0ull; acc2[i][1] = 0ull; }
    for (int kc = kc0; kc < kc1; kc++){
        int k0 = kc*16;
        #pragma unroll
        for (int i=0;i<4;i++){
            int l = tid + i*256;
            int m = l >> 4, kk = l & 15;
            int r = row0 + m, kg = k0 + kk;
            As[kk*64+m] = (r < M && kg < K) ? A[(size_t)r*K + kg] : 0.f;
        }
        #pragma unroll
        for (int i=0;i<4;i++){
            int l = tid + i*256;
            int kk = l >> 6, n = l & 63;
            int kg = k0 + kk, c = col0 + n;
            Bs[kk*64+n] = (kg < K && c < N) ? B[(size_t)kg*N + c] : 0.f;
        }
        __syncthreads();
        #pragma unroll
        for (int kk=0; kk<16; kk++){
            float ra[4];
            #pragma unroll
            for (int i=0;i<4;i++) ra[i] = As[kk*64 + ty*4 + i];
            unsigned long long rb0 = *(const unsigned long long*)&Bs[kk*64 + tx*4];
            unsigned long long rb1 = *(const unsigned long long*)&Bs[kk*64 + tx*4 + 2];
            #pragma unroll
            for (int i=0;i<4;i++){
                unsigned long long ad;
                asm("mov.b64 %0, {%1, %1};" : "=l"(ad) : "r"(__float_as_uint(ra[i])));
                asm("fma.rn.f32x2 %0, %1, %2, %0;" : "+l"(acc2[i][0]) : "l"(ad), "l"(rb0));
                asm("fma.rn.f32x2 %0, %1, %2, %0;" : "+l"(acc2[i][1]) : "l"(ad), "l"(rb1));
            }
        }
        __syncthreads();
    }
    #pragma unroll
    for (int i=0;i<4;i++){
        int r = row0 + ty*4 + i;
        if (r >= M) continue;
        #pragma unroll
        for (int jp=0;jp<2;jp++){
            unsigned int lo, hi;
            asm("mov.b64 {%0, %1}, %2;" : "=r"(lo), "=r"(hi) : "l"(acc2[i][jp]));
            float vv[2] = { __uint_as_float(lo), __uint_as_float(hi) };
            int c = col0 + tx*4 + jp*2;
            #pragma unroll
            for (int q=0;q<2;q++){
                int cc = c + q;
                if (cc >= N) continue;
                if (Z == 1){
                    float v = vv[q];
                    if (bias) v += bias[cc];
                    if (act)  v = fmaxf(v, 0.f);
                    C[(size_t)r*ldc + cc] = v;
                } else {
                    atomicAdd(&C[(size_t)r*ldc + cc], vv[q]);
                }
            }
        }
    }
}

__global__ void k_binit(float* __restrict__ C, const float* __restrict__ bias,
                        int M, int N, int ldc){
    int i = blockIdx.x*blockDim.x + threadIdx.x;
    if (i >= M*N) return;
    int r = i / N, c = i - r*N;
    C[(size_t)r*ldc + c] = bias[c];
}

// ================= target branch =================
__global__ void k_buildM(const float* __restrict__ emb){
    int i = blockIdx.x*blockDim.x + threadIdx.x;
    if (i >= 128*KP_U) return;
    int p = i / KP_U, kidx = i - p*KP_U;
    float val = 0.f;
    if (p < CONVOUT && kidx < UCOLS){
        int v = kidx >> 3, kk = kidx & 7;
        val = emb[v*EMB + p + kk];
    }
    __half h, l; split_fp16(val, h, l);
    d_Mmh[i] = h; d_Mml[i] = l;
}
__global__ void k_transW(const float* __restrict__ W){
    int i = blockIdx.x*blockDim.x + threadIdx.x;
    if (i >= NFILT*SEQL*8) return;
    int o = i / (SEQL*8), c = (i >> 3) % SEQL, k = i & 7;
    d_Wt[c*(NFILT*8) + o*8 + k] = W[i];
}
__global__ void k_buildU(const int* __restrict__ target){
    __shared__ float sU[USZ];
    __shared__ int   st[SEQL];
    int g = blockIdx.x;
    for (int i = threadIdx.x; i < USZ;  i += blockDim.x) sU[i] = 0.f;
    for (int i = threadIdx.x; i < SEQL; i += blockDim.x) st[i] = target[g*SEQL + i];
    __syncthreads();
    int o = threadIdx.x >> 3, k = threadIdx.x & 7;
    for (int c = 0; c < SEQL; c++){
        int v = st[c];
        sU[o*UCOLS + v*8 + k] += d_Wt[c*(NFILT*8) + threadIdx.x];
    }
    __syncthreads();
    for (int i = threadIdx.x; i < NFILT*KP_U; i += blockDim.x){
        int oo = i / KP_U, col = i - oo*KP_U;
        float v = (col < UCOLS) ? sU[oo*UCOLS + col] : 0.f;
        d_UA[((size_t)g*NFILT + oo)*KP_U + col] = __float2half_rn(v);
    }
}
__global__ void k_fcxtb2(const float* __restrict__ fcxt_W,
                         const float* __restrict__ fcxt_b,
                         const float* __restrict__ conv_b){
    int j = blockIdx.x;
    __shared__ float red[128];
    float s = 0.f;
    for (int r = threadIdx.x; r < NFILT*CONVOUT; r += blockDim.x)
        s += conv_b[r / CONVOUT] * fcxt_W[(size_t)r*128 + j];
    red[threadIdx.x] = s; __syncthreads();
    for (int o = 64; o > 0; o >>= 1){
        if (threadIdx.x < o) red[threadIdx.x] += red[threadIdx.x + o];
        __syncthreads();
    }
    if (!threadIdx.x) d_fcxtb2[j] = fcxt_b[j] + red[0];
}

// ================= final projection (ReLU fused) =================
__global__ void k_out(const float* __restrict__ oW, const float* __restrict__ ob,
                      float* __restrict__ out){
    int g    = (blockIdx.x*blockDim.x + threadIdx.x) >> 5;
    int lane = threadIdx.x & 31;
    if (g >= NG) return;
    float s = 0.f;
    for (int k = lane; k < 512; k += 32)
        s += fmaxf(d_f2[g*512 + k], 0.f) * oW[k];
    #pragma unroll
    for (int o = 16; o > 0; o >>= 1) s += __shfl_down_sync(~0u, s, o);
    if (!lane) out[g] = s + ob[0];
}

extern "C" void kernel_launch(void* const* d_in, const int* in_sizes, int n_in,
                              void* d_out, int out_size){
    const float* x        = (const float*)d_in[0];
    const int*   ei       = (const int*)  d_in[1];
    const int*   batch    = (const int*)  d_in[2];
    const int*   target   = (const int*)  d_in[3];
    const float* gat_W    = (const float*)d_in[4];
    const float* gat_asrc = (const float*)d_in[5];
    const float* gat_adst = (const float*)d_in[6];
    const float* gat_b    = (const float*)d_in[7];
    const float* gcn_W    = (const float*)d_in[8];
    const float* gcn_b    = (const float*)d_in[9];
    const float* fcg1_W   = (const float*)d_in[10];
    const float* fcg1_b   = (const float*)d_in[11];
    const float* fcg2_W   = (const float*)d_in[12];
    const float* fcg2_b   = (const float*)d_in[13];
    const float* emb      = (const float*)d_in[14];
    const float* conv_W   = (const float*)d_in[15];
    const float* conv_b   = (const float*)d_in[16];
    const float* fcxt_W   = (const float*)d_in[17];
    const float* fcxt_b   = (const float*)d_in[18];
    const float* fc1_W    = (const float*)d_in[19];
    const float* fc1_b    = (const float*)d_in[20];
    const float* fc2_W    = (const float*)d_in[21];
    const float* fc2_b    = (const float*)d_in[22];
    const float* out_W    = (const float*)d_in[23];
    const float* out_b    = (const float*)d_in[24];

    float *p_xg1, *p_xc, *p_conv, *p_f1, *p_f2, *p_fcxtb2;
    __half *p_hh, *p_h2h, *p_xA, *p_x1A, *p_gWh, *p_gWl, *p_cWh, *p_cWl;
    __half *p_poolA, *p_fWh, *p_fWl, *p_UA, *p_Mmh, *p_Mml;
    cudaGetSymbolAddress((void**)&p_hh,   d_hh);
    cudaGetSymbolAddress((void**)&p_h2h,  d_h2h);
    cudaGetSymbolAddress((void**)&p_xg1,  d_xg1);
    cudaGetSymbolAddress((void**)&p_xc,   d_xc);
    cudaGetSymbolAddress((void**)&p_conv, d_conv);
    cudaGetSymbolAddress((void**)&p_f1,   d_f1);
    cudaGetSymbolAddress((void**)&p_f2,   d_f2);
    cudaGetSymbolAddress((void**)&p_fcxtb2, d_fcxtb2);
    cudaGetSymbolAddress((void**)&p_xA,  d_xA);
    cudaGetSymbolAddress((void**)&p_x1A, d_x1A);
    cudaGetSymbolAddress((void**)&p_gWh, d_gWh);
    cudaGetSymbolAddress((void**)&p_gWl, d_gWl);
    cudaGetSymbolAddress((void**)&p_cWh, d_cWh);
    cudaGetSymbolAddress((void**)&p_cWl, d_cWl);
    cudaGetSymbolAddress((void**)&p_poolA, d_poolA);
    cudaGetSymbolAddress((void**)&p_fWh, d_fWh);
    cudaGetSymbolAddress((void**)&p_fWl, d_fWl);
    cudaGetSymbolAddress((void**)&p_UA, d_UA);
    cudaGetSymbolAddress((void**)&p_Mmh, d_Mmh);
    cudaGetSymbolAddress((void**)&p_Mml, d_Mml);

    cudaFuncSetAttribute(gemm_mma_t<0>, cudaFuncAttributeMaxDynamicSharedMemorySize, 2*STG2);
    cudaFuncSetAttribute(gemm_mma_t<1>, cudaFuncAttributeMaxDynamicSharedMemorySize, 2*STG2);

    dim3 tb(32, 8);

    // launches 0..2: splits (launch 3 = gemm GAT lands under ncu -s 5)
    k_split_x<<<(NN*KP_GAT + 255)/256, 256>>>(x);
    {
        dim3 g((KP_GAT + 31)/32, (NPADG + 31)/32);
        k_splitBT<<<g, tb>>>(gat_W, p_gWh, p_gWl, NF, HF, KP_GAT, NPADG);
    }
    {
        dim3 g((KP_GCN + 31)/32, (NPADG + 31)/32);
        k_splitBT<<<g, tb>>>(gcn_W, p_cWh, p_cWl, HF, HF, KP_GCN, NPADG);
    }

    // launch 3: GAT transform (2-term, fp16 out), Ksteps=5
    {
        dim3 grid(NPADG/64, (NN + 127)/128);
        gemm_mma_t<1><<<grid, 256, 2*STG2>>>(p_xA, p_gWh, p_gWl, p_hh, NN, HF, KP_GAT, HF, nullptr, 0, NPADG, 5);
    }

    // CSR build
    k_deg_init<<<(NN + 255)/256, 256>>>();
    k_count<<<(NE + 255)/256, 256>>>(ei);
    k_scan<<<1, 1024>>>();
    k_fill<<<(NEP + 255)/256, 256>>>(ei);
    k_dinv<<<(NN + 255)/256, 256>>>();

    // remaining prep
    {
        dim3 g((KP_POOL + 31)/32, (NP_FCG1 + 31)/32);
        k_splitBT<<<g, tb>>>(fcg1_W, p_fWh, p_fWl, 2*HF, 1024, KP_POOL, NP_FCG1);
    }
    k_buildM<<<(128*KP_U + 255)/256, 256>>>(emb);
    k_transW<<<(NFILT*SEQL*8 + 255)/256, 256>>>(conv_W);

    // GAT attention (folded) + fused softmax/aggregation
    k_attw<<<(2*NF*NH*32 + 255)/256, 256>>>(gat_W, gat_asrc, gat_adst);
    k_asrcdst<<<(NN + 255)/256, 256>>>(x);
    k_gat_agg<<<NN, 256>>>(gat_b);

    // GCN (2-term, fp16 out), Ksteps=49
    {
        dim3 grid(NPADG/64, (NN + 127)/128);
        gemm_mma_t<1><<<grid, 256, 2*STG2>>>(p_x1A, p_cWh, p_cWl, p_h2h, NN, HF, KP_GCN, HF, nullptr, 0, NPADG, 49);
    }
    k_gcn_agg<<<NN, 256>>>(gcn_b);

    // pooling + graph head
    k_start<<<3, 256>>>(batch);
    k_pool<<<NG, 256>>>();
    {   // fcg1 (2-term, f32 out + bias/relu), Ksteps=98
        dim3 grid(1024/64, NG/128);
        gemm_mma_t<0><<<grid, 256, 2*STG2>>>(p_poolA, p_fWh, p_fWl, p_xg1, NG, 1024, KP_POOL, 1024, fcg1_b, 1, NP_FCG1, 98);
    }
    {
        k_binit<<<(NG*128 + 255)/256, 256>>>(p_xc, fcg2_b, NG, 128, 256);
        dim3 grid(2, 8, 4);
        gemm2_kernel<<<grid, 256>>>(p_xg1, fcg2_W, nullptr, p_xc, NG, 128, 1024, 256, 0);
    }

    // target branch
    k_buildU<<<NG, 256>>>(target);
    {   // conv GEMM (2-term, f32 out), Ksteps=13; ldc=121 odd -> guarded epilogue
        dim3 grid(2, (NG*NFILT)/128);
        gemm_mma_t<0><<<grid, 256, 2*STG2>>>(p_UA, p_Mmh, p_Mml, p_conv, NG*NFILT, CONVOUT, KP_U, CONVOUT, nullptr, 0, 128, 13);
    }
    k_fcxtb2<<<128, 128>>>(fcxt_W, fcxt_b, conv_b);
    {
        k_binit<<<(NG*128 + 255)/256, 256>>>(p_xc + 128, p_fcxtb2, NG, 128, 256);
        dim3 grid(2, 8, 4);
        gemm2_kernel<<<grid, 256>>>(p_conv, fcxt_W, nullptr, p_xc + 128, NG, 128, NFILT*CONVOUT, 256, 0);
    }

    // fusion head (fc2 ReLU fused into k_out)
    {
        dim3 grid(16, 8, 1);
        gemm2_kernel<<<grid, 256>>>(p_xc, fc1_W, fc1_b, p_f1, NG, 1024, 256, 1024, 1);
    }
    {
        k_binit<<<(NG*512 + 255)/256, 256>>>(p_f2, fc2_b, NG, 512, 512);
        dim3 grid(8, 8, 2);
        gemm2_kernel<<<grid, 256>>>(p_f1, fc2_W, nullptr, p_f2, NG, 512, 1024, 512, 0);
    }
    k_out<<<(NG*32 + 255)/256, 256>>>(out_W, out_b, (float*)d_out);
}